// round 5
// baseline (speedup 1.0000x reference)
#include <cuda_runtime.h>
#include <math.h>

#define Bb 4
#define Ss 2048
#define Ee 1024
#define Hh 16
#define KVv 4
#define HDd 64
#define Rr 8
#define CDd 64
#define NQq 8
#define NCH 16
#define CHUNK 128
#define NTOK (Bb*Ss)      // 8192
#define NCAT 1600         // 64 + 3*512

// ---------------- scratch (device globals; no cudaMalloc allowed) ----------------
__device__ float g_Wcat[1024 * NCAT];
__device__ float g_bcat[NCAT];
__device__ float g_P[(size_t)NTOK * NCAT];
__device__ float g_v[(size_t)Bb * KVv * Ss * HDd];
__device__ float g_qf[(size_t)Bb * Hh * Ss * 16];
__device__ float g_kf[(size_t)Bb * KVv * Ss * 16];
__device__ float g_kvc[(size_t)Bb * KVv * NCH * 16 * 64];
__device__ float g_kvp[(size_t)Bb * KVv * NCH * 16 * 64];
__device__ float g_kfc[Bb * KVv * NCH * 16];
__device__ float g_kfp[Bb * KVv * NCH * 16];
__device__ float g_attn[(size_t)NTOK * Ee];

// ---------------- helpers ----------------
__device__ __forceinline__ void ld16(float* o, const float4* p) {
    float4 a = __ldg(p + 0), b = __ldg(p + 1), c = __ldg(p + 2), d = __ldg(p + 3);
    o[0] = a.x;  o[1] = a.y;  o[2] = a.z;  o[3] = a.w;
    o[4] = b.x;  o[5] = b.y;  o[6] = b.z;  o[7] = b.w;
    o[8] = c.x;  o[9] = c.y;  o[10] = c.z; o[11] = c.w;
    o[12] = d.x; o[13] = d.y; o[14] = d.z; o[15] = d.w;
}

// ---------------- K0: pack concatenated weights/bias ----------------
__global__ void pack_kernel(const float* __restrict__ ctxW, const float* __restrict__ qaW,
                            const float* __restrict__ kaW,  const float* __restrict__ vaW,
                            const float* __restrict__ ctxb, const float* __restrict__ qab,
                            const float* __restrict__ kab,  const float* __restrict__ vab) {
    const int total = 1024 * NCAT;
    for (int i = blockIdx.x * blockDim.x + threadIdx.x; i < total; i += gridDim.x * blockDim.x) {
        int e = i / NCAT, c = i % NCAT;
        float v;
        if (c < 64)        v = ctxW[e * 64 + c];
        else if (c < 576)  v = qaW[e * 512 + (c - 64)];
        else if (c < 1088) v = kaW[e * 512 + (c - 576)];
        else               v = vaW[e * 512 + (c - 1088)];
        g_Wcat[i] = v;
    }
    int j = blockIdx.x * blockDim.x + threadIdx.x;
    if (j < NCAT) {
        float v;
        if (j < 64)        v = ctxb[j];
        else if (j < 576)  v = qab[j - 64];
        else if (j < 1088) v = kab[j - 576];
        else               v = vab[j - 1088];
        g_bcat[j] = v;
    }
}

// ---------------- SGEMM body: C[M,N] = A[M,K] @ B[K,N] + bias (+ res) ----------------
// BM=BN=128, BK=16, 256 threads, 8x8 per thread. M%128==0, K%16==0 assumed; N guarded.
__device__ __forceinline__ void sgemm_body(int M, int N, int K,
                                           const float* __restrict__ A,
                                           const float* __restrict__ Bm,
                                           const float* __restrict__ bias,
                                           const float* __restrict__ res,
                                           float* __restrict__ C) {
    __shared__ float As[16][128];
    __shared__ float Bs[16][128];
    const int bm = blockIdx.y * 128, bn = blockIdx.x * 128;
    const int tid = threadIdx.x;
    const int tx = (tid & 15) * 8;
    const int ty = (tid >> 4) * 8;
    float acc[8][8];
#pragma unroll
    for (int i = 0; i < 8; i++)
#pragma unroll
        for (int j = 0; j < 8; j++) acc[i][j] = 0.f;

    for (int k0 = 0; k0 < K; k0 += 16) {
#pragma unroll
        for (int i = 0; i < 2; i++) {
            int idx = tid + i * 256;           // 512 float4 slots of the 128x16 A tile
            int m = idx >> 2;
            int kk = (idx & 3) * 4;
            float4 va = *reinterpret_cast<const float4*>(&A[(size_t)(bm + m) * K + k0 + kk]);
            As[kk + 0][m] = va.x; As[kk + 1][m] = va.y;
            As[kk + 2][m] = va.z; As[kk + 3][m] = va.w;
        }
#pragma unroll
        for (int i = 0; i < 2; i++) {
            int idx = tid + i * 256;           // 16 rows x 32 float4 of the B tile
            int kk = idx >> 5;
            int n = (idx & 31) * 4;
            int gn = bn + n;
            float4 vb = make_float4(0.f, 0.f, 0.f, 0.f);
            if (gn < N) vb = *reinterpret_cast<const float4*>(&Bm[(size_t)(k0 + kk) * N + gn]);
            Bs[kk][n + 0] = vb.x; Bs[kk][n + 1] = vb.y;
            Bs[kk][n + 2] = vb.z; Bs[kk][n + 3] = vb.w;
        }
        __syncthreads();
#pragma unroll
        for (int kk = 0; kk < 16; kk++) {
            float af[8], bfv[8];
#pragma unroll
            for (int i = 0; i < 8; i++) af[i] = As[kk][ty + i];
#pragma unroll
            for (int j = 0; j < 8; j++) bfv[j] = Bs[kk][tx + j];
#pragma unroll
            for (int i = 0; i < 8; i++)
#pragma unroll
                for (int j = 0; j < 8; j++) acc[i][j] += af[i] * bfv[j];
        }
        __syncthreads();
    }
#pragma unroll
    for (int i = 0; i < 8; i++) {
        int gm = bm + ty + i;
#pragma unroll
        for (int j = 0; j < 8; j++) {
            int gn = bn + tx + j;
            if (gn < N) {
                float v = acc[i][j] + bias[gn];
                if (res) v += res[(size_t)gm * N + gn];
                C[(size_t)gm * N + gn] = v;
            }
        }
    }
}

__global__ __launch_bounds__(256, 2)
void gemm1_kernel(const float* __restrict__ x) {
    sgemm_body(NTOK, NCAT, Ee, x, g_Wcat, g_bcat, nullptr, g_P);
}

__global__ __launch_bounds__(256, 2)
void gemm2_kernel(const float* __restrict__ outW, const float* __restrict__ outb,
                  const float* __restrict__ x, float* __restrict__ out) {
    sgemm_body(NTOK, Ee, Ee, g_attn, outW, outb, x, out);
}

// ---------------- K2: fused b-factors + TPA contraction + quantum features ----------------
__global__ __launch_bounds__(256, 4)
void tpa_feat_kernel(const float* __restrict__ qbW, const float* __restrict__ qbb,
                     const float* __restrict__ kbW, const float* __restrict__ kbb,
                     const float* __restrict__ vbW, const float* __restrict__ vbb,
                     const float* __restrict__ qeW, const float* __restrict__ qeb,
                     const float* __restrict__ vqc, const float* __restrict__ ent) {
    __shared__ float sP[NCAT];
    __shared__ float sQB[128], sKB[32], sVB[32];
    __shared__ float sQ[1024];
    __shared__ float sK[256];
    const int token = blockIdx.x;
    const int b = token / Ss, s = token % Ss;
    const int tid = threadIdx.x;

    const float4* p4 = reinterpret_cast<const float4*>(&g_P[(size_t)token * NCAT]);
    for (int i = tid; i < NCAT / 4; i += 256) reinterpret_cast<float4*>(sP)[i] = p4[i];
    __syncthreads();

    // b-factors from ctx (sP[0:64])
    if (tid < 128) {
        float a = qbb[tid];
#pragma unroll
        for (int c = 0; c < 64; c++) a += sP[c] * qbW[c * 128 + tid];
        sQB[tid] = a;
    } else if (tid < 160) {
        int t = tid - 128; float a = kbb[t];
#pragma unroll
        for (int c = 0; c < 64; c++) a += sP[c] * kbW[c * 32 + t];
        sKB[t] = a;
    } else if (tid < 192) {
        int t = tid - 160; float a = vbb[t];
#pragma unroll
        for (int c = 0; c < 64; c++) a += sP[c] * vbW[c * 32 + t];
        sVB[t] = a;
    }
    __syncthreads();

    // TPA contraction: q[h,d], k[kv,d] -> smem; v[kv,d] -> gmem
    for (int o = tid; o < 1024; o += 256) {
        int h = o >> 6, d = o & 63;
        float a = 0.f;
#pragma unroll
        for (int r = 0; r < 8; r++) a += sP[64 + r * 64 + d] * sQB[r * 16 + h];
        sQ[o] = a;
    }
    if (tid < 256) {
        int kv = tid >> 6, d = tid & 63;
        float ak = 0.f, av = 0.f;
#pragma unroll
        for (int r = 0; r < 8; r++) {
            ak += sP[576 + r * 64 + d] * sKB[r * 4 + kv];
            av += sP[1088 + r * 64 + d] * sVB[r * 4 + kv];
        }
        sK[tid] = ak;
        g_v[(((size_t)(b * KVv + kv)) * Ss + s) * 64 + d] = av;
    }
    __syncthreads();

    // quantum features: 20 heads (16 q + 4 k), one warp per head
    const int warp = tid >> 5, lane = tid & 31;
    const float ev = __ldg(ent);
    for (int head = warp; head < 20; head += 8) {
        const float* src = head < 16 ? &sQ[head * 64] : &sK[(head - 16) * 64];
        float x0 = src[lane], x1 = src[lane + 32];
        float p[8];
#pragma unroll
        for (int j = 0; j < 8; j++)
            p[j] = x0 * __ldg(&qeW[lane * 8 + j]) + x1 * __ldg(&qeW[(lane + 32) * 8 + j]);
#pragma unroll
        for (int off = 16; off; off >>= 1)
#pragma unroll
            for (int j = 0; j < 8; j++) p[j] += __shfl_xor_sync(0xffffffffu, p[j], off);
        float f[8];
#pragma unroll
        for (int j = 0; j < 8; j++) f[j] = tanhf(p[j] + __ldg(&qeb[j])) * 3.14159265358979323846f;
#pragma unroll
        for (int l = 0; l < 2; l++) {
            float g[8];
#pragma unroll
            for (int j = 0; j < 8; j++) {
                float a0 = __ldg(&vqc[(l * 8 + j) * 3 + 0]);
                float a1 = __ldg(&vqc[(l * 8 + j) * 3 + 1]);
                float a2 = __ldg(&vqc[(l * 8 + j) * 3 + 2]);
                g[j] = cosf(f[j] + a0) * sinf(f[j] + a1) + cosf(f[j] + a2);
            }
#pragma unroll
            for (int j = 0; j < 8; j++) f[j] = g[j] * (1.f + ev * g[(j + 7) & 7]);
        }
        float cs[16]; float nrm = 0.f;
#pragma unroll
        for (int j = 0; j < 8; j++) { cs[j] = cosf(f[j]); cs[j + 8] = sinf(f[j]); }
#pragma unroll
        for (int j = 0; j < 16; j++) nrm += cs[j] * cs[j];
        float inv = 1.f / (sqrtf(nrm) + 1e-6f);
        if (lane < 16) {
            float* dst = head < 16
                ? &g_qf[(((size_t)(b * Hh + head)) * Ss + s) * 16]
                : &g_kf[(((size_t)(b * KVv + (head - 16))) * Ss + s) * 16];
            dst[lane] = cs[lane] * inv;
        }
    }
}

// ---------------- Pass A: per-chunk sums of kf (x) v and kf ----------------
__global__ __launch_bounds__(64, 8)
void passA_kernel() {
    const int blk = blockIdx.x;            // (b*KV+kv)*NCH + c
    const int c = blk % NCH;
    const int bk = blk / NCH;
    const int tid = threadIdx.x;           // d
    const float4* kfb = reinterpret_cast<const float4*>(&g_kf[(((size_t)bk) * Ss + c * CHUNK) * 16]);
    const float* vb = &g_v[(((size_t)bk) * Ss + c * CHUNK) * 64];
    float acc[16];
#pragma unroll
    for (int f = 0; f < 16; f++) acc[f] = 0.f;
    float kfs = 0.f;
    for (int t = 0; t < CHUNK; t++) {
        float vd = vb[t * 64 + tid];
        float kv[16]; ld16(kv, kfb + t * 4);
#pragma unroll
        for (int f = 0; f < 16; f++) acc[f] += kv[f] * vd;
        if (tid < 16) kfs += __ldg(&g_kf[(((size_t)bk) * Ss + c * CHUNK + t) * 16 + tid]);
    }
#pragma unroll
    for (int f = 0; f < 16; f++) g_kvc[((size_t)blk * 16 + f) * 64 + tid] = acc[f];
    if (tid < 16) g_kfc[blk * 16 + tid] = kfs;
}

// ---------------- Pass B: exclusive prefix over chunks ----------------
__global__ __launch_bounds__(64, 8)
void passB_kernel() {
    const int bk = blockIdx.x;             // b*KV+kv
    const int tid = threadIdx.x;
    float run[16];
#pragma unroll
    for (int f = 0; f < 16; f++) run[f] = 0.f;
    float rk = 0.f;
    for (int c = 0; c < NCH; c++) {
        int blk = bk * NCH + c;
#pragma unroll
        for (int f = 0; f < 16; f++) {
            g_kvp[((size_t)blk * 16 + f) * 64 + tid] = run[f];
            run[f] += g_kvc[((size_t)blk * 16 + f) * 64 + tid];
        }
        if (tid < 16) { g_kfp[blk * 16 + tid] = rk; rk += g_kfc[blk * 16 + tid]; }
    }
}

// ---------------- Pass C: within-chunk scan + query eval for 4 heads ----------------
__global__ __launch_bounds__(64, 8)
void passC_kernel() {
    const int blk = blockIdx.x;
    const int c = blk % NCH;
    const int bk = blk / NCH;
    const int b = bk / KVv, kvh = bk % KVv;
    const int tid = threadIdx.x;           // d
    float st[16], kc[16];
#pragma unroll
    for (int f = 0; f < 16; f++) {
        st[f] = g_kvp[((size_t)blk * 16 + f) * 64 + tid];
        kc[f] = __ldg(&g_kfp[blk * 16 + f]);
    }
    const float4* kfb = reinterpret_cast<const float4*>(&g_kf[(((size_t)bk) * Ss + c * CHUNK) * 16]);
    const float* vb = &g_v[(((size_t)bk) * Ss + c * CHUNK) * 64];
    const int h0 = kvh * 4;                // q heads h map to kv head h/4
    const float4* qfb[4];
#pragma unroll
    for (int hh = 0; hh < 4; hh++)
        qfb[hh] = reinterpret_cast<const float4*>(&g_qf[(((size_t)(b * Hh + h0 + hh)) * Ss + c * CHUNK) * 16]);
    float* ab = &g_attn[((size_t)b * Ss + c * CHUNK) * Ee + h0 * 64 + tid];

    for (int t = 0; t < CHUNK; t++) {
        float vd = vb[t * 64 + tid];
        float kv[16]; ld16(kv, kfb + t * 4);
#pragma unroll
        for (int f = 0; f < 16; f++) { st[f] += kv[f] * vd; kc[f] += kv[f]; }
#pragma unroll
        for (int hh = 0; hh < 4; hh++) {
            float qv[16]; ld16(qv, qfb[hh] + t * 4);
            float num = 0.f, den = 0.f;
#pragma unroll
            for (int f = 0; f < 16; f++) { num += qv[f] * st[f]; den += qv[f] * kc[f]; }
            ab[(size_t)t * Ee + hh * 64] = num / (den + 1e-6f);
        }
    }
}

// ---------------- LayerNorm (in-place on d_out) ----------------
__global__ __launch_bounds__(256, 4)
void ln_kernel(float* __restrict__ y, const float* __restrict__ gamma, const float* __restrict__ beta) {
    const int row = blockIdx.x, tid = threadIdx.x;
    float4* yr = reinterpret_cast<float4*>(y + (size_t)row * Ee);
    float4 v = yr[tid];
    float s = v.x + v.y + v.z + v.w;
    float q = v.x * v.x + v.y * v.y + v.z * v.z + v.w * v.w;
    __shared__ float sS[8], sQ[8];
    const int lane = tid & 31, wid = tid >> 5;
#pragma unroll
    for (int off = 16; off; off >>= 1) {
        s += __shfl_xor_sync(0xffffffffu, s, off);
        q += __shfl_xor_sync(0xffffffffu, q, off);
    }
    if (lane == 0) { sS[wid] = s; sQ[wid] = q; }
    __syncthreads();
    if (tid == 0) {
        float ts = 0.f, tq = 0.f;
#pragma unroll
        for (int i = 0; i < 8; i++) { ts += sS[i]; tq += sQ[i]; }
        sS[0] = ts; sQ[0] = tq;
    }
    __syncthreads();
    float mu = sS[0] * (1.f / 1024.f);
    float var = sQ[0] * (1.f / 1024.f) - mu * mu;
    float rstd = rsqrtf(var + 1e-5f);
    const float4 gm = reinterpret_cast<const float4*>(gamma)[tid];
    const float4 bt = reinterpret_cast<const float4*>(beta)[tid];
    float4 o;
    o.x = gm.x * (v.x - mu) * rstd + bt.x;
    o.y = gm.y * (v.y - mu) * rstd + bt.y;
    o.z = gm.z * (v.z - mu) * rstd + bt.z;
    o.w = gm.w * (v.w - mu) * rstd + bt.w;
    yr[tid] = o;
}

// ---------------- launch ----------------
extern "C" void kernel_launch(void* const* d_in, const int* in_sizes, int n_in,
                              void* d_out, int out_size) {
    const float* x    = (const float*)d_in[0];
    const float* ctxW = (const float*)d_in[1];
    const float* ctxb = (const float*)d_in[2];
    const float* qaW  = (const float*)d_in[3];
    const float* qab  = (const float*)d_in[4];
    const float* qbW  = (const float*)d_in[5];
    const float* qbb  = (const float*)d_in[6];
    const float* kaW  = (const float*)d_in[7];
    const float* kab  = (const float*)d_in[8];
    const float* kbW  = (const float*)d_in[9];
    const float* kbb  = (const float*)d_in[10];
    const float* vaW  = (const float*)d_in[11];
    const float* vab  = (const float*)d_in[12];
    const float* vbW  = (const float*)d_in[13];
    const float* vbb  = (const float*)d_in[14];
    const float* qeW  = (const float*)d_in[15];
    const float* qeb  = (const float*)d_in[16];
    const float* vqc  = (const float*)d_in[17];
    const float* ent  = (const float*)d_in[18];
    const float* outW = (const float*)d_in[19];
    const float* outb = (const float*)d_in[20];
    const float* gamma = (const float*)d_in[21];
    const float* beta  = (const float*)d_in[22];
    float* out = (float*)d_out;

    pack_kernel<<<512, 256>>>(ctxW, qaW, kaW, vaW, ctxb, qab, kab, vab);

    dim3 g1((NCAT + 127) / 128, NTOK / 128);
    gemm1_kernel<<<g1, 256>>>(x);

    tpa_feat_kernel<<<NTOK, 256>>>(qbW, qbb, kbW, kbb, vbW, vbb, qeW, qeb, vqc, ent);

    passA_kernel<<<Bb * KVv * NCH, 64>>>();
    passB_kernel<<<Bb * KVv, 64>>>();
    passC_kernel<<<Bb * KVv * NCH, 64>>>();

    dim3 g2(Ee / 128, NTOK / 128);
    gemm2_kernel<<<g2, 256>>>(outW, outb, x, out);

    ln_kernel<<<NTOK, 256>>>(out, gamma, beta);
}

// round 6
// speedup vs baseline: 1.0023x; 1.0023x over previous
#include <cuda_runtime.h>
#include <math.h>

#define Bb 4
#define Ss 2048
#define Ee 1024
#define Hh 16
#define KVv 4
#define HDd 64
#define Rr 8
#define CDd 64
#define NQq 8
#define NCH 16
#define CHUNK 128
#define NTOK (Bb*Ss)      // 8192
#define NCAT 1600         // 64 + 3*512

// ---------------- scratch (device globals; no cudaMalloc allowed) ----------------
__device__ float g_Wcat[1024 * NCAT];
__device__ float g_bcat[NCAT];
__device__ float g_P[(size_t)NTOK * NCAT];
__device__ float g_v[(size_t)Bb * KVv * Ss * HDd];
__device__ float g_qf[(size_t)Bb * Hh * Ss * 16];
__device__ float g_kf[(size_t)Bb * KVv * Ss * 16];
__device__ float g_kvc[(size_t)Bb * KVv * NCH * 16 * 64];
__device__ float g_kvp[(size_t)Bb * KVv * NCH * 16 * 64];
__device__ float g_kfc[Bb * KVv * NCH * 16];
__device__ float g_kfp[Bb * KVv * NCH * 16];
__device__ float g_attn[(size_t)NTOK * Ee];

// ---------------- helpers ----------------
__device__ __forceinline__ void ld16(float* o, const float4* p) {
    float4 a = __ldg(p + 0), b = __ldg(p + 1), c = __ldg(p + 2), d = __ldg(p + 3);
    o[0] = a.x;  o[1] = a.y;  o[2] = a.z;  o[3] = a.w;
    o[4] = b.x;  o[5] = b.y;  o[6] = b.z;  o[7] = b.w;
    o[8] = c.x;  o[9] = c.y;  o[10] = c.z; o[11] = c.w;
    o[12] = d.x; o[13] = d.y; o[14] = d.z; o[15] = d.w;
}

// ---------------- K0: pack concatenated weights/bias ----------------
__global__ void pack_kernel(const float* __restrict__ ctxW, const float* __restrict__ qaW,
                            const float* __restrict__ kaW,  const float* __restrict__ vaW,
                            const float* __restrict__ ctxb, const float* __restrict__ qab,
                            const float* __restrict__ kab,  const float* __restrict__ vab) {
    const int total = 1024 * NCAT;
    for (int i = blockIdx.x * blockDim.x + threadIdx.x; i < total; i += gridDim.x * blockDim.x) {
        int e = i / NCAT, c = i % NCAT;
        float v;
        if (c < 64)        v = ctxW[e * 64 + c];
        else if (c < 576)  v = qaW[e * 512 + (c - 64)];
        else if (c < 1088) v = kaW[e * 512 + (c - 576)];
        else               v = vaW[e * 512 + (c - 1088)];
        g_Wcat[i] = v;
    }
    int j = blockIdx.x * blockDim.x + threadIdx.x;
    if (j < NCAT) {
        float v;
        if (j < 64)        v = ctxb[j];
        else if (j < 576)  v = qab[j - 64];
        else if (j < 1088) v = kab[j - 576];
        else               v = vab[j - 1088];
        g_bcat[j] = v;
    }
}

// ---------------- SGEMM body: C[M,N] = A[M,K] @ B[K,N] + bias (+ res) ----------------
// BM=BN=128, BK=16, 256 threads, 8x8 per thread. M%128==0, K%16==0 assumed; N guarded.
__device__ __forceinline__ void sgemm_body(int M, int N, int K,
                                           const float* __restrict__ A,
                                           const float* __restrict__ Bm,
                                           const float* __restrict__ bias,
                                           const float* __restrict__ res,
                                           float* __restrict__ C) {
    __shared__ float As[16][128];
    __shared__ float Bs[16][128];
    const int bm = blockIdx.y * 128, bn = blockIdx.x * 128;
    const int tid = threadIdx.x;
    const int tx = (tid & 15) * 8;
    const int ty = (tid >> 4) * 8;
    float acc[8][8];
#pragma unroll
    for (int i = 0; i < 8; i++)
#pragma unroll
        for (int j = 0; j < 8; j++) acc[i][j] = 0.f;

    for (int k0 = 0; k0 < K; k0 += 16) {
#pragma unroll
        for (int i = 0; i < 2; i++) {
            int idx = tid + i * 256;           // 512 float4 slots of the 128x16 A tile
            int m = idx >> 2;
            int kk = (idx & 3) * 4;
            float4 va = *reinterpret_cast<const float4*>(&A[(size_t)(bm + m) * K + k0 + kk]);
            As[kk + 0][m] = va.x; As[kk + 1][m] = va.y;
            As[kk + 2][m] = va.z; As[kk + 3][m] = va.w;
        }
#pragma unroll
        for (int i = 0; i < 2; i++) {
            int idx = tid + i * 256;           // 16 rows x 32 float4 of the B tile
            int kk = idx >> 5;
            int n = (idx & 31) * 4;
            int gn = bn + n;
            float4 vb = make_float4(0.f, 0.f, 0.f, 0.f);
            if (gn < N) vb = *reinterpret_cast<const float4*>(&Bm[(size_t)(k0 + kk) * N + gn]);
            Bs[kk][n + 0] = vb.x; Bs[kk][n + 1] = vb.y;
            Bs[kk][n + 2] = vb.z; Bs[kk][n + 3] = vb.w;
        }
        __syncthreads();
#pragma unroll
        for (int kk = 0; kk < 16; kk++) {
            float af[8], bfv[8];
#pragma unroll
            for (int i = 0; i < 8; i++) af[i] = As[kk][ty + i];
#pragma unroll
            for (int j = 0; j < 8; j++) bfv[j] = Bs[kk][tx + j];
#pragma unroll
            for (int i = 0; i < 8; i++)
#pragma unroll
                for (int j = 0; j < 8; j++) acc[i][j] += af[i] * bfv[j];
        }
        __syncthreads();
    }
#pragma unroll
    for (int i = 0; i < 8; i++) {
        int gm = bm + ty + i;
#pragma unroll
        for (int j = 0; j < 8; j++) {
            int gn = bn + tx + j;
            if (gn < N) {
                float v = acc[i][j] + bias[gn];
                if (res) v += res[(size_t)gm * N + gn];
                C[(size_t)gm * N + gn] = v;
            }
        }
    }
}

__global__ __launch_bounds__(256, 2)
void gemm1_kernel(const float* __restrict__ x) {
    sgemm_body(NTOK, NCAT, Ee, x, g_Wcat, g_bcat, nullptr, g_P);
}

__global__ __launch_bounds__(256, 2)
void gemm2_kernel(const float* __restrict__ outW, const float* __restrict__ outb,
                  const float* __restrict__ x, float* __restrict__ out) {
    sgemm_body(NTOK, Ee, Ee, g_attn, outW, outb, x, out);
}

// ---------------- K2: fused b-factors + TPA contraction + quantum features ----------------
__global__ __launch_bounds__(256, 4)
void tpa_feat_kernel(const float* __restrict__ qbW, const float* __restrict__ qbb,
                     const float* __restrict__ kbW, const float* __restrict__ kbb,
                     const float* __restrict__ vbW, const float* __restrict__ vbb,
                     const float* __restrict__ qeW, const float* __restrict__ qeb,
                     const float* __restrict__ vqc, const float* __restrict__ ent) {
    __shared__ float sP[NCAT];
    __shared__ float sQB[128], sKB[32], sVB[32];
    __shared__ float sQ[1024];
    __shared__ float sK[256];
    const int token = blockIdx.x;
    const int b = token / Ss, s = token % Ss;
    const int tid = threadIdx.x;

    const float4* p4 = reinterpret_cast<const float4*>(&g_P[(size_t)token * NCAT]);
    for (int i = tid; i < NCAT / 4; i += 256) reinterpret_cast<float4*>(sP)[i] = p4[i];
    __syncthreads();

    // b-factors from ctx (sP[0:64])
    if (tid < 128) {
        float a = qbb[tid];
#pragma unroll
        for (int c = 0; c < 64; c++) a += sP[c] * qbW[c * 128 + tid];
        sQB[tid] = a;
    } else if (tid < 160) {
        int t = tid - 128; float a = kbb[t];
#pragma unroll
        for (int c = 0; c < 64; c++) a += sP[c] * kbW[c * 32 + t];
        sKB[t] = a;
    } else if (tid < 192) {
        int t = tid - 160; float a = vbb[t];
#pragma unroll
        for (int c = 0; c < 64; c++) a += sP[c] * vbW[c * 32 + t];
        sVB[t] = a;
    }
    __syncthreads();

    // TPA contraction: q[h,d], k[kv,d] -> smem; v[kv,d] -> gmem
    for (int o = tid; o < 1024; o += 256) {
        int h = o >> 6, d = o & 63;
        float a = 0.f;
#pragma unroll
        for (int r = 0; r < 8; r++) a += sP[64 + r * 64 + d] * sQB[r * 16 + h];
        sQ[o] = a;
    }
    if (tid < 256) {
        int kv = tid >> 6, d = tid & 63;
        float ak = 0.f, av = 0.f;
#pragma unroll
        for (int r = 0; r < 8; r++) {
            ak += sP[576 + r * 64 + d] * sKB[r * 4 + kv];
            av += sP[1088 + r * 64 + d] * sVB[r * 4 + kv];
        }
        sK[tid] = ak;
        g_v[(((size_t)(b * KVv + kv)) * Ss + s) * 64 + d] = av;
    }
    __syncthreads();

    // quantum features: 20 heads (16 q + 4 k), one warp per head
    const int warp = tid >> 5, lane = tid & 31;
    const float ev = __ldg(ent);
    for (int head = warp; head < 20; head += 8) {
        const float* src = head < 16 ? &sQ[head * 64] : &sK[(head - 16) * 64];
        float x0 = src[lane], x1 = src[lane + 32];
        float p[8];
#pragma unroll
        for (int j = 0; j < 8; j++)
            p[j] = x0 * __ldg(&qeW[lane * 8 + j]) + x1 * __ldg(&qeW[(lane + 32) * 8 + j]);
#pragma unroll
        for (int off = 16; off; off >>= 1)
#pragma unroll
            for (int j = 0; j < 8; j++) p[j] += __shfl_xor_sync(0xffffffffu, p[j], off);
        float f[8];
#pragma unroll
        for (int j = 0; j < 8; j++) f[j] = tanhf(p[j] + __ldg(&qeb[j])) * 3.14159265358979323846f;
#pragma unroll
        for (int l = 0; l < 2; l++) {
            float g[8];
#pragma unroll
            for (int j = 0; j < 8; j++) {
                float a0 = __ldg(&vqc[(l * 8 + j) * 3 + 0]);
                float a1 = __ldg(&vqc[(l * 8 + j) * 3 + 1]);
                float a2 = __ldg(&vqc[(l * 8 + j) * 3 + 2]);
                g[j] = cosf(f[j] + a0) * sinf(f[j] + a1) + cosf(f[j] + a2);
            }
#pragma unroll
            for (int j = 0; j < 8; j++) f[j] = g[j] * (1.f + ev * g[(j + 7) & 7]);
        }
        float cs[16]; float nrm = 0.f;
#pragma unroll
        for (int j = 0; j < 8; j++) { cs[j] = cosf(f[j]); cs[j + 8] = sinf(f[j]); }
#pragma unroll
        for (int j = 0; j < 16; j++) nrm += cs[j] * cs[j];
        float inv = 1.f / (sqrtf(nrm) + 1e-6f);
        if (lane < 16) {
            float* dst = head < 16
                ? &g_qf[(((size_t)(b * Hh + head)) * Ss + s) * 16]
                : &g_kf[(((size_t)(b * KVv + (head - 16))) * Ss + s) * 16];
            dst[lane] = cs[lane] * inv;
        }
    }
}

// ---------------- Pass A: per-chunk sums of kf (x) v and kf ----------------
__global__ __launch_bounds__(64, 8)
void passA_kernel() {
    const int blk = blockIdx.x;            // (b*KV+kv)*NCH + c
    const int c = blk % NCH;
    const int bk = blk / NCH;
    const int tid = threadIdx.x;           // d
    const float4* kfb = reinterpret_cast<const float4*>(&g_kf[(((size_t)bk) * Ss + c * CHUNK) * 16]);
    const float* vb = &g_v[(((size_t)bk) * Ss + c * CHUNK) * 64];
    float acc[16];
#pragma unroll
    for (int f = 0; f < 16; f++) acc[f] = 0.f;
    float kfs = 0.f;
    for (int t = 0; t < CHUNK; t++) {
        float vd = vb[t * 64 + tid];
        float kv[16]; ld16(kv, kfb + t * 4);
#pragma unroll
        for (int f = 0; f < 16; f++) acc[f] += kv[f] * vd;
        if (tid < 16) kfs += __ldg(&g_kf[(((size_t)bk) * Ss + c * CHUNK + t) * 16 + tid]);
    }
#pragma unroll
    for (int f = 0; f < 16; f++) g_kvc[((size_t)blk * 16 + f) * 64 + tid] = acc[f];
    if (tid < 16) g_kfc[blk * 16 + tid] = kfs;
}

// ---------------- Pass B: exclusive prefix over chunks ----------------
__global__ __launch_bounds__(64, 8)
void passB_kernel() {
    const int bk = blockIdx.x;             // b*KV+kv
    const int tid = threadIdx.x;
    float run[16];
#pragma unroll
    for (int f = 0; f < 16; f++) run[f] = 0.f;
    float rk = 0.f;
    for (int c = 0; c < NCH; c++) {
        int blk = bk * NCH + c;
#pragma unroll
        for (int f = 0; f < 16; f++) {
            g_kvp[((size_t)blk * 16 + f) * 64 + tid] = run[f];
            run[f] += g_kvc[((size_t)blk * 16 + f) * 64 + tid];
        }
        if (tid < 16) { g_kfp[blk * 16 + tid] = rk; rk += g_kfc[blk * 16 + tid]; }
    }
}

// ---------------- Pass C: within-chunk scan + query eval for 4 heads ----------------
__global__ __launch_bounds__(64, 8)
void passC_kernel() {
    const int blk = blockIdx.x;
    const int c = blk % NCH;
    const int bk = blk / NCH;
    const int b = bk / KVv, kvh = bk % KVv;
    const int tid = threadIdx.x;           // d
    float st[16], kc[16];
#pragma unroll
    for (int f = 0; f < 16; f++) {
        st[f] = g_kvp[((size_t)blk * 16 + f) * 64 + tid];
        kc[f] = __ldg(&g_kfp[blk * 16 + f]);
    }
    const float4* kfb = reinterpret_cast<const float4*>(&g_kf[(((size_t)bk) * Ss + c * CHUNK) * 16]);
    const float* vb = &g_v[(((size_t)bk) * Ss + c * CHUNK) * 64];
    const int h0 = kvh * 4;                // q heads h map to kv head h/4
    const float4* qfb[4];
#pragma unroll
    for (int hh = 0; hh < 4; hh++)
        qfb[hh] = reinterpret_cast<const float4*>(&g_qf[(((size_t)(b * Hh + h0 + hh)) * Ss + c * CHUNK) * 16]);
    float* ab = &g_attn[((size_t)b * Ss + c * CHUNK) * Ee + h0 * 64 + tid];

    for (int t = 0; t < CHUNK; t++) {
        float vd = vb[t * 64 + tid];
        float kv[16]; ld16(kv, kfb + t * 4);
#pragma unroll
        for (int f = 0; f < 16; f++) { st[f] += kv[f] * vd; kc[f] += kv[f]; }
#pragma unroll
        for (int hh = 0; hh < 4; hh++) {
            float qv[16]; ld16(qv, qfb[hh] + t * 4);
            float num = 0.f, den = 0.f;
#pragma unroll
            for (int f = 0; f < 16; f++) { num += qv[f] * st[f]; den += qv[f] * kc[f]; }
            ab[(size_t)t * Ee + hh * 64] = num / (den + 1e-6f);
        }
    }
}

// ---------------- LayerNorm (in-place on d_out) ----------------
__global__ __launch_bounds__(256, 4)
void ln_kernel(float* __restrict__ y, const float* __restrict__ gamma, const float* __restrict__ beta) {
    const int row = blockIdx.x, tid = threadIdx.x;
    float4* yr = reinterpret_cast<float4*>(y + (size_t)row * Ee);
    float4 v = yr[tid];
    float s = v.x + v.y + v.z + v.w;
    float q = v.x * v.x + v.y * v.y + v.z * v.z + v.w * v.w;
    __shared__ float sS[8], sQ[8];
    const int lane = tid & 31, wid = tid >> 5;
#pragma unroll
    for (int off = 16; off; off >>= 1) {
        s += __shfl_xor_sync(0xffffffffu, s, off);
        q += __shfl_xor_sync(0xffffffffu, q, off);
    }
    if (lane == 0) { sS[wid] = s; sQ[wid] = q; }
    __syncthreads();
    if (tid == 0) {
        float ts = 0.f, tq = 0.f;
#pragma unroll
        for (int i = 0; i < 8; i++) { ts += sS[i]; tq += sQ[i]; }
        sS[0] = ts; sQ[0] = tq;
    }
    __syncthreads();
    float mu = sS[0] * (1.f / 1024.f);
    float var = sQ[0] * (1.f / 1024.f) - mu * mu;
    float rstd = rsqrtf(var + 1e-5f);
    const float4 gm = reinterpret_cast<const float4*>(gamma)[tid];
    const float4 bt = reinterpret_cast<const float4*>(beta)[tid];
    float4 o;
    o.x = gm.x * (v.x - mu) * rstd + bt.x;
    o.y = gm.y * (v.y - mu) * rstd + bt.y;
    o.z = gm.z * (v.z - mu) * rstd + bt.z;
    o.w = gm.w * (v.w - mu) * rstd + bt.w;
    yr[tid] = o;
}

// ---------------- launch ----------------
extern "C" void kernel_launch(void* const* d_in, const int* in_sizes, int n_in,
                              void* d_out, int out_size) {
    const float* x    = (const float*)d_in[0];
    const float* ctxW = (const float*)d_in[1];
    const float* ctxb = (const float*)d_in[2];
    const float* qaW  = (const float*)d_in[3];
    const float* qab  = (const float*)d_in[4];
    const float* qbW  = (const float*)d_in[5];
    const float* qbb  = (const float*)d_in[6];
    const float* kaW  = (const float*)d_in[7];
    const float* kab  = (const float*)d_in[8];
    const float* kbW  = (const float*)d_in[9];
    const float* kbb  = (const float*)d_in[10];
    const float* vaW  = (const float*)d_in[11];
    const float* vab  = (const float*)d_in[12];
    const float* vbW  = (const float*)d_in[13];
    const float* vbb  = (const float*)d_in[14];
    const float* qeW  = (const float*)d_in[15];
    const float* qeb  = (const float*)d_in[16];
    const float* vqc  = (const float*)d_in[17];
    const float* ent  = (const float*)d_in[18];
    const float* outW = (const float*)d_in[19];
    const float* outb = (const float*)d_in[20];
    const float* gamma = (const float*)d_in[21];
    const float* beta  = (const float*)d_in[22];
    float* out = (float*)d_out;

    pack_kernel<<<512, 256>>>(ctxW, qaW, kaW, vaW, ctxb, qab, kab, vab);

    dim3 g1((NCAT + 127) / 128, NTOK / 128);
    gemm1_kernel<<<g1, 256>>>(x);

    tpa_feat_kernel<<<NTOK, 256>>>(qbW, qbb, kbW, kbb, vbW, vbb, qeW, qeb, vqc, ent);

    passA_kernel<<<Bb * KVv * NCH, 64>>>();
    passB_kernel<<<Bb * KVv, 64>>>();
    passC_kernel<<<Bb * KVv * NCH, 64>>>();

    dim3 g2(Ee / 128, NTOK / 128);
    gemm2_kernel<<<g2, 256>>>(outW, outb, x, out);

    ln_kernel<<<NTOK, 256>>>(out, gamma, beta);
}

// round 7
// speedup vs baseline: 1.1881x; 1.1854x over previous
#include <cuda_runtime.h>
#include <cuda_bf16.h>
#include <math.h>

#define Bb 4
#define Ss 2048
#define Ee 1024
#define Hh 16
#define KVv 4
#define HDd 64
#define Rr 8
#define CDd 64
#define NQq 8
#define NCH 16
#define CHUNK 128
#define NTOK (Bb*Ss)      // 8192
#define NCAT 1600         // 64 + 3*512

// ---------------- scratch (device globals; no cudaMalloc allowed) ----------------
__device__ __align__(16) __nv_bfloat16 g_Wh[1024 * NCAT];
__device__ __align__(16) __nv_bfloat16 g_Wl[1024 * NCAT];
__device__ __align__(16) __nv_bfloat16 g_oWh[1024 * 1024];
__device__ __align__(16) __nv_bfloat16 g_oWl[1024 * 1024];
__device__ float g_bcat[NCAT];
__device__ float g_P[(size_t)NTOK * NCAT];
__device__ float g_v[(size_t)Bb * KVv * Ss * HDd];
__device__ float g_qf[(size_t)Bb * Hh * Ss * 16];
__device__ float g_kf[(size_t)Bb * KVv * Ss * 16];
__device__ float g_kvc[(size_t)Bb * KVv * NCH * 16 * 64];
__device__ float g_kvp[(size_t)Bb * KVv * NCH * 16 * 64];
__device__ float g_kfc[Bb * KVv * NCH * 16];
__device__ float g_kfp[Bb * KVv * NCH * 16];
__device__ float g_attn[(size_t)NTOK * Ee];

// ---------------- helpers ----------------
__device__ __forceinline__ void ld16(float* o, const float4* p) {
    float4 a = __ldg(p + 0), b = __ldg(p + 1), c = __ldg(p + 2), d = __ldg(p + 3);
    o[0] = a.x;  o[1] = a.y;  o[2] = a.z;  o[3] = a.w;
    o[4] = b.x;  o[5] = b.y;  o[6] = b.z;  o[7] = b.w;
    o[8] = c.x;  o[9] = c.y;  o[10] = c.z; o[11] = c.w;
    o[12] = d.x; o[13] = d.y; o[14] = d.z; o[15] = d.w;
}

__device__ __forceinline__ void split_bf16(float v, __nv_bfloat16& h, __nv_bfloat16& l) {
    h = __float2bfloat16_rn(v);
    l = __float2bfloat16_rn(v - __bfloat162float(h));
}

#define MMA_BF16(d, a, b0, b1)                                              \
    asm volatile("mma.sync.aligned.m16n8k16.row.col.f32.bf16.bf16.f32 "     \
                 "{%0,%1,%2,%3}, {%4,%5,%6,%7}, {%8,%9}, {%0,%1,%2,%3};"    \
                 : "+f"(d[0]), "+f"(d[1]), "+f"(d[2]), "+f"(d[3])           \
                 : "r"(a[0]), "r"(a[1]), "r"(a[2]), "r"(a[3]),              \
                   "r"(b0), "r"(b1))

// ---------------- K0: pack + split weights to bf16 hi/lo ----------------
__global__ void pack_kernel(const float* __restrict__ ctxW, const float* __restrict__ qaW,
                            const float* __restrict__ kaW,  const float* __restrict__ vaW,
                            const float* __restrict__ ctxb, const float* __restrict__ qab,
                            const float* __restrict__ kab,  const float* __restrict__ vab,
                            const float* __restrict__ outW) {
    const int total = 1024 * NCAT;
    for (int i = blockIdx.x * blockDim.x + threadIdx.x; i < total; i += gridDim.x * blockDim.x) {
        int e = i / NCAT, c = i % NCAT;
        float v;
        if (c < 64)        v = ctxW[e * 64 + c];
        else if (c < 576)  v = qaW[e * 512 + (c - 64)];
        else if (c < 1088) v = kaW[e * 512 + (c - 576)];
        else               v = vaW[e * 512 + (c - 1088)];
        __nv_bfloat16 h, l; split_bf16(v, h, l);
        g_Wh[i] = h; g_Wl[i] = l;
    }
    const int total2 = 1024 * 1024;
    for (int i = blockIdx.x * blockDim.x + threadIdx.x; i < total2; i += gridDim.x * blockDim.x) {
        __nv_bfloat16 h, l; split_bf16(outW[i], h, l);
        g_oWh[i] = h; g_oWl[i] = l;
    }
    int j = blockIdx.x * blockDim.x + threadIdx.x;
    if (j < NCAT) {
        float v;
        if (j < 64)        v = ctxb[j];
        else if (j < 576)  v = qab[j - 64];
        else if (j < 1088) v = kab[j - 576];
        else               v = vab[j - 1088];
        g_bcat[j] = v;
    }
}

// ---------------- tensor-core GEMM: C = A(fp32) @ B(bf16 hi/lo pre-split) ----------------
// BM=BN=128, BK=32, 256 threads = 8 warps, each warp 32M x 64N of m16n8k16 mma.
// 3-term bf16 split: C += Ah*Bh + Ah*Bl + Al*Bh  (~17-bit effective mantissa).
// Smem row stride 40 bf16 (80B) -> conflict-free fragment loads.
#define SSTR 40
__device__ __forceinline__ void gemm_bf16_body(
    int M, int N, int K,
    const float* __restrict__ A,
    const __nv_bfloat16* __restrict__ Bhi,
    const __nv_bfloat16* __restrict__ Blo,
    const float* __restrict__ bias,
    const float* __restrict__ res,
    float* __restrict__ C)
{
    __shared__ __align__(16) __nv_bfloat16 Ahs[128 * SSTR];
    __shared__ __align__(16) __nv_bfloat16 Als[128 * SSTR];
    __shared__ __align__(16) __nv_bfloat16 Bhs[128 * SSTR];
    __shared__ __align__(16) __nv_bfloat16 Bls[128 * SSTR];

    const int bm = blockIdx.y * 128, bn = blockIdx.x * 128;
    const int tid = threadIdx.x;
    const int warp = tid >> 5, lane = tid & 31;
    const int wm = (warp >> 1) * 32, wn = (warp & 1) * 64;
    const int r = lane >> 2, cq = (lane & 3) * 2;

    float acc[2][8][4];
#pragma unroll
    for (int mt = 0; mt < 2; mt++)
#pragma unroll
        for (int j = 0; j < 8; j++)
#pragma unroll
            for (int q = 0; q < 4; q++) acc[mt][j][q] = 0.f;

    for (int k0 = 0; k0 < K; k0 += 32) {
        // ---- A tile: 128 x 32 fp32, split to bf16 hi/lo ----
#pragma unroll
        for (int i = 0; i < 4; i++) {
            int idx = tid + i * 256;          // 1024 float4 slots
            int row = idx >> 3, c4 = (idx & 7) * 4;
            float4 v = *reinterpret_cast<const float4*>(&A[(size_t)(bm + row) * K + k0 + c4]);
            __nv_bfloat16 hx, lx, hy, ly, hz, lz, hw, lw;
            split_bf16(v.x, hx, lx); split_bf16(v.y, hy, ly);
            split_bf16(v.z, hz, lz); split_bf16(v.w, hw, lw);
            __nv_bfloat162 ph0; ph0.x = hx; ph0.y = hy;
            __nv_bfloat162 ph1; ph1.x = hz; ph1.y = hw;
            __nv_bfloat162 pl0; pl0.x = lx; pl0.y = ly;
            __nv_bfloat162 pl1; pl1.x = lz; pl1.y = lw;
            int off = row * SSTR + c4;
            *reinterpret_cast<__nv_bfloat162*>(&Ahs[off])     = ph0;
            *reinterpret_cast<__nv_bfloat162*>(&Ahs[off + 2]) = ph1;
            *reinterpret_cast<__nv_bfloat162*>(&Als[off])     = pl0;
            *reinterpret_cast<__nv_bfloat162*>(&Als[off + 2]) = pl1;
        }
        // ---- B tile: 32(k) x 128(n) bf16, stored transposed [n][k] ----
#pragma unroll
        for (int i = 0; i < 2; i++) {
            int idx = tid + i * 256;
            int kk = idx & 31, ng = idx >> 5;  // ng 0..15
            int gn = bn + ng * 8;
            uint4 vh = make_uint4(0u, 0u, 0u, 0u), vl = make_uint4(0u, 0u, 0u, 0u);
            if (gn < N) {
                vh = *reinterpret_cast<const uint4*>(&Bhi[(size_t)(k0 + kk) * N + gn]);
                vl = *reinterpret_cast<const uint4*>(&Blo[(size_t)(k0 + kk) * N + gn]);
            }
            const __nv_bfloat16* ph = reinterpret_cast<const __nv_bfloat16*>(&vh);
            const __nv_bfloat16* pl = reinterpret_cast<const __nv_bfloat16*>(&vl);
#pragma unroll
            for (int j = 0; j < 8; j++) {
                Bhs[(ng * 8 + j) * SSTR + kk] = ph[j];
                Bls[(ng * 8 + j) * SSTR + kk] = pl[j];
            }
        }
        __syncthreads();

#pragma unroll
        for (int ks = 0; ks < 2; ks++) {
            const int kb = ks * 16;
            unsigned ah[2][4], al[2][4];
#pragma unroll
            for (int mt = 0; mt < 2; mt++) {
                int rb = (wm + mt * 16 + r) * SSTR + kb + cq;
                ah[mt][0] = *reinterpret_cast<const unsigned*>(&Ahs[rb]);
                ah[mt][1] = *reinterpret_cast<const unsigned*>(&Ahs[rb + 8 * SSTR]);
                ah[mt][2] = *reinterpret_cast<const unsigned*>(&Ahs[rb + 8]);
                ah[mt][3] = *reinterpret_cast<const unsigned*>(&Ahs[rb + 8 * SSTR + 8]);
                al[mt][0] = *reinterpret_cast<const unsigned*>(&Als[rb]);
                al[mt][1] = *reinterpret_cast<const unsigned*>(&Als[rb + 8 * SSTR]);
                al[mt][2] = *reinterpret_cast<const unsigned*>(&Als[rb + 8]);
                al[mt][3] = *reinterpret_cast<const unsigned*>(&Als[rb + 8 * SSTR + 8]);
            }
#pragma unroll
            for (int j = 0; j < 8; j++) {
                int nb = (wn + j * 8 + r) * SSTR + kb + cq;
                unsigned bh0 = *reinterpret_cast<const unsigned*>(&Bhs[nb]);
                unsigned bh1 = *reinterpret_cast<const unsigned*>(&Bhs[nb + 8]);
                unsigned bl0 = *reinterpret_cast<const unsigned*>(&Bls[nb]);
                unsigned bl1 = *reinterpret_cast<const unsigned*>(&Bls[nb + 8]);
#pragma unroll
                for (int mt = 0; mt < 2; mt++) {
                    MMA_BF16(acc[mt][j], ah[mt], bh0, bh1);
                    MMA_BF16(acc[mt][j], ah[mt], bl0, bl1);
                    MMA_BF16(acc[mt][j], al[mt], bh0, bh1);
                }
            }
        }
        __syncthreads();
    }

    // ---- epilogue: + bias (+ residual) ----
#pragma unroll
    for (int mt = 0; mt < 2; mt++) {
        int row0 = bm + wm + mt * 16 + r;
#pragma unroll
        for (int j = 0; j < 8; j++) {
            int col = bn + wn + j * 8 + cq;
            if (col < N) {
                float b0v = bias[col], b1v = bias[col + 1];
                size_t o0 = (size_t)row0 * N + col;
                size_t o1 = (size_t)(row0 + 8) * N + col;
                float v0 = acc[mt][j][0] + b0v, v1 = acc[mt][j][1] + b1v;
                float v2 = acc[mt][j][2] + b0v, v3 = acc[mt][j][3] + b1v;
                if (res) {
                    v0 += res[o0]; v1 += res[o0 + 1];
                    v2 += res[o1]; v3 += res[o1 + 1];
                }
                C[o0] = v0; C[o0 + 1] = v1;
                C[o1] = v2; C[o1 + 1] = v3;
            }
        }
    }
}

__global__ __launch_bounds__(256)
void gemm1_kernel(const float* __restrict__ x) {
    gemm_bf16_body(NTOK, NCAT, Ee, x, g_Wh, g_Wl, g_bcat, nullptr, g_P);
}

__global__ __launch_bounds__(256)
void gemm2_kernel(const float* __restrict__ outb,
                  const float* __restrict__ x, float* __restrict__ out) {
    gemm_bf16_body(NTOK, Ee, Ee, g_attn, g_oWh, g_oWl, outb, x, out);
}

// ---------------- K2: fused b-factors + TPA contraction + quantum features ----------------
__global__ __launch_bounds__(256, 4)
void tpa_feat_kernel(const float* __restrict__ qbW, const float* __restrict__ qbb,
                     const float* __restrict__ kbW, const float* __restrict__ kbb,
                     const float* __restrict__ vbW, const float* __restrict__ vbb,
                     const float* __restrict__ qeW, const float* __restrict__ qeb,
                     const float* __restrict__ vqc, const float* __restrict__ ent) {
    __shared__ float sP[NCAT];
    __shared__ float sQB[128], sKB[32], sVB[32];
    __shared__ float sQ[1024];
    __shared__ float sK[256];
    const int token = blockIdx.x;
    const int b = token / Ss, s = token % Ss;
    const int tid = threadIdx.x;

    const float4* p4 = reinterpret_cast<const float4*>(&g_P[(size_t)token * NCAT]);
    for (int i = tid; i < NCAT / 4; i += 256) reinterpret_cast<float4*>(sP)[i] = p4[i];
    __syncthreads();

    // b-factors from ctx (sP[0:64])
    if (tid < 128) {
        float a = qbb[tid];
#pragma unroll
        for (int c = 0; c < 64; c++) a += sP[c] * qbW[c * 128 + tid];
        sQB[tid] = a;
    } else if (tid < 160) {
        int t = tid - 128; float a = kbb[t];
#pragma unroll
        for (int c = 0; c < 64; c++) a += sP[c] * kbW[c * 32 + t];
        sKB[t] = a;
    } else if (tid < 192) {
        int t = tid - 160; float a = vbb[t];
#pragma unroll
        for (int c = 0; c < 64; c++) a += sP[c] * vbW[c * 32 + t];
        sVB[t] = a;
    }
    __syncthreads();

    // TPA contraction: q[h,d], k[kv,d] -> smem; v[kv,d] -> gmem
    for (int o = tid; o < 1024; o += 256) {
        int h = o >> 6, d = o & 63;
        float a = 0.f;
#pragma unroll
        for (int r = 0; r < 8; r++) a += sP[64 + r * 64 + d] * sQB[r * 16 + h];
        sQ[o] = a;
    }
    if (tid < 256) {
        int kv = tid >> 6, d = tid & 63;
        float ak = 0.f, av = 0.f;
#pragma unroll
        for (int r = 0; r < 8; r++) {
            ak += sP[576 + r * 64 + d] * sKB[r * 4 + kv];
            av += sP[1088 + r * 64 + d] * sVB[r * 4 + kv];
        }
        sK[tid] = ak;
        g_v[(((size_t)(b * KVv + kv)) * Ss + s) * 64 + d] = av;
    }
    __syncthreads();

    // quantum features: 20 heads (16 q + 4 k), one warp per head
    const int warp = tid >> 5, lane = tid & 31;
    const float ev = __ldg(ent);
    for (int head = warp; head < 20; head += 8) {
        const float* src = head < 16 ? &sQ[head * 64] : &sK[(head - 16) * 64];
        float x0 = src[lane], x1 = src[lane + 32];
        float p[8];
#pragma unroll
        for (int j = 0; j < 8; j++)
            p[j] = x0 * __ldg(&qeW[lane * 8 + j]) + x1 * __ldg(&qeW[(lane + 32) * 8 + j]);
#pragma unroll
        for (int off = 16; off; off >>= 1)
#pragma unroll
            for (int j = 0; j < 8; j++) p[j] += __shfl_xor_sync(0xffffffffu, p[j], off);
        float f[8];
#pragma unroll
        for (int j = 0; j < 8; j++) f[j] = tanhf(p[j] + __ldg(&qeb[j])) * 3.14159265358979323846f;
#pragma unroll
        for (int l = 0; l < 2; l++) {
            float g[8];
#pragma unroll
            for (int j = 0; j < 8; j++) {
                float a0 = __ldg(&vqc[(l * 8 + j) * 3 + 0]);
                float a1 = __ldg(&vqc[(l * 8 + j) * 3 + 1]);
                float a2 = __ldg(&vqc[(l * 8 + j) * 3 + 2]);
                g[j] = cosf(f[j] + a0) * sinf(f[j] + a1) + cosf(f[j] + a2);
            }
#pragma unroll
            for (int j = 0; j < 8; j++) f[j] = g[j] * (1.f + ev * g[(j + 7) & 7]);
        }
        float cs[16]; float nrm = 0.f;
#pragma unroll
        for (int j = 0; j < 8; j++) { cs[j] = cosf(f[j]); cs[j + 8] = sinf(f[j]); }
#pragma unroll
        for (int j = 0; j < 16; j++) nrm += cs[j] * cs[j];
        float inv = 1.f / (sqrtf(nrm) + 1e-6f);
        if (lane < 16) {
            float* dst = head < 16
                ? &g_qf[(((size_t)(b * Hh + head)) * Ss + s) * 16]
                : &g_kf[(((size_t)(b * KVv + (head - 16))) * Ss + s) * 16];
            dst[lane] = cs[lane] * inv;
        }
    }
}

// ---------------- Pass A: per-chunk sums of kf (x) v and kf ----------------
__global__ __launch_bounds__(64, 8)
void passA_kernel() {
    const int blk = blockIdx.x;            // (b*KV+kv)*NCH + c
    const int c = blk % NCH;
    const int bk = blk / NCH;
    const int tid = threadIdx.x;           // d
    const float4* kfb = reinterpret_cast<const float4*>(&g_kf[(((size_t)bk) * Ss + c * CHUNK) * 16]);
    const float* vb = &g_v[(((size_t)bk) * Ss + c * CHUNK) * 64];
    float acc[16];
#pragma unroll
    for (int f = 0; f < 16; f++) acc[f] = 0.f;
    float kfs = 0.f;
    for (int t = 0; t < CHUNK; t++) {
        float vd = vb[t * 64 + tid];
        float kv[16]; ld16(kv, kfb + t * 4);
#pragma unroll
        for (int f = 0; f < 16; f++) acc[f] += kv[f] * vd;
        if (tid < 16) kfs += __ldg(&g_kf[(((size_t)bk) * Ss + c * CHUNK + t) * 16 + tid]);
    }
#pragma unroll
    for (int f = 0; f < 16; f++) g_kvc[((size_t)blk * 16 + f) * 64 + tid] = acc[f];
    if (tid < 16) g_kfc[blk * 16 + tid] = kfs;
}

// ---------------- Pass B: exclusive prefix over chunks ----------------
__global__ __launch_bounds__(64, 8)
void passB_kernel() {
    const int bk = blockIdx.x;             // b*KV+kv
    const int tid = threadIdx.x;
    float run[16];
#pragma unroll
    for (int f = 0; f < 16; f++) run[f] = 0.f;
    float rk = 0.f;
    for (int c = 0; c < NCH; c++) {
        int blk = bk * NCH + c;
#pragma unroll
        for (int f = 0; f < 16; f++) {
            g_kvp[((size_t)blk * 16 + f) * 64 + tid] = run[f];
            run[f] += g_kvc[((size_t)blk * 16 + f) * 64 + tid];
        }
        if (tid < 16) { g_kfp[blk * 16 + tid] = rk; rk += g_kfc[blk * 16 + tid]; }
    }
}

// ---------------- Pass C: within-chunk scan + query eval for 4 heads ----------------
__global__ __launch_bounds__(64, 8)
void passC_kernel() {
    const int blk = blockIdx.x;
    const int c = blk % NCH;
    const int bk = blk / NCH;
    const int b = bk / KVv, kvh = bk % KVv;
    const int tid = threadIdx.x;           // d
    float st[16], kc[16];
#pragma unroll
    for (int f = 0; f < 16; f++) {
        st[f] = g_kvp[((size_t)blk * 16 + f) * 64 + tid];
        kc[f] = __ldg(&g_kfp[blk * 16 + f]);
    }
    const float4* kfb = reinterpret_cast<const float4*>(&g_kf[(((size_t)bk) * Ss + c * CHUNK) * 16]);
    const float* vb = &g_v[(((size_t)bk) * Ss + c * CHUNK) * 64];
    const int h0 = kvh * 4;                // q heads h map to kv head h/4
    const float4* qfb[4];
#pragma unroll
    for (int hh = 0; hh < 4; hh++)
        qfb[hh] = reinterpret_cast<const float4*>(&g_qf[(((size_t)(b * Hh + h0 + hh)) * Ss + c * CHUNK) * 16]);
    float* ab = &g_attn[((size_t)b * Ss + c * CHUNK) * Ee + h0 * 64 + tid];

    for (int t = 0; t < CHUNK; t++) {
        float vd = vb[t * 64 + tid];
        float kv[16]; ld16(kv, kfb + t * 4);
#pragma unroll
        for (int f = 0; f < 16; f++) { st[f] += kv[f] * vd; kc[f] += kv[f]; }
#pragma unroll
        for (int hh = 0; hh < 4; hh++) {
            float qv[16]; ld16(qv, qfb[hh] + t * 4);
            float num = 0.f, den = 0.f;
#pragma unroll
            for (int f = 0; f < 16; f++) { num += qv[f] * st[f]; den += qv[f] * kc[f]; }
            ab[(size_t)t * Ee + hh * 64] = num / (den + 1e-6f);
        }
    }
}

// ---------------- LayerNorm (in-place on d_out) ----------------
__global__ __launch_bounds__(256, 4)
void ln_kernel(float* __restrict__ y, const float* __restrict__ gamma, const float* __restrict__ beta) {
    const int row = blockIdx.x, tid = threadIdx.x;
    float4* yr = reinterpret_cast<float4*>(y + (size_t)row * Ee);
    float4 v = yr[tid];
    float s = v.x + v.y + v.z + v.w;
    float q = v.x * v.x + v.y * v.y + v.z * v.z + v.w * v.w;
    __shared__ float sS[8], sQ[8];
    const int lane = tid & 31, wid = tid >> 5;
#pragma unroll
    for (int off = 16; off; off >>= 1) {
        s += __shfl_xor_sync(0xffffffffu, s, off);
        q += __shfl_xor_sync(0xffffffffu, q, off);
    }
    if (lane == 0) { sS[wid] = s; sQ[wid] = q; }
    __syncthreads();
    if (tid == 0) {
        float ts = 0.f, tq = 0.f;
#pragma unroll
        for (int i = 0; i < 8; i++) { ts += sS[i]; tq += sQ[i]; }
        sS[0] = ts; sQ[0] = tq;
    }
    __syncthreads();
    float mu = sS[0] * (1.f / 1024.f);
    float var = sQ[0] * (1.f / 1024.f) - mu * mu;
    float rstd = rsqrtf(var + 1e-5f);
    const float4 gm = reinterpret_cast<const float4*>(gamma)[tid];
    const float4 bt = reinterpret_cast<const float4*>(beta)[tid];
    float4 o;
    o.x = gm.x * (v.x - mu) * rstd + bt.x;
    o.y = gm.y * (v.y - mu) * rstd + bt.y;
    o.z = gm.z * (v.z - mu) * rstd + bt.z;
    o.w = gm.w * (v.w - mu) * rstd + bt.w;
    yr[tid] = o;
}

// ---------------- launch ----------------
extern "C" void kernel_launch(void* const* d_in, const int* in_sizes, int n_in,
                              void* d_out, int out_size) {
    const float* x    = (const float*)d_in[0];
    const float* ctxW = (const float*)d_in[1];
    const float* ctxb = (const float*)d_in[2];
    const float* qaW  = (const float*)d_in[3];
    const float* qab  = (const float*)d_in[4];
    const float* qbW  = (const float*)d_in[5];
    const float* qbb  = (const float*)d_in[6];
    const float* kaW  = (const float*)d_in[7];
    const float* kab  = (const float*)d_in[8];
    const float* kbW  = (const float*)d_in[9];
    const float* kbb  = (const float*)d_in[10];
    const float* vaW  = (const float*)d_in[11];
    const float* vab  = (const float*)d_in[12];
    const float* vbW  = (const float*)d_in[13];
    const float* vbb  = (const float*)d_in[14];
    const float* qeW  = (const float*)d_in[15];
    const float* qeb  = (const float*)d_in[16];
    const float* vqc  = (const float*)d_in[17];
    const float* ent  = (const float*)d_in[18];
    const float* outW = (const float*)d_in[19];
    const float* outb = (const float*)d_in[20];
    const float* gamma = (const float*)d_in[21];
    const float* beta  = (const float*)d_in[22];
    float* out = (float*)d_out;

    pack_kernel<<<592, 256>>>(ctxW, qaW, kaW, vaW, ctxb, qab, kab, vab, outW);

    dim3 g1((NCAT + 127) / 128, NTOK / 128);
    gemm1_kernel<<<g1, 256>>>(x);

    tpa_feat_kernel<<<NTOK, 256>>>(qbW, qbb, kbW, kbb, vbW, vbb, qeW, qeb, vqc, ent);

    passA_kernel<<<Bb * KVv * NCH, 64>>>();
    passB_kernel<<<Bb * KVv, 64>>>();
    passC_kernel<<<Bb * KVv * NCH, 64>>>();

    dim3 g2(Ee / 128, NTOK / 128);
    gemm2_kernel<<<g2, 256>>>(outb, x, out);

    ln_kernel<<<NTOK, 256>>>(out, gamma, beta);
}

// round 8
// speedup vs baseline: 2.9444x; 2.4782x over previous
#include <cuda_runtime.h>
#include <cuda_bf16.h>
#include <math.h>

#define Bb 4
#define Ss 2048
#define Ee 1024
#define Hh 16
#define KVv 4
#define HDd 64
#define Rr 8
#define CDd 64
#define NQq 8
#define NCH 16
#define CHUNK 128
#define NTOK (Bb*Ss)      // 8192
#define NCAT 1600         // 64 + 3*512

// ---------------- scratch (device globals; no cudaMalloc allowed) ----------------
// Weights stored TRANSPOSED [N][K] for cp.async-friendly GEMM B operand.
__device__ __align__(16) __nv_bfloat16 g_Wh[(size_t)NCAT * 1024];
__device__ __align__(16) __nv_bfloat16 g_Wl[(size_t)NCAT * 1024];
__device__ __align__(16) __nv_bfloat16 g_oWh[(size_t)1024 * 1024];
__device__ __align__(16) __nv_bfloat16 g_oWl[(size_t)1024 * 1024];
__device__ __align__(16) __nv_bfloat16 g_xh[(size_t)NTOK * Ee];
__device__ __align__(16) __nv_bfloat16 g_xl[(size_t)NTOK * Ee];
__device__ __align__(16) __nv_bfloat16 g_ah[(size_t)NTOK * Ee];
__device__ __align__(16) __nv_bfloat16 g_al[(size_t)NTOK * Ee];
__device__ float g_bcat[NCAT];
__device__ float g_P[(size_t)NTOK * NCAT];
__device__ float g_v[(size_t)Bb * KVv * Ss * HDd];
__device__ float g_qf[(size_t)Bb * Hh * Ss * 16];
__device__ float g_kf[(size_t)Bb * KVv * Ss * 16];
__device__ float g_kvc[(size_t)Bb * KVv * NCH * 16 * 64];
__device__ float g_kvp[(size_t)Bb * KVv * NCH * 16 * 64];
__device__ float g_kfc[Bb * KVv * NCH * 16];
__device__ float g_kfp[Bb * KVv * NCH * 16];

// ---------------- helpers ----------------
__device__ __forceinline__ void ld16(float* o, const float4* p) {
    float4 a = __ldg(p + 0), b = __ldg(p + 1), c = __ldg(p + 2), d = __ldg(p + 3);
    o[0] = a.x;  o[1] = a.y;  o[2] = a.z;  o[3] = a.w;
    o[4] = b.x;  o[5] = b.y;  o[6] = b.z;  o[7] = b.w;
    o[8] = c.x;  o[9] = c.y;  o[10] = c.z; o[11] = c.w;
    o[12] = d.x; o[13] = d.y; o[14] = d.z; o[15] = d.w;
}

__device__ __forceinline__ void split_bf16(float v, __nv_bfloat16& h, __nv_bfloat16& l) {
    h = __float2bfloat16_rn(v);
    l = __float2bfloat16_rn(v - __bfloat162float(h));
}

#define MMA_BF16(d, a, b0, b1)                                              \
    asm volatile("mma.sync.aligned.m16n8k16.row.col.f32.bf16.bf16.f32 "     \
                 "{%0,%1,%2,%3}, {%4,%5,%6,%7}, {%8,%9}, {%0,%1,%2,%3};"    \
                 : "+f"(d[0]), "+f"(d[1]), "+f"(d[2]), "+f"(d[3])           \
                 : "r"(a[0]), "r"(a[1]), "r"(a[2]), "r"(a[3]),              \
                   "r"(b0), "r"(b1))

// ---------------- K0: pack + split weights (transposed) ----------------
__global__ void pack_kernel(const float* __restrict__ ctxW, const float* __restrict__ qaW,
                            const float* __restrict__ kaW,  const float* __restrict__ vaW,
                            const float* __restrict__ ctxb, const float* __restrict__ qab,
                            const float* __restrict__ kab,  const float* __restrict__ vab,
                            const float* __restrict__ outW) {
    const size_t totalW = (size_t)NCAT * 1024;
    for (size_t i = blockIdx.x * blockDim.x + threadIdx.x; i < totalW; i += (size_t)gridDim.x * blockDim.x) {
        int k = (int)(i & 1023), n = (int)(i >> 10);
        float v;
        if (n < 64)        v = ctxW[k * 64 + n];
        else if (n < 576)  v = qaW[k * 512 + (n - 64)];
        else if (n < 1088) v = kaW[k * 512 + (n - 576)];
        else               v = vaW[k * 512 + (n - 1088)];
        __nv_bfloat16 h, l; split_bf16(v, h, l);
        g_Wh[i] = h; g_Wl[i] = l;
    }
    const size_t total2 = (size_t)1024 * 1024;
    for (size_t i = blockIdx.x * blockDim.x + threadIdx.x; i < total2; i += (size_t)gridDim.x * blockDim.x) {
        int k = (int)(i & 1023), n = (int)(i >> 10);
        __nv_bfloat16 h, l; split_bf16(outW[(size_t)k * 1024 + n], h, l);
        g_oWh[i] = h; g_oWl[i] = l;
    }
    int j = blockIdx.x * blockDim.x + threadIdx.x;
    if (j < NCAT) {
        float v;
        if (j < 64)        v = ctxb[j];
        else if (j < 576)  v = qab[j - 64];
        else if (j < 1088) v = kab[j - 576];
        else               v = vab[j - 1088];
        g_bcat[j] = v;
    }
}

// ---------------- K0b: split x to bf16 hi/lo ----------------
__global__ void convx_kernel(const float* __restrict__ x) {
    const int total4 = NTOK * Ee / 4;
    for (int i = blockIdx.x * blockDim.x + threadIdx.x; i < total4; i += gridDim.x * blockDim.x) {
        float4 v = reinterpret_cast<const float4*>(x)[i];
        __nv_bfloat16 h0, l0, h1, l1, h2, l2, h3, l3;
        split_bf16(v.x, h0, l0); split_bf16(v.y, h1, l1);
        split_bf16(v.z, h2, l2); split_bf16(v.w, h3, l3);
        __nv_bfloat162 a; a.x = h0; a.y = h1;
        __nv_bfloat162 b; b.x = h2; b.y = h3;
        __nv_bfloat162 c; c.x = l0; c.y = l1;
        __nv_bfloat162 d; d.x = l2; d.y = l3;
        reinterpret_cast<__nv_bfloat162*>(g_xh)[i * 2]     = a;
        reinterpret_cast<__nv_bfloat162*>(g_xh)[i * 2 + 1] = b;
        reinterpret_cast<__nv_bfloat162*>(g_xl)[i * 2]     = c;
        reinterpret_cast<__nv_bfloat162*>(g_xl)[i * 2 + 1] = d;
    }
}

// ---------------- tensor-core GEMM ----------------
// C[M,N] = (Ah+Al)[M,K] @ (Bh+Bl)^T  with B stored [N][K]; 3-term bf16 split.
// BM=BN=128, BK=32, 256 thr, 2-stage cp.async double buffer, ldmatrix fragments.
// Smem tile: 128 rows x 32 cols bf16, 16B-chunk swizzle: phys_chunk = ch ^ ((row>>1)&3).

__device__ __forceinline__ void ldm4(unsigned base, int row0, int kb, int lane, unsigned* r) {
    int row = row0 + (lane & 15);
    int ch = (kb >> 3) + (lane >> 4);
    unsigned addr = base + (unsigned)(row * 64 + ((ch ^ ((row >> 1) & 3)) << 4));
    asm volatile("ldmatrix.sync.aligned.m8n8.x4.shared.b16 {%0,%1,%2,%3}, [%4];"
                 : "=r"(r[0]), "=r"(r[1]), "=r"(r[2]), "=r"(r[3]) : "r"(addr));
}

__device__ __forceinline__ void gemm_fill_stage(
    unsigned sbase, int tid, int bm, int bn, int k0, int N, int K,
    const __nv_bfloat16* __restrict__ Ah, const __nv_bfloat16* __restrict__ Al,
    const __nv_bfloat16* __restrict__ Bh, const __nv_bfloat16* __restrict__ Bl)
{
#pragma unroll
    for (int w = 0; w < 8; w++) {
        int tsk = tid + w * 256;
        int arr = tsk >> 9;
        int sub = tsk & 511;
        int row = sub >> 2, ch = sub & 3;
        unsigned dst = sbase + (unsigned)arr * 8192u
                     + (unsigned)(row * 64 + ((ch ^ ((row >> 1) & 3)) << 4));
        const __nv_bfloat16* g;
        int sz = 16;
        if (arr == 0)      g = Ah + (size_t)(bm + row) * K + k0 + ch * 8;
        else if (arr == 1) g = Al + (size_t)(bm + row) * K + k0 + ch * 8;
        else {
            int n = bn + row;
            int nc = n < N ? n : 0;
            sz = n < N ? 16 : 0;
            g = (arr == 2 ? Bh : Bl) + (size_t)nc * K + k0 + ch * 8;
        }
        asm volatile("cp.async.cg.shared.global [%0], [%1], 16, %2;"
                     :: "r"(dst), "l"(g), "r"(sz));
    }
}

__global__ __launch_bounds__(256, 2)
void gemm_tc_kernel(int N, int K,
                    const __nv_bfloat16* __restrict__ Ah, const __nv_bfloat16* __restrict__ Al,
                    const __nv_bfloat16* __restrict__ Bh, const __nv_bfloat16* __restrict__ Bl,
                    const float* __restrict__ bias, const float* __restrict__ res,
                    float* __restrict__ C)
{
    extern __shared__ __align__(16) unsigned char dsm[];
    unsigned sbase = (unsigned)__cvta_generic_to_shared(dsm);
    const int bm = blockIdx.y * 128, bn = blockIdx.x * 128;
    const int tid = threadIdx.x, warp = tid >> 5, lane = tid & 31;
    const int wm = (warp >> 1) * 32, wn = (warp & 1) * 64;
    const int r = lane >> 2, cq = (lane & 3) * 2;

    float acc[2][8][4];
#pragma unroll
    for (int mt = 0; mt < 2; mt++)
#pragma unroll
        for (int j = 0; j < 8; j++)
#pragma unroll
            for (int q = 0; q < 4; q++) acc[mt][j][q] = 0.f;

    const int nk = K / 32;
    gemm_fill_stage(sbase, tid, bm, bn, 0, N, K, Ah, Al, Bh, Bl);
    asm volatile("cp.async.commit_group;");
    gemm_fill_stage(sbase + 32768u, tid, bm, bn, 32, N, K, Ah, Al, Bh, Bl);
    asm volatile("cp.async.commit_group;");
    asm volatile("cp.async.wait_group 1;");
    __syncthreads();

    for (int kt = 0; kt < nk; kt++) {
        unsigned st = sbase + (unsigned)(kt & 1) * 32768u;
#pragma unroll
        for (int ks = 0; ks < 2; ks++) {
            const int kb = ks * 16;
            unsigned ah[2][4], al[2][4];
            ldm4(st,          wm,      kb, lane, ah[0]);
            ldm4(st,          wm + 16, kb, lane, ah[1]);
            ldm4(st + 8192u,  wm,      kb, lane, al[0]);
            ldm4(st + 8192u,  wm + 16, kb, lane, al[1]);
#pragma unroll
            for (int jj = 0; jj < 4; jj++) {
                unsigned bh[4], bl[4];
                ldm4(st + 16384u, wn + jj * 16, kb, lane, bh);
                ldm4(st + 24576u, wn + jj * 16, kb, lane, bl);
#pragma unroll
                for (int sub = 0; sub < 2; sub++) {
                    int j = jj * 2 + sub;
                    unsigned b0h = bh[sub], b1h = bh[2 + sub];
                    unsigned b0l = bl[sub], b1l = bl[2 + sub];
#pragma unroll
                    for (int mt = 0; mt < 2; mt++) {
                        MMA_BF16(acc[mt][j], ah[mt], b0h, b1h);
                        MMA_BF16(acc[mt][j], ah[mt], b0l, b1l);
                        MMA_BF16(acc[mt][j], al[mt], b0h, b1h);
                    }
                }
            }
        }
        __syncthreads();
        if (kt + 2 < nk)
            gemm_fill_stage(sbase + (unsigned)(kt & 1) * 32768u, tid, bm, bn,
                            (kt + 2) * 32, N, K, Ah, Al, Bh, Bl);
        asm volatile("cp.async.commit_group;");
        asm volatile("cp.async.wait_group 1;");
        __syncthreads();
    }

    // ---- epilogue: + bias (+ residual) ----
#pragma unroll
    for (int mt = 0; mt < 2; mt++) {
        int row0 = bm + wm + mt * 16 + r;
#pragma unroll
        for (int j = 0; j < 8; j++) {
            int col = bn + wn + j * 8 + cq;
            if (col < N) {
                float b0v = bias[col], b1v = bias[col + 1];
                size_t o0 = (size_t)row0 * N + col;
                size_t o1 = (size_t)(row0 + 8) * N + col;
                float v0 = acc[mt][j][0] + b0v, v1 = acc[mt][j][1] + b1v;
                float v2 = acc[mt][j][2] + b0v, v3 = acc[mt][j][3] + b1v;
                if (res) {
                    v0 += res[o0]; v1 += res[o0 + 1];
                    v2 += res[o1]; v3 += res[o1 + 1];
                }
                C[o0] = v0; C[o0 + 1] = v1;
                C[o1] = v2; C[o1 + 1] = v3;
            }
        }
    }
}

// ---------------- K2: fused b-factors + TPA contraction + quantum features ----------------
__global__ __launch_bounds__(256, 4)
void tpa_feat_kernel(const float* __restrict__ qbW, const float* __restrict__ qbb,
                     const float* __restrict__ kbW, const float* __restrict__ kbb,
                     const float* __restrict__ vbW, const float* __restrict__ vbb,
                     const float* __restrict__ qeW, const float* __restrict__ qeb,
                     const float* __restrict__ vqc, const float* __restrict__ ent) {
    __shared__ float sP[NCAT];
    __shared__ float sQB[128], sKB[32], sVB[32];
    __shared__ float sQ[1024];
    __shared__ float sK[256];
    __shared__ float sQE[512];
    __shared__ float sVQ[48];
    __shared__ float sQEB[8];
    const int token = blockIdx.x;
    const int b = token / Ss, s = token % Ss;
    const int tid = threadIdx.x;

    const float4* p4 = reinterpret_cast<const float4*>(&g_P[(size_t)token * NCAT]);
    for (int i = tid; i < NCAT / 4; i += 256) reinterpret_cast<float4*>(sP)[i] = p4[i];
    for (int i = tid; i < 512; i += 256) sQE[i] = __ldg(&qeW[i]);
    if (tid < 48) sVQ[tid] = __ldg(&vqc[tid]);
    if (tid < 8)  sQEB[tid] = __ldg(&qeb[tid]);
    __syncthreads();

    // b-factors from ctx (sP[0:64])
    if (tid < 128) {
        float a = qbb[tid];
#pragma unroll
        for (int c = 0; c < 64; c++) a += sP[c] * qbW[c * 128 + tid];
        sQB[tid] = a;
    } else if (tid < 160) {
        int t = tid - 128; float a = kbb[t];
#pragma unroll
        for (int c = 0; c < 64; c++) a += sP[c] * kbW[c * 32 + t];
        sKB[t] = a;
    } else if (tid < 192) {
        int t = tid - 160; float a = vbb[t];
#pragma unroll
        for (int c = 0; c < 64; c++) a += sP[c] * vbW[c * 32 + t];
        sVB[t] = a;
    }
    __syncthreads();

    // TPA contraction: q[h,d], k[kv,d] -> smem; v[kv,d] -> gmem
    for (int o = tid; o < 1024; o += 256) {
        int h = o >> 6, d = o & 63;
        float a = 0.f;
#pragma unroll
        for (int r = 0; r < 8; r++) a += sP[64 + r * 64 + d] * sQB[r * 16 + h];
        sQ[o] = a;
    }
    if (tid < 256) {
        int kv = tid >> 6, d = tid & 63;
        float ak = 0.f, av = 0.f;
#pragma unroll
        for (int r = 0; r < 8; r++) {
            ak += sP[576 + r * 64 + d] * sKB[r * 4 + kv];
            av += sP[1088 + r * 64 + d] * sVB[r * 4 + kv];
        }
        sK[tid] = ak;
        g_v[(((size_t)(b * KVv + kv)) * Ss + s) * 64 + d] = av;
    }
    __syncthreads();

    // quantum features: one thread per (head, qubit). 20 heads x 8 qubits = 160 threads.
    const int oct = tid >> 3, j = tid & 7;
    if (oct < 20) {
        const float ev = __ldg(ent);
        const float* src = oct < 16 ? &sQ[oct * 64] : &sK[(oct - 16) * 64];
        float p = sQEB[j];
#pragma unroll 16
        for (int d = 0; d < 64; d++) p += src[d] * sQE[d * 8 + j];
        float f = tanhf(p) * 3.14159265358979323846f;
#pragma unroll
        for (int l = 0; l < 2; l++) {
            float a0 = sVQ[(l * 8 + j) * 3 + 0];
            float a1 = sVQ[(l * 8 + j) * 3 + 1];
            float a2 = sVQ[(l * 8 + j) * 3 + 2];
            float g = cosf(f + a0) * sinf(f + a1) + cosf(f + a2);
            int srcLane = ((tid & 31) & ~7) | ((j + 7) & 7);
            float gp = __shfl_sync(0xffffffffu, g, srcLane);
            f = g * (1.f + ev * gp);
        }
        float cv = cosf(f), sv = sinf(f);
        float nr = cv * cv + sv * sv;
        nr += __shfl_xor_sync(0xffffffffu, nr, 1);
        nr += __shfl_xor_sync(0xffffffffu, nr, 2);
        nr += __shfl_xor_sync(0xffffffffu, nr, 4);
        float inv = 1.f / (sqrtf(nr) + 1e-6f);
        float* dst = oct < 16
            ? &g_qf[(((size_t)(b * Hh + oct)) * Ss + s) * 16]
            : &g_kf[(((size_t)(b * KVv + (oct - 16))) * Ss + s) * 16];
        dst[j]     = cv * inv;
        dst[j + 8] = sv * inv;
    }
}

// ---------------- Pass A: per-chunk sums of kf (x) v and kf ----------------
__global__ __launch_bounds__(64, 8)
void passA_kernel() {
    const int blk = blockIdx.x;            // (b*KV+kv)*NCH + c
    const int c = blk % NCH;
    const int bk = blk / NCH;
    const int tid = threadIdx.x;           // d
    const float4* kfb = reinterpret_cast<const float4*>(&g_kf[(((size_t)bk) * Ss + c * CHUNK) * 16]);
    const float* vb = &g_v[(((size_t)bk) * Ss + c * CHUNK) * 64];
    float acc[16];
#pragma unroll
    for (int f = 0; f < 16; f++) acc[f] = 0.f;
    float kfs = 0.f;
    for (int t = 0; t < CHUNK; t++) {
        float vd = vb[t * 64 + tid];
        float kv[16]; ld16(kv, kfb + t * 4);
#pragma unroll
        for (int f = 0; f < 16; f++) acc[f] += kv[f] * vd;
        if (tid < 16) kfs += __ldg(&g_kf[(((size_t)bk) * Ss + c * CHUNK + t) * 16 + tid]);
    }
#pragma unroll
    for (int f = 0; f < 16; f++) g_kvc[((size_t)blk * 16 + f) * 64 + tid] = acc[f];
    if (tid < 16) g_kfc[blk * 16 + tid] = kfs;
}

// ---------------- Pass B: exclusive prefix over chunks ----------------
__global__ __launch_bounds__(64, 8)
void passB_kernel() {
    const int bk = blockIdx.x;             // b*KV+kv
    const int tid = threadIdx.x;
    float run[16];
#pragma unroll
    for (int f = 0; f < 16; f++) run[f] = 0.f;
    float rk = 0.f;
    for (int c = 0; c < NCH; c++) {
        int blk = bk * NCH + c;
#pragma unroll
        for (int f = 0; f < 16; f++) {
            g_kvp[((size_t)blk * 16 + f) * 64 + tid] = run[f];
            run[f] += g_kvc[((size_t)blk * 16 + f) * 64 + tid];
        }
        if (tid < 16) { g_kfp[blk * 16 + tid] = rk; rk += g_kfc[blk * 16 + tid]; }
    }
}

// ---------------- Pass C: within-chunk scan + query eval; writes attn bf16 hi/lo ----------------
__global__ __launch_bounds__(64, 8)
void passC_kernel() {
    const int blk = blockIdx.x;
    const int c = blk % NCH;
    const int bk = blk / NCH;
    const int b = bk / KVv, kvh = bk % KVv;
    const int tid = threadIdx.x;           // d
    float st[16], kc[16];
#pragma unroll
    for (int f = 0; f < 16; f++) {
        st[f] = g_kvp[((size_t)blk * 16 + f) * 64 + tid];
        kc[f] = __ldg(&g_kfp[blk * 16 + f]);
    }
    const float4* kfb = reinterpret_cast<const float4*>(&g_kf[(((size_t)bk) * Ss + c * CHUNK) * 16]);
    const float* vb = &g_v[(((size_t)bk) * Ss + c * CHUNK) * 64];
    const int h0 = kvh * 4;                // q heads h map to kv head h/4
    const float4* qfb[4];
#pragma unroll
    for (int hh = 0; hh < 4; hh++)
        qfb[hh] = reinterpret_cast<const float4*>(&g_qf[(((size_t)(b * Hh + h0 + hh)) * Ss + c * CHUNK) * 16]);
    const size_t abase = ((size_t)b * Ss + c * CHUNK) * Ee + h0 * 64 + tid;

    for (int t = 0; t < CHUNK; t++) {
        float vd = vb[t * 64 + tid];
        float kv[16]; ld16(kv, kfb + t * 4);
#pragma unroll
        for (int f = 0; f < 16; f++) { st[f] += kv[f] * vd; kc[f] += kv[f]; }
#pragma unroll
        for (int hh = 0; hh < 4; hh++) {
            float qv[16]; ld16(qv, qfb[hh] + t * 4);
            float num = 0.f, den = 0.f;
#pragma unroll
            for (int f = 0; f < 16; f++) { num += qv[f] * st[f]; den += qv[f] * kc[f]; }
            float val = num / (den + 1e-6f);
            __nv_bfloat16 h, l; split_bf16(val, h, l);
            size_t o = abase + (size_t)t * Ee + hh * 64;
            g_ah[o] = h; g_al[o] = l;
        }
    }
}

// ---------------- LayerNorm (in-place on d_out) ----------------
__global__ __launch_bounds__(256, 4)
void ln_kernel(float* __restrict__ y, const float* __restrict__ gamma, const float* __restrict__ beta) {
    const int row = blockIdx.x, tid = threadIdx.x;
    float4* yr = reinterpret_cast<float4*>(y + (size_t)row * Ee);
    float4 v = yr[tid];
    float s = v.x + v.y + v.z + v.w;
    float q = v.x * v.x + v.y * v.y + v.z * v.z + v.w * v.w;
    __shared__ float sS[8], sQ[8];
    const int lane = tid & 31, wid = tid >> 5;
#pragma unroll
    for (int off = 16; off; off >>= 1) {
        s += __shfl_xor_sync(0xffffffffu, s, off);
        q += __shfl_xor_sync(0xffffffffu, q, off);
    }
    if (lane == 0) { sS[wid] = s; sQ[wid] = q; }
    __syncthreads();
    if (tid == 0) {
        float ts = 0.f, tq = 0.f;
#pragma unroll
        for (int i = 0; i < 8; i++) { ts += sS[i]; tq += sQ[i]; }
        sS[0] = ts; sQ[0] = tq;
    }
    __syncthreads();
    float mu = sS[0] * (1.f / 1024.f);
    float var = sQ[0] * (1.f / 1024.f) - mu * mu;
    float rstd = rsqrtf(var + 1e-5f);
    const float4 gm = reinterpret_cast<const float4*>(gamma)[tid];
    const float4 bt = reinterpret_cast<const float4*>(beta)[tid];
    float4 o;
    o.x = gm.x * (v.x - mu) * rstd + bt.x;
    o.y = gm.y * (v.y - mu) * rstd + bt.y;
    o.z = gm.z * (v.z - mu) * rstd + bt.z;
    o.w = gm.w * (v.w - mu) * rstd + bt.w;
    yr[tid] = o;
}

// ---------------- launch ----------------
extern "C" void kernel_launch(void* const* d_in, const int* in_sizes, int n_in,
                              void* d_out, int out_size) {
    const float* x    = (const float*)d_in[0];
    const float* ctxW = (const float*)d_in[1];
    const float* ctxb = (const float*)d_in[2];
    const float* qaW  = (const float*)d_in[3];
    const float* qab  = (const float*)d_in[4];
    const float* qbW  = (const float*)d_in[5];
    const float* qbb  = (const float*)d_in[6];
    const float* kaW  = (const float*)d_in[7];
    const float* kab  = (const float*)d_in[8];
    const float* kbW  = (const float*)d_in[9];
    const float* kbb  = (const float*)d_in[10];
    const float* vaW  = (const float*)d_in[11];
    const float* vab  = (const float*)d_in[12];
    const float* vbW  = (const float*)d_in[13];
    const float* vbb  = (const float*)d_in[14];
    const float* qeW  = (const float*)d_in[15];
    const float* qeb  = (const float*)d_in[16];
    const float* vqc  = (const float*)d_in[17];
    const float* ent  = (const float*)d_in[18];
    const float* outW = (const float*)d_in[19];
    const float* outb = (const float*)d_in[20];
    const float* gamma = (const float*)d_in[21];
    const float* beta  = (const float*)d_in[22];
    float* out = (float*)d_out;

    cudaFuncSetAttribute(gemm_tc_kernel, cudaFuncAttributeMaxDynamicSharedMemorySize, 65536);

    pack_kernel<<<1024, 256>>>(ctxW, qaW, kaW, vaW, ctxb, qab, kab, vab, outW);
    convx_kernel<<<1024, 256>>>(x);

    // resolve device-global addresses for GEMM operands
    __nv_bfloat16 *p_xh, *p_xl, *p_Wh, *p_Wl, *p_ah, *p_al, *p_oWh, *p_oWl;
    float *p_P, *p_bcat;
    cudaGetSymbolAddress((void**)&p_xh, g_xh);
    cudaGetSymbolAddress((void**)&p_xl, g_xl);
    cudaGetSymbolAddress((void**)&p_Wh, g_Wh);
    cudaGetSymbolAddress((void**)&p_Wl, g_Wl);
    cudaGetSymbolAddress((void**)&p_ah, g_ah);
    cudaGetSymbolAddress((void**)&p_al, g_al);
    cudaGetSymbolAddress((void**)&p_oWh, g_oWh);
    cudaGetSymbolAddress((void**)&p_oWl, g_oWl);
    cudaGetSymbolAddress((void**)&p_P, g_P);
    cudaGetSymbolAddress((void**)&p_bcat, g_bcat);

    dim3 g1((NCAT + 127) / 128, NTOK / 128);
    gemm_tc_kernel<<<g1, 256, 65536>>>(NCAT, Ee, p_xh, p_xl, p_Wh, p_Wl, p_bcat, nullptr, p_P);

    tpa_feat_kernel<<<NTOK, 256>>>(qbW, qbb, kbW, kbb, vbW, vbb, qeW, qeb, vqc, ent);

    passA_kernel<<<Bb * KVv * NCH, 64>>>();
    passB_kernel<<<Bb * KVv, 64>>>();
    passC_kernel<<<Bb * KVv * NCH, 64>>>();

    dim3 g2(Ee / 128, NTOK / 128);
    gemm_tc_kernel<<<g2, 256, 65536>>>(Ee, Ee, p_ah, p_al, p_oWh, p_oWl, outb, x, out);

    ln_kernel<<<NTOK, 256>>>(out, gamma, beta);
}

// round 9
// speedup vs baseline: 4.4718x; 1.5188x over previous
#include <cuda_runtime.h>
#include <cuda_bf16.h>
#include <math.h>

#define Bb 4
#define Ss 2048
#define Ee 1024
#define Hh 16
#define KVv 4
#define HDd 64
#define Rr 8
#define CDd 64
#define NQq 8
#define NCH 32
#define CHUNK 64
#define NTOK (Bb*Ss)      // 8192
#define NCAT 832          // aq 64 | kaq 64 | qb 128 | kb 32 | vb 32 | va 512

// ---------------- scratch (device globals; no cudaMalloc allowed) ----------------
// GEMM B operands stored TRANSPOSED [N][K] for cp.async.
__device__ __align__(16) __nv_bfloat16 g_Wh[(size_t)NCAT * 1024];
__device__ __align__(16) __nv_bfloat16 g_Wl[(size_t)NCAT * 1024];
__device__ __align__(16) __nv_bfloat16 g_oWh[(size_t)1024 * 1024];
__device__ __align__(16) __nv_bfloat16 g_oWl[(size_t)1024 * 1024];
__device__ __align__(16) __nv_bfloat16 g_xh[(size_t)NTOK * Ee];
__device__ __align__(16) __nv_bfloat16 g_xl[(size_t)NTOK * Ee];
__device__ __align__(16) __nv_bfloat16 g_ah[(size_t)NTOK * Ee];
__device__ __align__(16) __nv_bfloat16 g_al[(size_t)NTOK * Ee];
__device__ float g_cw[(size_t)1024 * 320];     // fp32 composite weights [k][n<320]
__device__ float g_bcat[NCAT];
__device__ float g_P[(size_t)NTOK * NCAT];
__device__ float g_v[(size_t)Bb * KVv * Ss * HDd];
__device__ float g_qf[(size_t)Bb * Hh * Ss * 16];
__device__ float g_kf[(size_t)Bb * KVv * Ss * 16];
__device__ float g_kvc[(size_t)Bb * KVv * NCH * 16 * 64];
__device__ float g_kfc[Bb * KVv * NCH * 16];

// ---------------- helpers ----------------
__device__ __forceinline__ void ld16(float* o, const float4* p) {
    float4 a = __ldg(p + 0), b = __ldg(p + 1), c = __ldg(p + 2), d = __ldg(p + 3);
    o[0] = a.x;  o[1] = a.y;  o[2] = a.z;  o[3] = a.w;
    o[4] = b.x;  o[5] = b.y;  o[6] = b.z;  o[7] = b.w;
    o[8] = c.x;  o[9] = c.y;  o[10] = c.z; o[11] = c.w;
    o[12] = d.x; o[13] = d.y; o[14] = d.z; o[15] = d.w;
}

__device__ __forceinline__ void split_bf16(float v, __nv_bfloat16& h, __nv_bfloat16& l) {
    h = __float2bfloat16_rn(v);
    l = __float2bfloat16_rn(v - __bfloat162float(h));
}

#define MMA_BF16(d, a, b0, b1)                                              \
    asm volatile("mma.sync.aligned.m16n8k16.row.col.f32.bf16.bf16.f32 "     \
                 "{%0,%1,%2,%3}, {%4,%5,%6,%7}, {%8,%9}, {%0,%1,%2,%3};"    \
                 : "+f"(d[0]), "+f"(d[1]), "+f"(d[2]), "+f"(d[3])           \
                 : "r"(a[0]), "r"(a[1]), "r"(a[2]), "r"(a[3]),              \
                   "r"(b0), "r"(b1))

// ---------------- K0a: composite weights, fp32, [k][n] (coalesced writes) ----------------
// n<64:    aq  = qaW_r @ qeW            (r=n>>3, j=n&7)
// n<128:   kaq = kaW_r @ qeW
// n<256:   qb  = ctxW @ qbW
// n<288:   kb  = ctxW @ kbW
// n<320:   vb  = ctxW @ vbW
// block 1024 computes the 832 biases.
__global__ void pack_comp_kernel(
    const float* __restrict__ ctxW, const float* __restrict__ qaW, const float* __restrict__ kaW,
    const float* __restrict__ qbW,  const float* __restrict__ kbW, const float* __restrict__ vbW,
    const float* __restrict__ ctxb, const float* __restrict__ qab, const float* __restrict__ kab,
    const float* __restrict__ qbb,  const float* __restrict__ kbb, const float* __restrict__ vbb,
    const float* __restrict__ vab,  const float* __restrict__ qeW)
{
    const int k = blockIdx.x;
    const int tid = threadIdx.x;
    if (k < 1024) {
        __shared__ float sA[512], sKA[512], sCtx[64];
        for (int i = tid; i < 512; i += 256) { sA[i] = qaW[(size_t)k * 512 + i]; sKA[i] = kaW[(size_t)k * 512 + i]; }
        if (tid < 64) sCtx[tid] = ctxW[k * 64 + tid];
        __syncthreads();
        for (int n = tid; n < 320; n += 256) {
            float v = 0.f;
            if (n < 64) {
                int r = n >> 3, j = n & 7;
#pragma unroll 8
                for (int d = 0; d < 64; d++) v += sA[r * 64 + d] * __ldg(&qeW[d * 8 + j]);
            } else if (n < 128) {
                int m = n - 64, r = m >> 3, j = m & 7;
#pragma unroll 8
                for (int d = 0; d < 64; d++) v += sKA[r * 64 + d] * __ldg(&qeW[d * 8 + j]);
            } else if (n < 256) {
                int h = n - 128;
#pragma unroll 8
                for (int c = 0; c < 64; c++) v += sCtx[c] * __ldg(&qbW[c * 128 + h]);
            } else if (n < 288) {
                int h = n - 256;
#pragma unroll 8
                for (int c = 0; c < 64; c++) v += sCtx[c] * __ldg(&kbW[c * 32 + h]);
            } else {
                int h = n - 288;
#pragma unroll 8
                for (int c = 0; c < 64; c++) v += sCtx[c] * __ldg(&vbW[c * 32 + h]);
            }
            g_cw[(size_t)k * 320 + n] = v;
        }
    } else {
        // biases
        for (int n = tid; n < NCAT; n += 256) {
            float v = 0.f;
            if (n < 64) {
                int r = n >> 3, j = n & 7;
                for (int d = 0; d < 64; d++) v += __ldg(&qab[r * 64 + d]) * __ldg(&qeW[d * 8 + j]);
            } else if (n < 128) {
                int m = n - 64, r = m >> 3, j = m & 7;
                for (int d = 0; d < 64; d++) v += __ldg(&kab[r * 64 + d]) * __ldg(&qeW[d * 8 + j]);
            } else if (n < 256) {
                int h = n - 128; v = qbb[h];
                for (int c = 0; c < 64; c++) v += ctxb[c] * __ldg(&qbW[c * 128 + h]);
            } else if (n < 288) {
                int h = n - 256; v = kbb[h];
                for (int c = 0; c < 64; c++) v += ctxb[c] * __ldg(&kbW[c * 32 + h]);
            } else if (n < 320) {
                int h = n - 288; v = vbb[h];
                for (int c = 0; c < 64; c++) v += ctxb[c] * __ldg(&vbW[c * 32 + h]);
            } else {
                v = vab[n - 320];
            }
            g_bcat[n] = v;
        }
    }
}

// ---------------- K0b: split weights to bf16 hi/lo, [n][k] layout ----------------
__global__ void pack_split_kernel(const float* __restrict__ vaW, const float* __restrict__ outW) {
    const size_t totalW = (size_t)NCAT * 1024;
    for (size_t i = blockIdx.x * blockDim.x + threadIdx.x; i < totalW; i += (size_t)gridDim.x * blockDim.x) {
        int k = (int)(i & 1023), n = (int)(i >> 10);
        float v = (n < 320) ? g_cw[(size_t)k * 320 + n]
                            : __ldg(&vaW[(size_t)k * 512 + (n - 320)]);
        __nv_bfloat16 h, l; split_bf16(v, h, l);
        g_Wh[i] = h; g_Wl[i] = l;
    }
    const size_t total2 = (size_t)1024 * 1024;
    for (size_t i = blockIdx.x * blockDim.x + threadIdx.x; i < total2; i += (size_t)gridDim.x * blockDim.x) {
        int k = (int)(i & 1023);
        int n = (int)(i >> 10);
        __nv_bfloat16 h, l; split_bf16(__ldg(&outW[(size_t)k * 1024 + n]), h, l);
        g_oWh[i] = h; g_oWl[i] = l;
    }
}

// ---------------- K0c: split x to bf16 hi/lo ----------------
__global__ void convx_kernel(const float* __restrict__ x) {
    const int total4 = NTOK * Ee / 4;
    for (int i = blockIdx.x * blockDim.x + threadIdx.x; i < total4; i += gridDim.x * blockDim.x) {
        float4 v = reinterpret_cast<const float4*>(x)[i];
        __nv_bfloat16 h0, l0, h1, l1, h2, l2, h3, l3;
        split_bf16(v.x, h0, l0); split_bf16(v.y, h1, l1);
        split_bf16(v.z, h2, l2); split_bf16(v.w, h3, l3);
        __nv_bfloat162 a; a.x = h0; a.y = h1;
        __nv_bfloat162 b; b.x = h2; b.y = h3;
        __nv_bfloat162 c; c.x = l0; c.y = l1;
        __nv_bfloat162 d; d.x = l2; d.y = l3;
        reinterpret_cast<__nv_bfloat162*>(g_xh)[i * 2]     = a;
        reinterpret_cast<__nv_bfloat162*>(g_xh)[i * 2 + 1] = b;
        reinterpret_cast<__nv_bfloat162*>(g_xl)[i * 2]     = c;
        reinterpret_cast<__nv_bfloat162*>(g_xl)[i * 2 + 1] = d;
    }
}

// ---------------- tensor-core GEMM, 3-stage cp.async pipeline ----------------
// C[M,N] = (Ah+Al)[M,K] @ (Bh+Bl)^T, B stored [N][K]; 3-term bf16 split.
// BM=BN=128, BK=32, 256 thr; smem 16B-chunk swizzle: phys_chunk = ch ^ ((row>>1)&3).
#define STAGE_BYTES 32768u

__device__ __forceinline__ void ldm4(unsigned base, int row0, int kb, int lane, unsigned* r) {
    int row = row0 + (lane & 15);
    int ch = (kb >> 3) + (lane >> 4);
    unsigned addr = base + (unsigned)(row * 64 + ((ch ^ ((row >> 1) & 3)) << 4));
    asm volatile("ldmatrix.sync.aligned.m8n8.x4.shared.b16 {%0,%1,%2,%3}, [%4];"
                 : "=r"(r[0]), "=r"(r[1]), "=r"(r[2]), "=r"(r[3]) : "r"(addr));
}

__device__ __forceinline__ void gemm_fill_stage(
    unsigned sbase, int tid, int bm, int bn, int k0, int N, int K,
    const __nv_bfloat16* __restrict__ Ah, const __nv_bfloat16* __restrict__ Al,
    const __nv_bfloat16* __restrict__ Bh, const __nv_bfloat16* __restrict__ Bl)
{
#pragma unroll
    for (int w = 0; w < 8; w++) {
        int tsk = tid + w * 256;
        int arr = tsk >> 9;
        int sub = tsk & 511;
        int row = sub >> 2, ch = sub & 3;
        unsigned dst = sbase + (unsigned)arr * 8192u
                     + (unsigned)(row * 64 + ((ch ^ ((row >> 1) & 3)) << 4));
        const __nv_bfloat16* g;
        int sz = 16;
        if (arr == 0)      g = Ah + (size_t)(bm + row) * K + k0 + ch * 8;
        else if (arr == 1) g = Al + (size_t)(bm + row) * K + k0 + ch * 8;
        else {
            int n = bn + row;
            int nc = n < N ? n : 0;
            sz = n < N ? 16 : 0;
            g = (arr == 2 ? Bh : Bl) + (size_t)nc * K + k0 + ch * 8;
        }
        asm volatile("cp.async.cg.shared.global [%0], [%1], 16, %2;"
                     :: "r"(dst), "l"(g), "r"(sz));
    }
}

__global__ __launch_bounds__(256, 2)
void gemm_tc_kernel(int N, int K,
                    const __nv_bfloat16* __restrict__ Ah, const __nv_bfloat16* __restrict__ Al,
                    const __nv_bfloat16* __restrict__ Bh, const __nv_bfloat16* __restrict__ Bl,
                    const float* __restrict__ bias, const float* __restrict__ res,
                    float* __restrict__ C)
{
    extern __shared__ __align__(16) unsigned char dsm[];
    unsigned sbase = (unsigned)__cvta_generic_to_shared(dsm);
    const int bm = blockIdx.y * 128, bn = blockIdx.x * 128;
    const int tid = threadIdx.x, warp = tid >> 5, lane = tid & 31;
    const int wm = (warp >> 1) * 32, wn = (warp & 1) * 64;
    const int r = lane >> 2, cq = (lane & 3) * 2;

    float acc[2][8][4];
#pragma unroll
    for (int mt = 0; mt < 2; mt++)
#pragma unroll
        for (int j = 0; j < 8; j++)
#pragma unroll
            for (int q = 0; q < 4; q++) acc[mt][j][q] = 0.f;

    const int nk = K / 32;   // >= 3 for all uses here (K=1024)
    gemm_fill_stage(sbase,                   tid, bm, bn, 0,  N, K, Ah, Al, Bh, Bl);
    asm volatile("cp.async.commit_group;");
    gemm_fill_stage(sbase + STAGE_BYTES,     tid, bm, bn, 32, N, K, Ah, Al, Bh, Bl);
    asm volatile("cp.async.commit_group;");
    gemm_fill_stage(sbase + 2 * STAGE_BYTES, tid, bm, bn, 64, N, K, Ah, Al, Bh, Bl);
    asm volatile("cp.async.commit_group;");
    asm volatile("cp.async.wait_group 2;");
    __syncthreads();

    for (int kt = 0; kt < nk; kt++) {
        unsigned st = sbase + (unsigned)(kt % 3) * STAGE_BYTES;
#pragma unroll
        for (int ks = 0; ks < 2; ks++) {
            const int kb = ks * 16;
            unsigned ah[2][4], al[2][4];
            ldm4(st,          wm,      kb, lane, ah[0]);
            ldm4(st,          wm + 16, kb, lane, ah[1]);
            ldm4(st + 8192u,  wm,      kb, lane, al[0]);
            ldm4(st + 8192u,  wm + 16, kb, lane, al[1]);
#pragma unroll
            for (int jj = 0; jj < 4; jj++) {
                unsigned bh[4], bl[4];
                ldm4(st + 16384u, wn + jj * 16, kb, lane, bh);
                ldm4(st + 24576u, wn + jj * 16, kb, lane, bl);
#pragma unroll
                for (int sub = 0; sub < 2; sub++) {
                    int j = jj * 2 + sub;
                    unsigned b0h = bh[sub], b1h = bh[2 + sub];
                    unsigned b0l = bl[sub], b1l = bl[2 + sub];
#pragma unroll
                    for (int mt = 0; mt < 2; mt++) {
                        MMA_BF16(acc[mt][j], ah[mt], b0h, b1h);
                        MMA_BF16(acc[mt][j], ah[mt], b0l, b1l);
                        MMA_BF16(acc[mt][j], al[mt], b0h, b1h);
                    }
                }
            }
        }
        __syncthreads();
        if (kt + 3 < nk)
            gemm_fill_stage(sbase + (unsigned)(kt % 3) * STAGE_BYTES, tid, bm, bn,
                            (kt + 3) * 32, N, K, Ah, Al, Bh, Bl);
        asm volatile("cp.async.commit_group;");
        asm volatile("cp.async.wait_group 2;");
        __syncthreads();
    }

    // ---- epilogue: + bias (+ residual) ----
#pragma unroll
    for (int mt = 0; mt < 2; mt++) {
        int row0 = bm + wm + mt * 16 + r;
#pragma unroll
        for (int j = 0; j < 8; j++) {
            int col = bn + wn + j * 8 + cq;
            if (col < N) {
                float b0v = bias[col], b1v = bias[col + 1];
                size_t o0 = (size_t)row0 * N + col;
                size_t o1 = (size_t)(row0 + 8) * N + col;
                float v0 = acc[mt][j][0] + b0v, v1 = acc[mt][j][1] + b1v;
                float v2 = acc[mt][j][2] + b0v, v3 = acc[mt][j][3] + b1v;
                if (res) {
                    v0 += res[o0]; v1 += res[o0 + 1];
                    v2 += res[o1]; v3 += res[o1 + 1];
                }
                C[o0] = v0; C[o0 + 1] = v1;
                C[o1] = v2; C[o1 + 1] = v3;
            }
        }
    }
}

// ---------------- K2: v-assembly + quantum features (all dots pre-folded into GEMM1) ----------------
// g_P row layout: [aq 0:64 | kaq 64:128 | qb 128:256 | kb 256:288 | vb 288:320 | va 320:832]
__global__ __launch_bounds__(256, 6)
void tpa_feat_kernel(const float* __restrict__ qeb, const float* __restrict__ vqc,
                     const float* __restrict__ ent) {
    __shared__ float sP[NCAT];
    __shared__ float sVQ[48];
    __shared__ float sQEB[8];
    const int token = blockIdx.x;
    const int b = token / Ss, s = token % Ss;
    const int tid = threadIdx.x;

    const float4* p4 = reinterpret_cast<const float4*>(&g_P[(size_t)token * NCAT]);
    if (tid < NCAT / 4) reinterpret_cast<float4*>(sP)[tid] = p4[tid];
    if (tid >= 192 && tid < 240) sVQ[tid - 192] = __ldg(&vqc[tid - 192]);
    if (tid >= 240 && tid < 248) sQEB[tid - 240] = __ldg(&qeb[tid - 240]);
    __syncthreads();

    // v[kv,d] = sum_r va[r,d] * vb[r,kv]
    {
        int kv = tid >> 6, d = tid & 63;
        float av = 0.f;
#pragma unroll
        for (int r = 0; r < 8; r++) av += sP[320 + r * 64 + d] * sP[288 + r * 4 + kv];
        g_v[(((size_t)(b * KVv + kv)) * Ss + s) * 64 + d] = av;
    }

    // quantum features: one thread per (head, qubit), 20 heads x 8 = 160 threads
    const int oct = tid >> 3, j = tid & 7;
    if (oct < 20) {
        const float ev = __ldg(ent);
        float p = sQEB[j];
        if (oct < 16) {
#pragma unroll
            for (int r = 0; r < 8; r++) p += sP[128 + r * 16 + oct] * sP[r * 8 + j];
        } else {
#pragma unroll
            for (int r = 0; r < 8; r++) p += sP[256 + r * 4 + (oct - 16)] * sP[64 + r * 8 + j];
        }
        float f = tanhf(p) * 3.14159265358979323846f;
#pragma unroll
        for (int l = 0; l < 2; l++) {
            float a0 = sVQ[(l * 8 + j) * 3 + 0];
            float a1 = sVQ[(l * 8 + j) * 3 + 1];
            float a2 = sVQ[(l * 8 + j) * 3 + 2];
            float g = cosf(f + a0) * sinf(f + a1) + cosf(f + a2);
            int srcLane = ((tid & 31) & ~7) | ((j + 7) & 7);
            float gp = __shfl_sync(0xffffffffu, g, srcLane);
            f = g * (1.f + ev * gp);
        }
        float cv = cosf(f), sv = sinf(f);
        float nr = cv * cv + sv * sv;
        nr += __shfl_xor_sync(0xffffffffu, nr, 1);
        nr += __shfl_xor_sync(0xffffffffu, nr, 2);
        nr += __shfl_xor_sync(0xffffffffu, nr, 4);
        float inv = 1.f / (sqrtf(nr) + 1e-6f);
        float* dst = oct < 16
            ? &g_qf[(((size_t)(b * Hh + oct)) * Ss + s) * 16]
            : &g_kf[(((size_t)(b * KVv + (oct - 16))) * Ss + s) * 16];
        dst[j]     = cv * inv;
        dst[j + 8] = sv * inv;
    }
}

// ---------------- Pass A: per-chunk sums of kf (x) v and kf ----------------
__global__ __launch_bounds__(64, 8)
void passA_kernel() {
    const int blk = blockIdx.x;            // (b*KV+kv)*NCH + c
    const int c = blk % NCH;
    const int bk = blk / NCH;
    const int tid = threadIdx.x;           // d
    const float4* kfb = reinterpret_cast<const float4*>(&g_kf[(((size_t)bk) * Ss + c * CHUNK) * 16]);
    const float* vb = &g_v[(((size_t)bk) * Ss + c * CHUNK) * 64];
    float acc[16];
#pragma unroll
    for (int f = 0; f < 16; f++) acc[f] = 0.f;
    float kfs = 0.f;
    for (int t = 0; t < CHUNK; t++) {
        float vd = vb[t * 64 + tid];
        float kv[16]; ld16(kv, kfb + t * 4);
#pragma unroll
        for (int f = 0; f < 16; f++) acc[f] += kv[f] * vd;
        if (tid < 16) kfs += __ldg(&g_kf[(((size_t)bk) * Ss + c * CHUNK + t) * 16 + tid]);
    }
#pragma unroll
    for (int f = 0; f < 16; f++) g_kvc[((size_t)blk * 16 + f) * 64 + tid] = acc[f];
    if (tid < 16) g_kfc[blk * 16 + tid] = kfs;
}

// ---------------- Pass C: chunk prefix (folded) + within-chunk scan + query eval ----------------
__global__ __launch_bounds__(64, 8)
void passC_kernel() {
    const int blk = blockIdx.x;
    const int c = blk % NCH;
    const int bk = blk / NCH;
    const int b = bk / KVv, kvh = bk % KVv;
    const int tid = threadIdx.x;           // d
    float st[16], kc[16];
#pragma unroll
    for (int f = 0; f < 16; f++) { st[f] = 0.f; kc[f] = 0.f; }
    for (int cp = 0; cp < c; cp++) {
        int blk2 = bk * NCH + cp;
#pragma unroll
        for (int f = 0; f < 16; f++) {
            st[f] += g_kvc[((size_t)blk2 * 16 + f) * 64 + tid];
            kc[f] += __ldg(&g_kfc[blk2 * 16 + f]);
        }
    }
    const float4* kfb = reinterpret_cast<const float4*>(&g_kf[(((size_t)bk) * Ss + c * CHUNK) * 16]);
    const float* vb = &g_v[(((size_t)bk) * Ss + c * CHUNK) * 64];
    const int h0 = kvh * 4;                // q heads h map to kv head h/4
    const float4* qfb[4];
#pragma unroll
    for (int hh = 0; hh < 4; hh++)
        qfb[hh] = reinterpret_cast<const float4*>(&g_qf[(((size_t)(b * Hh + h0 + hh)) * Ss + c * CHUNK) * 16]);
    const size_t abase = ((size_t)b * Ss + c * CHUNK) * Ee + h0 * 64 + tid;

    for (int t = 0; t < CHUNK; t++) {
        float vd = vb[t * 64 + tid];
        float kv[16]; ld16(kv, kfb + t * 4);
#pragma unroll
        for (int f = 0; f < 16; f++) { st[f] += kv[f] * vd; kc[f] += kv[f]; }
#pragma unroll
        for (int hh = 0; hh < 4; hh++) {
            float qv[16]; ld16(qv, qfb[hh] + t * 4);
            float num = 0.f, den = 0.f;
#pragma unroll
            for (int f = 0; f < 16; f++) { num += qv[f] * st[f]; den += qv[f] * kc[f]; }
            float val = num / (den + 1e-6f);
            __nv_bfloat16 h, l; split_bf16(val, h, l);
            size_t o = abase + (size_t)t * Ee + hh * 64;
            g_ah[o] = h; g_al[o] = l;
        }
    }
}

// ---------------- LayerNorm (in-place on d_out) ----------------
__global__ __launch_bounds__(256, 4)
void ln_kernel(float* __restrict__ y, const float* __restrict__ gamma, const float* __restrict__ beta) {
    const int row = blockIdx.x, tid = threadIdx.x;
    float4* yr = reinterpret_cast<float4*>(y + (size_t)row * Ee);
    float4 v = yr[tid];
    float s = v.x + v.y + v.z + v.w;
    float q = v.x * v.x + v.y * v.y + v.z * v.z + v.w * v.w;
    __shared__ float sS[8], sQ[8];
    const int lane = tid & 31, wid = tid >> 5;
#pragma unroll
    for (int off = 16; off; off >>= 1) {
        s += __shfl_xor_sync(0xffffffffu, s, off);
        q += __shfl_xor_sync(0xffffffffu, q, off);
    }
    if (lane == 0) { sS[wid] = s; sQ[wid] = q; }
    __syncthreads();
    if (tid == 0) {
        float ts = 0.f, tq = 0.f;
#pragma unroll
        for (int i = 0; i < 8; i++) { ts += sS[i]; tq += sQ[i]; }
        sS[0] = ts; sQ[0] = tq;
    }
    __syncthreads();
    float mu = sS[0] * (1.f / 1024.f);
    float var = sQ[0] * (1.f / 1024.f) - mu * mu;
    float rstd = rsqrtf(var + 1e-5f);
    const float4 gm = reinterpret_cast<const float4*>(gamma)[tid];
    const float4 bt = reinterpret_cast<const float4*>(beta)[tid];
    float4 o;
    o.x = gm.x * (v.x - mu) * rstd + bt.x;
    o.y = gm.y * (v.y - mu) * rstd + bt.y;
    o.z = gm.z * (v.z - mu) * rstd + bt.z;
    o.w = gm.w * (v.w - mu) * rstd + bt.w;
    yr[tid] = o;
}

// ---------------- launch ----------------
extern "C" void kernel_launch(void* const* d_in, const int* in_sizes, int n_in,
                              void* d_out, int out_size) {
    const float* x    = (const float*)d_in[0];
    const float* ctxW = (const float*)d_in[1];
    const float* ctxb = (const float*)d_in[2];
    const float* qaW  = (const float*)d_in[3];
    const float* qab  = (const float*)d_in[4];
    const float* qbW  = (const float*)d_in[5];
    const float* qbb  = (const float*)d_in[6];
    const float* kaW  = (const float*)d_in[7];
    const float* kab  = (const float*)d_in[8];
    const float* kbW  = (const float*)d_in[9];
    const float* kbb  = (const float*)d_in[10];
    const float* vaW  = (const float*)d_in[11];
    const float* vab  = (const float*)d_in[12];
    const float* vbW  = (const float*)d_in[13];
    const float* vbb  = (const float*)d_in[14];
    const float* qeW  = (const float*)d_in[15];
    const float* qeb  = (const float*)d_in[16];
    const float* vqc  = (const float*)d_in[17];
    const float* ent  = (const float*)d_in[18];
    const float* outW = (const float*)d_in[19];
    const float* outb = (const float*)d_in[20];
    const float* gamma = (const float*)d_in[21];
    const float* beta  = (const float*)d_in[22];
    float* out = (float*)d_out;

    cudaFuncSetAttribute(gemm_tc_kernel, cudaFuncAttributeMaxDynamicSharedMemorySize, 98304);

    pack_comp_kernel<<<1025, 256>>>(ctxW, qaW, kaW, qbW, kbW, vbW,
                                    ctxb, qab, kab, qbb, kbb, vbb, vab, qeW);
    pack_split_kernel<<<1024, 256>>>(vaW, outW);
    convx_kernel<<<1024, 256>>>(x);

    // resolve device-global addresses for GEMM operands
    __nv_bfloat16 *p_xh, *p_xl, *p_Wh, *p_Wl, *p_ah, *p_al, *p_oWh, *p_oWl;
    float *p_P, *p_bcat;
    cudaGetSymbolAddress((void**)&p_xh, g_xh);
    cudaGetSymbolAddress((void**)&p_xl, g_xl);
    cudaGetSymbolAddress((void**)&p_Wh, g_Wh);
    cudaGetSymbolAddress((void**)&p_Wl, g_Wl);
    cudaGetSymbolAddress((void**)&p_ah, g_ah);
    cudaGetSymbolAddress((void**)&p_al, g_al);
    cudaGetSymbolAddress((void**)&p_oWh, g_oWh);
    cudaGetSymbolAddress((void**)&p_oWl, g_oWl);
    cudaGetSymbolAddress((void**)&p_P, g_P);
    cudaGetSymbolAddress((void**)&p_bcat, g_bcat);

    dim3 g1((NCAT + 127) / 128, NTOK / 128);
    gemm_tc_kernel<<<g1, 256, 98304>>>(NCAT, Ee, p_xh, p_xl, p_Wh, p_Wl, p_bcat, nullptr, p_P);

    tpa_feat_kernel<<<NTOK, 256>>>(qeb, vqc, ent);

    passA_kernel<<<Bb * KVv * NCH, 64>>>();
    passC_kernel<<<Bb * KVv * NCH, 64>>>();

    dim3 g2(Ee / 128, NTOK / 128);
    gemm_tc_kernel<<<g2, 256, 98304>>>(Ee, Ee, p_ah, p_al, p_oWh, p_oWl, outb, x, out);

    ln_kernel<<<NTOK, 256>>>(out, gamma, beta);
}

// round 10
// speedup vs baseline: 4.6688x; 1.0441x over previous
#include <cuda_runtime.h>
#include <cuda_bf16.h>
#include <math.h>

#define Bb 4
#define Ss 2048
#define Ee 1024
#define Hh 16
#define KVv 4
#define HDd 64
#define Rr 8
#define CDd 64
#define NQq 8
#define NCH 32
#define CHUNK 64
#define NTOK (Bb*Ss)      // 8192
#define NCAT 832          // aq 64 | kaq 64 | qb 128 | kb 32 | vb 32 | va 512

// ---------------- scratch (device globals; no cudaMalloc allowed) ----------------
// GEMM B operands stored TRANSPOSED [N][K] for cp.async.
__device__ __align__(16) __nv_bfloat16 g_Wh[(size_t)NCAT * 1024];
__device__ __align__(16) __nv_bfloat16 g_Wl[(size_t)NCAT * 1024];
__device__ __align__(16) __nv_bfloat16 g_oWh[(size_t)1024 * 1024];
__device__ __align__(16) __nv_bfloat16 g_oWl[(size_t)1024 * 1024];
__device__ __align__(16) __nv_bfloat16 g_xh[(size_t)NTOK * Ee];
__device__ __align__(16) __nv_bfloat16 g_xl[(size_t)NTOK * Ee];
__device__ __align__(16) __nv_bfloat16 g_ah[(size_t)NTOK * Ee];
__device__ __align__(16) __nv_bfloat16 g_al[(size_t)NTOK * Ee];
__device__ float g_cw[(size_t)1024 * 320];     // fp32 composite weights [k][n<320]
__device__ float g_bcat[NCAT];
__device__ float g_P[(size_t)NTOK * NCAT];
__device__ float g_v[(size_t)Bb * KVv * Ss * HDd];
__device__ float g_qf[(size_t)Bb * Hh * Ss * 16];
__device__ float g_kf[(size_t)Bb * KVv * Ss * 16];
__device__ float g_kvc[(size_t)Bb * KVv * NCH * 16 * 64];
__device__ float g_kfc[Bb * KVv * NCH * 16];

// ---------------- helpers ----------------
__device__ __forceinline__ void ld16(float* o, const float4* p) {
    float4 a = __ldg(p + 0), b = __ldg(p + 1), c = __ldg(p + 2), d = __ldg(p + 3);
    o[0] = a.x;  o[1] = a.y;  o[2] = a.z;  o[3] = a.w;
    o[4] = b.x;  o[5] = b.y;  o[6] = b.z;  o[7] = b.w;
    o[8] = c.x;  o[9] = c.y;  o[10] = c.z; o[11] = c.w;
    o[12] = d.x; o[13] = d.y; o[14] = d.z; o[15] = d.w;
}

__device__ __forceinline__ void split_bf16(float v, __nv_bfloat16& h, __nv_bfloat16& l) {
    h = __float2bfloat16_rn(v);
    l = __float2bfloat16_rn(v - __bfloat162float(h));
}

#define MMA_BF16(d, a, b0, b1)                                              \
    asm volatile("mma.sync.aligned.m16n8k16.row.col.f32.bf16.bf16.f32 "     \
                 "{%0,%1,%2,%3}, {%4,%5,%6,%7}, {%8,%9}, {%0,%1,%2,%3};"    \
                 : "+f"(d[0]), "+f"(d[1]), "+f"(d[2]), "+f"(d[3])           \
                 : "r"(a[0]), "r"(a[1]), "r"(a[2]), "r"(a[3]),              \
                   "r"(b0), "r"(b1))

// ---------------- K0a: composite weights, fp32, [k][n] (coalesced writes) ----------------
__global__ void pack_comp_kernel(
    const float* __restrict__ ctxW, const float* __restrict__ qaW, const float* __restrict__ kaW,
    const float* __restrict__ qbW,  const float* __restrict__ kbW, const float* __restrict__ vbW,
    const float* __restrict__ ctxb, const float* __restrict__ qab, const float* __restrict__ kab,
    const float* __restrict__ qbb,  const float* __restrict__ kbb, const float* __restrict__ vbb,
    const float* __restrict__ vab,  const float* __restrict__ qeW)
{
    const int k = blockIdx.x;
    const int tid = threadIdx.x;
    if (k < 1024) {
        __shared__ float sA[512], sKA[512], sCtx[64];
        for (int i = tid; i < 512; i += 256) { sA[i] = qaW[(size_t)k * 512 + i]; sKA[i] = kaW[(size_t)k * 512 + i]; }
        if (tid < 64) sCtx[tid] = ctxW[k * 64 + tid];
        __syncthreads();
        for (int n = tid; n < 320; n += 256) {
            float v = 0.f;
            if (n < 64) {
                int r = n >> 3, j = n & 7;
#pragma unroll 8
                for (int d = 0; d < 64; d++) v += sA[r * 64 + d] * __ldg(&qeW[d * 8 + j]);
            } else if (n < 128) {
                int m = n - 64, r = m >> 3, j = m & 7;
#pragma unroll 8
                for (int d = 0; d < 64; d++) v += sKA[r * 64 + d] * __ldg(&qeW[d * 8 + j]);
            } else if (n < 256) {
                int h = n - 128;
#pragma unroll 8
                for (int c = 0; c < 64; c++) v += sCtx[c] * __ldg(&qbW[c * 128 + h]);
            } else if (n < 288) {
                int h = n - 256;
#pragma unroll 8
                for (int c = 0; c < 64; c++) v += sCtx[c] * __ldg(&kbW[c * 32 + h]);
            } else {
                int h = n - 288;
#pragma unroll 8
                for (int c = 0; c < 64; c++) v += sCtx[c] * __ldg(&vbW[c * 32 + h]);
            }
            g_cw[(size_t)k * 320 + n] = v;
        }
    } else {
        for (int n = tid; n < NCAT; n += 256) {
            float v = 0.f;
            if (n < 64) {
                int r = n >> 3, j = n & 7;
                for (int d = 0; d < 64; d++) v += __ldg(&qab[r * 64 + d]) * __ldg(&qeW[d * 8 + j]);
            } else if (n < 128) {
                int m = n - 64, r = m >> 3, j = m & 7;
                for (int d = 0; d < 64; d++) v += __ldg(&kab[r * 64 + d]) * __ldg(&qeW[d * 8 + j]);
            } else if (n < 256) {
                int h = n - 128; v = qbb[h];
                for (int c = 0; c < 64; c++) v += ctxb[c] * __ldg(&qbW[c * 128 + h]);
            } else if (n < 288) {
                int h = n - 256; v = kbb[h];
                for (int c = 0; c < 64; c++) v += ctxb[c] * __ldg(&kbW[c * 32 + h]);
            } else if (n < 320) {
                int h = n - 288; v = vbb[h];
                for (int c = 0; c < 64; c++) v += ctxb[c] * __ldg(&vbW[c * 32 + h]);
            } else {
                v = vab[n - 320];
            }
            g_bcat[n] = v;
        }
    }
}

// ---------------- K0b: split weights to bf16 hi/lo, [n][k] layout ----------------
__global__ void pack_split_kernel(const float* __restrict__ vaW, const float* __restrict__ outW) {
    const size_t totalW = (size_t)NCAT * 1024;
    for (size_t i = blockIdx.x * blockDim.x + threadIdx.x; i < totalW; i += (size_t)gridDim.x * blockDim.x) {
        int k = (int)(i & 1023), n = (int)(i >> 10);
        float v = (n < 320) ? g_cw[(size_t)k * 320 + n]
                            : __ldg(&vaW[(size_t)k * 512 + (n - 320)]);
        __nv_bfloat16 h, l; split_bf16(v, h, l);
        g_Wh[i] = h; g_Wl[i] = l;
    }
    const size_t total2 = (size_t)1024 * 1024;
    for (size_t i = blockIdx.x * blockDim.x + threadIdx.x; i < total2; i += (size_t)gridDim.x * blockDim.x) {
        int k = (int)(i & 1023);
        int n = (int)(i >> 10);
        __nv_bfloat16 h, l; split_bf16(__ldg(&outW[(size_t)k * 1024 + n]), h, l);
        g_oWh[i] = h; g_oWl[i] = l;
    }
}

// ---------------- K0c: split x to bf16 hi/lo ----------------
__global__ void convx_kernel(const float* __restrict__ x) {
    const int total4 = NTOK * Ee / 4;
    for (int i = blockIdx.x * blockDim.x + threadIdx.x; i < total4; i += gridDim.x * blockDim.x) {
        float4 v = reinterpret_cast<const float4*>(x)[i];
        __nv_bfloat16 h0, l0, h1, l1, h2, l2, h3, l3;
        split_bf16(v.x, h0, l0); split_bf16(v.y, h1, l1);
        split_bf16(v.z, h2, l2); split_bf16(v.w, h3, l3);
        __nv_bfloat162 a; a.x = h0; a.y = h1;
        __nv_bfloat162 b; b.x = h2; b.y = h3;
        __nv_bfloat162 c; c.x = l0; c.y = l1;
        __nv_bfloat162 d; d.x = l2; d.y = l3;
        reinterpret_cast<__nv_bfloat162*>(g_xh)[i * 2]     = a;
        reinterpret_cast<__nv_bfloat162*>(g_xh)[i * 2 + 1] = b;
        reinterpret_cast<__nv_bfloat162*>(g_xl)[i * 2]     = c;
        reinterpret_cast<__nv_bfloat162*>(g_xl)[i * 2 + 1] = d;
    }
}

// ---------------- tensor-core GEMM, single-sync 3-stage cp.async pipeline ----------------
// C[M,N] = (Ah+Al)[M,K] @ (Bh+Bl)^T, B stored [N][K]; 3-term bf16 split.
// BM=64, BN=128, BK=32, 256 thr, 3 CTAs/SM.
// Stage layout: Ah@0 (4KB) | Al@4K | Bh@8K (8KB) | Bl@16K; stage = 24KB, 3 stages = 72KB.
// Smem 16B-chunk swizzle: phys_chunk = ch ^ ((row>>1)&3).
#define STAGE_BYTES 24576u

__device__ __forceinline__ void ldm4(unsigned base, int row0, int kb, int lane, unsigned* r) {
    int row = row0 + (lane & 15);
    int ch = (kb >> 3) + (lane >> 4);
    unsigned addr = base + (unsigned)(row * 64 + ((ch ^ ((row >> 1) & 3)) << 4));
    asm volatile("ldmatrix.sync.aligned.m8n8.x4.shared.b16 {%0,%1,%2,%3}, [%4];"
                 : "=r"(r[0]), "=r"(r[1]), "=r"(r[2]), "=r"(r[3]) : "r"(addr));
}

__device__ __forceinline__ void gemm_fill_stage(
    unsigned sbase, int tid, int bm, int bn, int k0, int N, int K,
    const __nv_bfloat16* __restrict__ Ah, const __nv_bfloat16* __restrict__ Al,
    const __nv_bfloat16* __restrict__ Bh, const __nv_bfloat16* __restrict__ Bl)
{
#pragma unroll
    for (int w = 0; w < 6; w++) {
        int tsk = tid + w * 256;       // 0..1535 16B-chunks
        const __nv_bfloat16* g;
        unsigned abase;
        int row, ch, sz = 16;
        if (tsk < 512) {               // A tiles: 64 rows x 4 chunks, hi then lo
            int a = tsk >> 8;
            int sub = tsk & 255;
            row = sub >> 2; ch = sub & 3;
            abase = (unsigned)a * 4096u;
            g = (a ? Al : Ah) + (size_t)(bm + row) * K + k0 + ch * 8;
        } else {                       // B tiles: 128 rows x 4 chunks, hi then lo
            int t2 = tsk - 512;
            int a = t2 >> 9;
            int sub = t2 & 511;
            row = sub >> 2; ch = sub & 3;
            abase = 8192u + (unsigned)a * 8192u;
            int n = bn + row;
            int nc = n < N ? n : 0;
            sz = n < N ? 16 : 0;
            g = (a ? Bl : Bh) + (size_t)nc * K + k0 + ch * 8;
        }
        unsigned dst = sbase + abase + (unsigned)(row * 64 + ((ch ^ ((row >> 1) & 3)) << 4));
        asm volatile("cp.async.cg.shared.global [%0], [%1], 16, %2;"
                     :: "r"(dst), "l"(g), "r"(sz));
    }
}

__global__ __launch_bounds__(256, 3)
void gemm_tc_kernel(int N, int K,
                    const __nv_bfloat16* __restrict__ Ah, const __nv_bfloat16* __restrict__ Al,
                    const __nv_bfloat16* __restrict__ Bh, const __nv_bfloat16* __restrict__ Bl,
                    const float* __restrict__ bias, const float* __restrict__ res,
                    float* __restrict__ C)
{
    extern __shared__ __align__(16) unsigned char dsm[];
    unsigned sbase = (unsigned)__cvta_generic_to_shared(dsm);
    const int bm = blockIdx.y * 64, bn = blockIdx.x * 128;
    const int tid = threadIdx.x, warp = tid >> 5, lane = tid & 31;
    const int wm = (warp >> 2) * 32, wn = (warp & 3) * 32;
    const int r = lane >> 2, cq = (lane & 3) * 2;

    float acc[2][4][4];
#pragma unroll
    for (int mt = 0; mt < 2; mt++)
#pragma unroll
        for (int j = 0; j < 4; j++)
#pragma unroll
            for (int q = 0; q < 4; q++) acc[mt][j][q] = 0.f;

    const int nk = K / 32;
    gemm_fill_stage(sbase,               tid, bm, bn, 0,  N, K, Ah, Al, Bh, Bl);
    asm volatile("cp.async.commit_group;");
    gemm_fill_stage(sbase + STAGE_BYTES, tid, bm, bn, 32, N, K, Ah, Al, Bh, Bl);
    asm volatile("cp.async.commit_group;");

    for (int kt = 0; kt < nk; kt++) {
        asm volatile("cp.async.wait_group 1;");
        __syncthreads();
        // prefetch stage kt+2 (overwrites stage consumed at iteration kt-1; the
        // barrier above guarantees every thread finished reading it)
        if (kt + 2 < nk)
            gemm_fill_stage(sbase + (unsigned)((kt + 2) % 3) * STAGE_BYTES, tid, bm, bn,
                            (kt + 2) * 32, N, K, Ah, Al, Bh, Bl);
        asm volatile("cp.async.commit_group;");

        unsigned st = sbase + (unsigned)(kt % 3) * STAGE_BYTES;
#pragma unroll
        for (int ks = 0; ks < 2; ks++) {
            const int kb = ks * 16;
            unsigned ah[2][4], al[2][4];
            ldm4(st,         wm,      kb, lane, ah[0]);
            ldm4(st,         wm + 16, kb, lane, ah[1]);
            ldm4(st + 4096u, wm,      kb, lane, al[0]);
            ldm4(st + 4096u, wm + 16, kb, lane, al[1]);
#pragma unroll
            for (int jj = 0; jj < 2; jj++) {
                unsigned bh[4], bl[4];
                ldm4(st + 8192u,  wn + jj * 16, kb, lane, bh);
                ldm4(st + 16384u, wn + jj * 16, kb, lane, bl);
#pragma unroll
                for (int sub = 0; sub < 2; sub++) {
                    int j = jj * 2 + sub;
                    unsigned b0h = bh[sub], b1h = bh[2 + sub];
                    unsigned b0l = bl[sub], b1l = bl[2 + sub];
#pragma unroll
                    for (int mt = 0; mt < 2; mt++) {
                        MMA_BF16(acc[mt][j], ah[mt], b0h, b1h);
                        MMA_BF16(acc[mt][j], ah[mt], b0l, b1l);
                        MMA_BF16(acc[mt][j], al[mt], b0h, b1h);
                    }
                }
            }
        }
    }

    // ---- epilogue: + bias (+ residual) ----
#pragma unroll
    for (int mt = 0; mt < 2; mt++) {
        int row0 = bm + wm + mt * 16 + r;
#pragma unroll
        for (int j = 0; j < 4; j++) {
            int col = bn + wn + j * 8 + cq;
            if (col < N) {
                float b0v = bias[col], b1v = bias[col + 1];
                size_t o0 = (size_t)row0 * N + col;
                size_t o1 = (size_t)(row0 + 8) * N + col;
                float v0 = acc[mt][j][0] + b0v, v1 = acc[mt][j][1] + b1v;
                float v2 = acc[mt][j][2] + b0v, v3 = acc[mt][j][3] + b1v;
                if (res) {
                    v0 += res[o0]; v1 += res[o0 + 1];
                    v2 += res[o1]; v3 += res[o1 + 1];
                }
                C[o0] = v0; C[o0 + 1] = v1;
                C[o1] = v2; C[o1 + 1] = v3;
            }
        }
    }
}

// ---------------- K2: v-assembly + quantum features ----------------
// g_P row layout: [aq 0:64 | kaq 64:128 | qb 128:256 | kb 256:288 | vb 288:320 | va 320:832]
__global__ __launch_bounds__(256, 6)
void tpa_feat_kernel(const float* __restrict__ qeb, const float* __restrict__ vqc,
                     const float* __restrict__ ent) {
    __shared__ float sP[NCAT];
    __shared__ float sVQ[48];
    __shared__ float sQEB[8];
    const int token = blockIdx.x;
    const int b = token / Ss, s = token % Ss;
    const int tid = threadIdx.x;

    const float4* p4 = reinterpret_cast<const float4*>(&g_P[(size_t)token * NCAT]);
    if (tid < NCAT / 4) reinterpret_cast<float4*>(sP)[tid] = p4[tid];
    if (tid >= 192 && tid < 240) sVQ[tid - 192] = __ldg(&vqc[tid - 192]);
    if (tid >= 240 && tid < 248) sQEB[tid - 240] = __ldg(&qeb[tid - 240]);
    __syncthreads();

    // v[kv,d] = sum_r va[r,d] * vb[r,kv]
    {
        int kv = tid >> 6, d = tid & 63;
        float av = 0.f;
#pragma unroll
        for (int r = 0; r < 8; r++) av += sP[320 + r * 64 + d] * sP[288 + r * 4 + kv];
        g_v[(((size_t)(b * KVv + kv)) * Ss + s) * 64 + d] = av;
    }

    // quantum features: one thread per (head, qubit), 20 heads x 8 = 160 threads
    const int oct = tid >> 3, j = tid & 7;
    if (oct < 20) {
        const float ev = __ldg(ent);
        float p = sQEB[j];
        if (oct < 16) {
#pragma unroll
            for (int r = 0; r < 8; r++) p += sP[128 + r * 16 + oct] * sP[r * 8 + j];
        } else {
#pragma unroll
            for (int r = 0; r < 8; r++) p += sP[256 + r * 4 + (oct - 16)] * sP[64 + r * 8 + j];
        }
        float f = tanhf(p) * 3.14159265358979323846f;
#pragma unroll
        for (int l = 0; l < 2; l++) {
            float a0 = sVQ[(l * 8 + j) * 3 + 0];
            float a1 = sVQ[(l * 8 + j) * 3 + 1];
            float a2 = sVQ[(l * 8 + j) * 3 + 2];
            float g = cosf(f + a0) * sinf(f + a1) + cosf(f + a2);
            int srcLane = ((tid & 31) & ~7) | ((j + 7) & 7);
            float gp = __shfl_sync(0xffffffffu, g, srcLane);
            f = g * (1.f + ev * gp);
        }
        float cv = cosf(f), sv = sinf(f);
        float nr = cv * cv + sv * sv;
        nr += __shfl_xor_sync(0xffffffffu, nr, 1);
        nr += __shfl_xor_sync(0xffffffffu, nr, 2);
        nr += __shfl_xor_sync(0xffffffffu, nr, 4);
        float inv = 1.f / (sqrtf(nr) + 1e-6f);
        float* dst = oct < 16
            ? &g_qf[(((size_t)(b * Hh + oct)) * Ss + s) * 16]
            : &g_kf[(((size_t)(b * KVv + (oct - 16))) * Ss + s) * 16];
        dst[j]     = cv * inv;
        dst[j + 8] = sv * inv;
    }
}

// ---------------- Pass A: per-chunk sums of kf (x) v and kf ----------------
__global__ __launch_bounds__(64, 8)
void passA_kernel() {
    const int blk = blockIdx.x;            // (b*KV+kv)*NCH + c
    const int c = blk % NCH;
    const int bk = blk / NCH;
    const int tid = threadIdx.x;           // d
    const float4* kfb = reinterpret_cast<const float4*>(&g_kf[(((size_t)bk) * Ss + c * CHUNK) * 16]);
    const float* vb = &g_v[(((size_t)bk) * Ss + c * CHUNK) * 64];
    float acc[16];
#pragma unroll
    for (int f = 0; f < 16; f++) acc[f] = 0.f;
    float kfs = 0.f;
    for (int t = 0; t < CHUNK; t++) {
        float vd = vb[t * 64 + tid];
        float kv[16]; ld16(kv, kfb + t * 4);
#pragma unroll
        for (int f = 0; f < 16; f++) acc[f] += kv[f] * vd;
        if (tid < 16) kfs += __ldg(&g_kf[(((size_t)bk) * Ss + c * CHUNK + t) * 16 + tid]);
    }
#pragma unroll
    for (int f = 0; f < 16; f++) g_kvc[((size_t)blk * 16 + f) * 64 + tid] = acc[f];
    if (tid < 16) g_kfc[blk * 16 + tid] = kfs;
}

// ---------------- Pass C: chunk prefix + within-chunk scan + query eval ----------------
__global__ __launch_bounds__(64, 8)
void passC_kernel() {
    const int blk = blockIdx.x;
    const int c = blk % NCH;
    const int bk = blk / NCH;
    const int b = bk / KVv, kvh = bk % KVv;
    const int tid = threadIdx.x;           // d
    float st[16], kc[16];
#pragma unroll
    for (int f = 0; f < 16; f++) { st[f] = 0.f; kc[f] = 0.f; }
    for (int cp = 0; cp < c; cp++) {
        int blk2 = bk * NCH + cp;
#pragma unroll
        for (int f = 0; f < 16; f++) {
            st[f] += g_kvc[((size_t)blk2 * 16 + f) * 64 + tid];
            kc[f] += __ldg(&g_kfc[blk2 * 16 + f]);
        }
    }
    const float4* kfb = reinterpret_cast<const float4*>(&g_kf[(((size_t)bk) * Ss + c * CHUNK) * 16]);
    const float* vb = &g_v[(((size_t)bk) * Ss + c * CHUNK) * 64];
    const int h0 = kvh * 4;
    const float4* qfb[4];
#pragma unroll
    for (int hh = 0; hh < 4; hh++)
        qfb[hh] = reinterpret_cast<const float4*>(&g_qf[(((size_t)(b * Hh + h0 + hh)) * Ss + c * CHUNK) * 16]);
    const size_t abase = ((size_t)b * Ss + c * CHUNK) * Ee + h0 * 64 + tid;

    for (int t = 0; t < CHUNK; t++) {
        float vd = vb[t * 64 + tid];
        float kv[16]; ld16(kv, kfb + t * 4);
#pragma unroll
        for (int f = 0; f < 16; f++) { st[f] += kv[f] * vd; kc[f] += kv[f]; }
#pragma unroll
        for (int hh = 0; hh < 4; hh++) {
            float qv[16]; ld16(qv, qfb[hh] + t * 4);
            float num = 0.f, den = 0.f;
#pragma unroll
            for (int f = 0; f < 16; f++) { num += qv[f] * st[f]; den += qv[f] * kc[f]; }
            float val = num / (den + 1e-6f);
            __nv_bfloat16 h, l; split_bf16(val, h, l);
            size_t o = abase + (size_t)t * Ee + hh * 64;
            g_ah[o] = h; g_al[o] = l;
        }
    }
}

// ---------------- LayerNorm (in-place on d_out) ----------------
__global__ __launch_bounds__(256, 4)
void ln_kernel(float* __restrict__ y, const float* __restrict__ gamma, const float* __restrict__ beta) {
    const int row = blockIdx.x, tid = threadIdx.x;
    float4* yr = reinterpret_cast<float4*>(y + (size_t)row * Ee);
    float4 v = yr[tid];
    float s = v.x + v.y + v.z + v.w;
    float q = v.x * v.x + v.y * v.y + v.z * v.z + v.w * v.w;
    __shared__ float sS[8], sQ[8];
    const int lane = tid & 31, wid = tid >> 5;
#pragma unroll
    for (int off = 16; off; off >>= 1) {
        s += __shfl_xor_sync(0xffffffffu, s, off);
        q += __shfl_xor_sync(0xffffffffu, q, off);
    }
    if (lane == 0) { sS[wid] = s; sQ[wid] = q; }
    __syncthreads();
    if (tid == 0) {
        float ts = 0.f, tq = 0.f;
#pragma unroll
        for (int i = 0; i < 8; i++) { ts += sS[i]; tq += sQ[i]; }
        sS[0] = ts; sQ[0] = tq;
    }
    __syncthreads();
    float mu = sS[0] * (1.f / 1024.f);
    float var = sQ[0] * (1.f / 1024.f) - mu * mu;
    float rstd = rsqrtf(var + 1e-5f);
    const float4 gm = reinterpret_cast<const float4*>(gamma)[tid];
    const float4 bt = reinterpret_cast<const float4*>(beta)[tid];
    float4 o;
    o.x = gm.x * (v.x - mu) * rstd + bt.x;
    o.y = gm.y * (v.y - mu) * rstd + bt.y;
    o.z = gm.z * (v.z - mu) * rstd + bt.z;
    o.w = gm.w * (v.w - mu) * rstd + bt.w;
    yr[tid] = o;
}

// ---------------- launch ----------------
extern "C" void kernel_launch(void* const* d_in, const int* in_sizes, int n_in,
                              void* d_out, int out_size) {
    const float* x    = (const float*)d_in[0];
    const float* ctxW = (const float*)d_in[1];
    const float* ctxb = (const float*)d_in[2];
    const float* qaW  = (const float*)d_in[3];
    const float* qab  = (const float*)d_in[4];
    const float* qbW  = (const float*)d_in[5];
    const float* qbb  = (const float*)d_in[6];
    const float* kaW  = (const float*)d_in[7];
    const float* kab  = (const float*)d_in[8];
    const float* kbW  = (const float*)d_in[9];
    const float* kbb  = (const float*)d_in[10];
    const float* vaW  = (const float*)d_in[11];
    const float* vab  = (const float*)d_in[12];
    const float* vbW  = (const float*)d_in[13];
    const float* vbb  = (const float*)d_in[14];
    const float* qeW  = (const float*)d_in[15];
    const float* qeb  = (const float*)d_in[16];
    const float* vqc  = (const float*)d_in[17];
    const float* ent  = (const float*)d_in[18];
    const float* outW = (const float*)d_in[19];
    const float* outb = (const float*)d_in[20];
    const float* gamma = (const float*)d_in[21];
    const float* beta  = (const float*)d_in[22];
    float* out = (float*)d_out;

    cudaFuncSetAttribute(gemm_tc_kernel, cudaFuncAttributeMaxDynamicSharedMemorySize, 3 * (int)STAGE_BYTES);

    pack_comp_kernel<<<1025, 256>>>(ctxW, qaW, kaW, qbW, kbW, vbW,
                                    ctxb, qab, kab, qbb, kbb, vbb, vab, qeW);
    pack_split_kernel<<<1024, 256>>>(vaW, outW);
    convx_kernel<<<1024, 256>>>(x);

    __nv_bfloat16 *p_xh, *p_xl, *p_Wh, *p_Wl, *p_ah, *p_al, *p_oWh, *p_oWl;
    float *p_P, *p_bcat;
    cudaGetSymbolAddress((void**)&p_xh, g_xh);
    cudaGetSymbolAddress((void**)&p_xl, g_xl);
    cudaGetSymbolAddress((void**)&p_Wh, g_Wh);
    cudaGetSymbolAddress((void**)&p_Wl, g_Wl);
    cudaGetSymbolAddress((void**)&p_ah, g_ah);
    cudaGetSymbolAddress((void**)&p_al, g_al);
    cudaGetSymbolAddress((void**)&p_oWh, g_oWh);
    cudaGetSymbolAddress((void**)&p_oWl, g_oWl);
    cudaGetSymbolAddress((void**)&p_P, g_P);
    cudaGetSymbolAddress((void**)&p_bcat, g_bcat);

    dim3 g1((NCAT + 127) / 128, NTOK / 64);
    gemm_tc_kernel<<<g1, 256, 3 * STAGE_BYTES>>>(NCAT, Ee, p_xh, p_xl, p_Wh, p_Wl, p_bcat, nullptr, p_P);

    tpa_feat_kernel<<<NTOK, 256>>>(qeb, vqc, ent);

    passA_kernel<<<Bb * KVv * NCH, 64>>>();
    passC_kernel<<<Bb * KVv * NCH, 64>>>();

    dim3 g2(Ee / 128, NTOK / 64);
    gemm_tc_kernel<<<g2, 256, 3 * STAGE_BYTES>>>(Ee, Ee, p_ah, p_al, p_oWh, p_oWl, outb, x, out);

    ln_kernel<<<NTOK, 256>>>(out, gamma, beta);
}

// round 12
// speedup vs baseline: 4.6945x; 1.0055x over previous
#include <cuda_runtime.h>
#include <cuda_bf16.h>
#include <math.h>

#define Bb 4
#define Ss 2048
#define Ee 1024
#define Hh 16
#define KVv 4
#define HDd 64
#define Rr 8
#define CDd 64
#define NQq 8
#define NCH 32
#define CHUNK 64
#define NTOK (Bb*Ss)      // 8192
#define NCAT 832          // aq 64 | kaq 64 | qb 128 | kb 32 | vb 32 | va 512

// ---------------- scratch (device globals; no cudaMalloc allowed) ----------------
// GEMM B operands stored TRANSPOSED [N][K] for cp.async.
__device__ __align__(16) __nv_bfloat16 g_Wh[(size_t)NCAT * 1024];
__device__ __align__(16) __nv_bfloat16 g_Wl[(size_t)NCAT * 1024];
__device__ __align__(16) __nv_bfloat16 g_oWh[(size_t)1024 * 1024];
__device__ __align__(16) __nv_bfloat16 g_oWl[(size_t)1024 * 1024];
__device__ __align__(16) __nv_bfloat16 g_xh[(size_t)NTOK * Ee];
__device__ __align__(16) __nv_bfloat16 g_xl[(size_t)NTOK * Ee];
__device__ __align__(16) __nv_bfloat16 g_ah[(size_t)NTOK * Ee];
__device__ __align__(16) __nv_bfloat16 g_al[(size_t)NTOK * Ee];
__device__ float g_cw[(size_t)1024 * 320];     // fp32 composite weights [k][n<320]
__device__ float g_bcat[NCAT];
__device__ float g_P[(size_t)NTOK * NCAT];
__device__ float g_v[(size_t)Bb * KVv * Ss * HDd];
__device__ float g_qf[(size_t)Bb * Hh * Ss * 16];
__device__ float g_kf[(size_t)Bb * KVv * Ss * 16];
__device__ float g_kvc[(size_t)Bb * KVv * NCH * 16 * 64];
__device__ float g_kfc[Bb * KVv * NCH * 16];

// ---------------- helpers ----------------
__device__ __forceinline__ void ld16(float* o, const float4* p) {
    float4 a = __ldg(p + 0), b = __ldg(p + 1), c = __ldg(p + 2), d = __ldg(p + 3);
    o[0] = a.x;  o[1] = a.y;  o[2] = a.z;  o[3] = a.w;
    o[4] = b.x;  o[5] = b.y;  o[6] = b.z;  o[7] = b.w;
    o[8] = c.x;  o[9] = c.y;  o[10] = c.z; o[11] = c.w;
    o[12] = d.x; o[13] = d.y; o[14] = d.z; o[15] = d.w;
}

__device__ __forceinline__ void split_bf16(float v, __nv_bfloat16& h, __nv_bfloat16& l) {
    h = __float2bfloat16_rn(v);
    l = __float2bfloat16_rn(v - __bfloat162float(h));
}

#define MMA_BF16(d, a, b0, b1)                                              \
    asm volatile("mma.sync.aligned.m16n8k16.row.col.f32.bf16.bf16.f32 "     \
                 "{%0,%1,%2,%3}, {%4,%5,%6,%7}, {%8,%9}, {%0,%1,%2,%3};"    \
                 : "+f"(d[0]), "+f"(d[1]), "+f"(d[2]), "+f"(d[3])           \
                 : "r"(a[0]), "r"(a[1]), "r"(a[2]), "r"(a[3]),              \
                   "r"(b0), "r"(b1))

#define LDM4A(rr, addr)                                                     \
    asm volatile("ldmatrix.sync.aligned.m8n8.x4.shared.b16 {%0,%1,%2,%3}, [%4];" \
                 : "=r"((rr)[0]), "=r"((rr)[1]), "=r"((rr)[2]), "=r"((rr)[3]) \
                 : "r"(addr))

// ---------------- K0a: composite weights, fp32, [k][n] (coalesced writes) ----------------
__global__ void pack_comp_kernel(
    const float* __restrict__ ctxW, const float* __restrict__ qaW, const float* __restrict__ kaW,
    const float* __restrict__ qbW,  const float* __restrict__ kbW, const float* __restrict__ vbW,
    const float* __restrict__ ctxb, const float* __restrict__ qab, const float* __restrict__ kab,
    const float* __restrict__ qbb,  const float* __restrict__ kbb, const float* __restrict__ vbb,
    const float* __restrict__ vab,  const float* __restrict__ qeW)
{
    const int k = blockIdx.x;
    const int tid = threadIdx.x;
    if (k < 1024) {
        __shared__ float sA[512], sKA[512], sCtx[64];
        for (int i = tid; i < 512; i += 256) { sA[i] = qaW[(size_t)k * 512 + i]; sKA[i] = kaW[(size_t)k * 512 + i]; }
        if (tid < 64) sCtx[tid] = ctxW[k * 64 + tid];
        __syncthreads();
        for (int n = tid; n < 320; n += 256) {
            float v = 0.f;
            if (n < 64) {
                int r = n >> 3, j = n & 7;
#pragma unroll 8
                for (int d = 0; d < 64; d++) v += sA[r * 64 + d] * __ldg(&qeW[d * 8 + j]);
            } else if (n < 128) {
                int m = n - 64, r = m >> 3, j = m & 7;
#pragma unroll 8
                for (int d = 0; d < 64; d++) v += sKA[r * 64 + d] * __ldg(&qeW[d * 8 + j]);
            } else if (n < 256) {
                int h = n - 128;
#pragma unroll 8
                for (int c = 0; c < 64; c++) v += sCtx[c] * __ldg(&qbW[c * 128 + h]);
            } else if (n < 288) {
                int h = n - 256;
#pragma unroll 8
                for (int c = 0; c < 64; c++) v += sCtx[c] * __ldg(&kbW[c * 32 + h]);
            } else {
                int h = n - 288;
#pragma unroll 8
                for (int c = 0; c < 64; c++) v += sCtx[c] * __ldg(&vbW[c * 32 + h]);
            }
            g_cw[(size_t)k * 320 + n] = v;
        }
    } else {
        for (int n = tid; n < NCAT; n += 256) {
            float v = 0.f;
            if (n < 64) {
                int r = n >> 3, j = n & 7;
                for (int d = 0; d < 64; d++) v += __ldg(&qab[r * 64 + d]) * __ldg(&qeW[d * 8 + j]);
            } else if (n < 128) {
                int m = n - 64, r = m >> 3, j = m & 7;
                for (int d = 0; d < 64; d++) v += __ldg(&kab[r * 64 + d]) * __ldg(&qeW[d * 8 + j]);
            } else if (n < 256) {
                int h = n - 128; v = qbb[h];
                for (int c = 0; c < 64; c++) v += ctxb[c] * __ldg(&qbW[c * 128 + h]);
            } else if (n < 288) {
                int h = n - 256; v = kbb[h];
                for (int c = 0; c < 64; c++) v += ctxb[c] * __ldg(&kbW[c * 32 + h]);
            } else if (n < 320) {
                int h = n - 288; v = vbb[h];
                for (int c = 0; c < 64; c++) v += ctxb[c] * __ldg(&vbW[c * 32 + h]);
            } else {
                v = vab[n - 320];
            }
            g_bcat[n] = v;
        }
    }
}

// ---------------- K0b: split weights to bf16 hi/lo, [n][k] layout ----------------
__global__ void pack_split_kernel(const float* __restrict__ vaW, const float* __restrict__ outW) {
    const size_t totalW = (size_t)NCAT * 1024;
    for (size_t i = blockIdx.x * blockDim.x + threadIdx.x; i < totalW; i += (size_t)gridDim.x * blockDim.x) {
        int k = (int)(i & 1023), n = (int)(i >> 10);
        float v = (n < 320) ? g_cw[(size_t)k * 320 + n]
                            : __ldg(&vaW[(size_t)k * 512 + (n - 320)]);
        __nv_bfloat16 h, l; split_bf16(v, h, l);
        g_Wh[i] = h; g_Wl[i] = l;
    }
    const size_t total2 = (size_t)1024 * 1024;
    for (size_t i = blockIdx.x * blockDim.x + threadIdx.x; i < total2; i += (size_t)gridDim.x * blockDim.x) {
        int k = (int)(i & 1023);
        int n = (int)(i >> 10);
        __nv_bfloat16 h, l; split_bf16(__ldg(&outW[(size_t)k * 1024 + n]), h, l);
        g_oWh[i] = h; g_oWl[i] = l;
    }
}

// ---------------- K0c: split x to bf16 hi/lo ----------------
__global__ void convx_kernel(const float* __restrict__ x) {
    const int total4 = NTOK * Ee / 4;
    for (int i = blockIdx.x * blockDim.x + threadIdx.x; i < total4; i += gridDim.x * blockDim.x) {
        float4 v = reinterpret_cast<const float4*>(x)[i];
        __nv_bfloat16 h0, l0, h1, l1, h2, l2, h3, l3;
        split_bf16(v.x, h0, l0); split_bf16(v.y, h1, l1);
        split_bf16(v.z, h2, l2); split_bf16(v.w, h3, l3);
        __nv_bfloat162 a; a.x = h0; a.y = h1;
        __nv_bfloat162 b; b.x = h2; b.y = h3;
        __nv_bfloat162 c; c.x = l0; c.y = l1;
        __nv_bfloat162 d; d.x = l2; d.y = l3;
        reinterpret_cast<__nv_bfloat162*>(g_xh)[i * 2]     = a;
        reinterpret_cast<__nv_bfloat162*>(g_xh)[i * 2 + 1] = b;
        reinterpret_cast<__nv_bfloat162*>(g_xl)[i * 2]     = c;
        reinterpret_cast<__nv_bfloat162*>(g_xl)[i * 2 + 1] = d;
    }
}

// ---------------- tensor-core GEMM, single-sync 3-stage cp.async pipeline ----------------
// C[M,N] = (Ah+Al)[M,K] @ (Bh+Bl)^T, B stored [N][K]; 3-term bf16 split.
// BM=64, BN=128, BK=32, 256 thr, 3 CTAs/SM.
// Stage layout: Ah@0 (4KB) | Al@4K | Bh@8K (8KB) | Bl@16K; stage = 24KB x 3 = 72KB.
// Smem 16B-chunk swizzle: phys_chunk = ch ^ ((row>>1)&3).
// Addresses hoisted: 6 persistent global ptrs per thread (+32 elem per stage),
// fragment offsets reduced to 2 bases (row+16 => +1024, same swizzle; ks => ^0x20).
#define STAGE_BYTES 24576u

__global__ __launch_bounds__(256, 3)
void gemm_tc_kernel(int N, int K,
                    const __nv_bfloat16* __restrict__ Ah, const __nv_bfloat16* __restrict__ Al,
                    const __nv_bfloat16* __restrict__ Bh, const __nv_bfloat16* __restrict__ Bl,
                    const float* __restrict__ bias, const float* __restrict__ res,
                    float* __restrict__ C)
{
    extern __shared__ __align__(16) unsigned char dsm[];
    unsigned sbase = (unsigned)__cvta_generic_to_shared(dsm);
    const int bm = blockIdx.y * 64, bn = blockIdx.x * 128;
    const int tid = threadIdx.x, warp = tid >> 5, lane = tid & 31;
    const int wm = (warp >> 2) * 32, wn = (warp & 3) * 32;
    const int r = lane >> 2, cq = (lane & 3) * 2;

    // ---- persistent fill-task state (pointers advance +32 elems per stage) ----
    const __nv_bfloat16* gp[6];
    unsigned doff[6], fsz[6];
#pragma unroll
    for (int w = 0; w < 6; w++) {
        int tsk = tid + w * 256;             // 0..1535 16B-chunks of one stage
        int row, ch;
        unsigned abase;
        const __nv_bfloat16* g;
        unsigned s = 16;
        if (tsk < 512) {                     // A: 64 rows x 4 chunks, hi | lo
            int a = tsk >> 8;
            int sub = tsk & 255;
            row = sub >> 2; ch = sub & 3;
            abase = (unsigned)a * 4096u;
            g = (a ? Al : Ah) + (size_t)(bm + row) * K + ch * 8;
        } else {                             // B: 128 rows x 4 chunks, hi | lo
            int t2 = tsk - 512;
            int a = t2 >> 9;
            int sub = t2 & 511;
            row = sub >> 2; ch = sub & 3;
            abase = 8192u + (unsigned)a * 8192u;
            int n = bn + row;
            int nc = n < N ? n : 0;
            s = n < N ? 16u : 0u;
            g = (a ? Bl : Bh) + (size_t)nc * K + ch * 8;
        }
        gp[w] = g; fsz[w] = s;
        doff[w] = abase + (unsigned)(row * 64 + ((ch ^ ((row >> 1) & 3)) << 4));
    }

#define FILL_STAGE(ST) do {                                                  \
    _Pragma("unroll")                                                        \
    for (int w = 0; w < 6; w++) {                                            \
        asm volatile("cp.async.cg.shared.global [%0], [%1], 16, %2;"         \
                     :: "r"((ST) + doff[w]), "l"(gp[w]), "r"(fsz[w]));       \
        gp[w] += 32;                                                         \
    }                                                                        \
    asm volatile("cp.async.commit_group;");                                  \
} while (0)

    // ---- fragment base offsets (within a stage) ----
    unsigned oA, oB;
    {
        int rA = wm + (lane & 15);
        int rB = wn + (lane & 15);
        int ch0 = lane >> 4;
        oA = (unsigned)(rA * 64 + ((ch0 ^ ((rA >> 1) & 3)) << 4));
        oB = 8192u + (unsigned)(rB * 64 + ((ch0 ^ ((rB >> 1) & 3)) << 4));
    }

    float acc[2][4][4];
#pragma unroll
    for (int mt = 0; mt < 2; mt++)
#pragma unroll
        for (int j = 0; j < 4; j++)
#pragma unroll
            for (int q = 0; q < 4; q++) acc[mt][j][q] = 0.f;

    const int nk = K / 32;
    FILL_STAGE(sbase);
    FILL_STAGE(sbase + STAGE_BYTES);

    for (int kt = 0; kt < nk; kt++) {
        asm volatile("cp.async.wait_group 1;");
        __syncthreads();
        if (kt + 2 < nk) {
            FILL_STAGE(sbase + (unsigned)((kt + 2) % 3) * STAGE_BYTES);
        } else {
            asm volatile("cp.async.commit_group;");
        }

        const unsigned st = sbase + (unsigned)(kt % 3) * STAGE_BYTES;
        const unsigned aab = st + oA;
        const unsigned bbb = st + oB;
#pragma unroll
        for (int ks = 0; ks < 2; ks++) {
            const unsigned xk = (unsigned)ks * 32u;
            unsigned ah[2][4], al[2][4];
            LDM4A(ah[0], aab ^ xk);
            LDM4A(ah[1], (aab + 1024u) ^ xk);
            LDM4A(al[0], (aab + 4096u) ^ xk);
            LDM4A(al[1], (aab + 5120u) ^ xk);
#pragma unroll
            for (int jj = 0; jj < 2; jj++) {
                unsigned bh[4], bl[4];
                LDM4A(bh, (bbb + (unsigned)jj * 1024u) ^ xk);
                LDM4A(bl, (bbb + 8192u + (unsigned)jj * 1024u) ^ xk);
                // term-outer ordering: 4 independent MMAs between acc reuses
#pragma unroll
                for (int sub = 0; sub < 2; sub++)
#pragma unroll
                    for (int mt = 0; mt < 2; mt++)
                        MMA_BF16(acc[mt][jj * 2 + sub], ah[mt], bh[sub], bh[2 + sub]);
#pragma unroll
                for (int sub = 0; sub < 2; sub++)
#pragma unroll
                    for (int mt = 0; mt < 2; mt++)
                        MMA_BF16(acc[mt][jj * 2 + sub], ah[mt], bl[sub], bl[2 + sub]);
#pragma unroll
                for (int sub = 0; sub < 2; sub++)
#pragma unroll
                    for (int mt = 0; mt < 2; mt++)
                        MMA_BF16(acc[mt][jj * 2 + sub], al[mt], bh[sub], bh[2 + sub]);
            }
        }
    }

    // ---- epilogue: + bias (+ residual) ----
#pragma unroll
    for (int mt = 0; mt < 2; mt++) {
        int row0 = bm + wm + mt * 16 + r;
#pragma unroll
        for (int j = 0; j < 4; j++) {
            int col = bn + wn + j * 8 + cq;
            if (col < N) {
                float b0v = bias[col], b1v = bias[col + 1];
                size_t o0 = (size_t)row0 * N + col;
                size_t o1 = (size_t)(row0 + 8) * N + col;
                float v0 = acc[mt][j][0] + b0v, v1 = acc[mt][j][1] + b1v;
                float v2 = acc[mt][j][2] + b0v, v3 = acc[mt][j][3] + b1v;
                if (res) {
                    v0 += res[o0]; v1 += res[o0 + 1];
                    v2 += res[o1]; v3 += res[o1 + 1];
                }
                C[o0] = v0; C[o0 + 1] = v1;
                C[o1] = v2; C[o1 + 1] = v3;
            }
        }
    }
#undef FILL_STAGE
}

// ---------------- K2: v-assembly + quantum features ----------------
// g_P row layout: [aq 0:64 | kaq 64:128 | qb 128:256 | kb 256:288 | vb 288:320 | va 320:832]
__global__ __launch_bounds__(256, 6)
void tpa_feat_kernel(const float* __restrict__ qeb, const float* __restrict__ vqc,
                     const float* __restrict__ ent) {
    __shared__ float sP[NCAT];
    __shared__ float sVQ[48];
    __shared__ float sQEB[8];
    const int token = blockIdx.x;
    const int b = token / Ss, s = token % Ss;
    const int tid = threadIdx.x;

    const float4* p4 = reinterpret_cast<const float4*>(&g_P[(size_t)token * NCAT]);
    if (tid < NCAT / 4) reinterpret_cast<float4*>(sP)[tid] = p4[tid];
    if (tid >= 192 && tid < 240) sVQ[tid - 192] = __ldg(&vqc[tid - 192]);
    if (tid >= 240 && tid < 248) sQEB[tid - 240] = __ldg(&qeb[tid - 240]);
    __syncthreads();

    // v[kv,d] = sum_r va[r,d] * vb[r,kv]
    {
        int kv = tid >> 6, d = tid & 63;
        float av = 0.f;
#pragma unroll
        for (int r = 0; r < 8; r++) av += sP[320 + r * 64 + d] * sP[288 + r * 4 + kv];
        g_v[(((size_t)(b * KVv + kv)) * Ss + s) * 64 + d] = av;
    }

    // quantum features: one thread per (head, qubit), 20 heads x 8 = 160 threads
    const int oct = tid >> 3, j = tid & 7;
    if (oct < 20) {
        const float ev = __ldg(ent);
        float p = sQEB[j];
        if (oct < 16) {
#pragma unroll
            for (int r = 0; r < 8; r++) p += sP[128 + r * 16 + oct] * sP[r * 8 + j];
        } else {
#pragma unroll
            for (int r = 0; r < 8; r++) p += sP[256 + r * 4 + (oct - 16)] * sP[64 + r * 8 + j];
        }
        float f = tanhf(p) * 3.14159265358979323846f;
#pragma unroll
        for (int l = 0; l < 2; l++) {
            float a0 = sVQ[(l * 8 + j) * 3 + 0];
            float a1 = sVQ[(l * 8 + j) * 3 + 1];
            float a2 = sVQ[(l * 8 + j) * 3 + 2];
            float g = cosf(f + a0) * sinf(f + a1) + cosf(f + a2);
            int srcLane = ((tid & 31) & ~7) | ((j + 7) & 7);
            float gp = __shfl_sync(0xffffffffu, g, srcLane);
            f = g * (1.f + ev * gp);
        }
        float cv = cosf(f), sv = sinf(f);
        float nr = cv * cv + sv * sv;
        nr += __shfl_xor_sync(0xffffffffu, nr, 1);
        nr += __shfl_xor_sync(0xffffffffu, nr, 2);
        nr += __shfl_xor_sync(0xffffffffu, nr, 4);
        float inv = 1.f / (sqrtf(nr) + 1e-6f);
        float* dst = oct < 16
            ? &g_qf[(((size_t)(b * Hh + oct)) * Ss + s) * 16]
            : &g_kf[(((size_t)(b * KVv + (oct - 16))) * Ss + s) * 16];
        dst[j]     = cv * inv;
        dst[j + 8] = sv * inv;
    }
}

// ---------------- Pass A: per-chunk sums of kf (x) v and kf ----------------
__global__ __launch_bounds__(64, 8)
void passA_kernel() {
    const int blk = blockIdx.x;            // (b*KV+kv)*NCH + c
    const int c = blk % NCH;
    const int bk = blk / NCH;
    const int tid = threadIdx.x;           // d
    const float4* kfb = reinterpret_cast<const float4*>(&g_kf[(((size_t)bk) * Ss + c * CHUNK) * 16]);
    const float* vb = &g_v[(((size_t)bk) * Ss + c * CHUNK) * 64];
    float acc[16];
#pragma unroll
    for (int f = 0; f < 16; f++) acc[f] = 0.f;
    float kfs = 0.f;
    for (int t = 0; t < CHUNK; t++) {
        float vd = vb[t * 64 + tid];
        float kv[16]; ld16(kv, kfb + t * 4);
#pragma unroll
        for (int f = 0; f < 16; f++) acc[f] += kv[f] * vd;
        if (tid < 16) kfs += __ldg(&g_kf[(((size_t)bk) * Ss + c * CHUNK + t) * 16 + tid]);
    }
#pragma unroll
    for (int f = 0; f < 16; f++) g_kvc[((size_t)blk * 16 + f) * 64 + tid] = acc[f];
    if (tid < 16) g_kfc[blk * 16 + tid] = kfs;
}

// ---------------- Pass C: chunk prefix + within-chunk scan + query eval ----------------
__global__ __launch_bounds__(64, 8)
void passC_kernel() {
    const int blk = blockIdx.x;
    const int c = blk % NCH;
    const int bk = blk / NCH;
    const int b = bk / KVv, kvh = bk % KVv;
    const int tid = threadIdx.x;           // d
    float st[16], kc[16];
#pragma unroll
    for (int f = 0; f < 16; f++) { st[f] = 0.f; kc[f] = 0.f; }
    for (int cp = 0; cp < c; cp++) {
        int blk2 = bk * NCH + cp;
#pragma unroll
        for (int f = 0; f < 16; f++) {
            st[f] += g_kvc[((size_t)blk2 * 16 + f) * 64 + tid];
            kc[f] += __ldg(&g_kfc[blk2 * 16 + f]);
        }
    }
    const float4* kfb = reinterpret_cast<const float4*>(&g_kf[(((size_t)bk) * Ss + c * CHUNK) * 16]);
    const float* vb = &g_v[(((size_t)bk) * Ss + c * CHUNK) * 64];
    const int h0 = kvh * 4;
    const float4* qfb[4];
#pragma unroll
    for (int hh = 0; hh < 4; hh++)
        qfb[hh] = reinterpret_cast<const float4*>(&g_qf[(((size_t)(b * Hh + h0 + hh)) * Ss + c * CHUNK) * 16]);
    const size_t abase = ((size_t)b * Ss + c * CHUNK) * Ee + h0 * 64 + tid;

    for (int t = 0; t < CHUNK; t++) {
        float vd = vb[t * 64 + tid];
        float kv[16]; ld16(kv, kfb + t * 4);
#pragma unroll
        for (int f = 0; f < 16; f++) { st[f] += kv[f] * vd; kc[f] += kv[f]; }
#pragma unroll
        for (int hh = 0; hh < 4; hh++) {
            float qv[16]; ld16(qv, qfb[hh] + t * 4);
            float num = 0.f, den = 0.f;
#pragma unroll
            for (int f = 0; f < 16; f++) { num += qv[f] * st[f]; den += qv[f] * kc[f]; }
            float val = num / (den + 1e-6f);
            __nv_bfloat16 h, l; split_bf16(val, h, l);
            size_t o = abase + (size_t)t * Ee + hh * 64;
            g_ah[o] = h; g_al[o] = l;
        }
    }
}

// ---------------- LayerNorm (in-place on d_out) ----------------
__global__ __launch_bounds__(256, 4)
void ln_kernel(float* __restrict__ y, const float* __restrict__ gamma, const float* __restrict__ beta) {
    const int row = blockIdx.x, tid = threadIdx.x;
    float4* yr = reinterpret_cast<float4*>(y + (size_t)row * Ee);
    float4 v = yr[tid];
    float s = v.x + v.y + v.z + v.w;
    float q = v.x * v.x + v.y * v.y + v.z * v.z + v.w * v.w;
    __shared__ float sS[8], sQ[8];
    const int lane = tid & 31, wid = tid >> 5;
#pragma unroll
    for (int off = 16; off; off >>= 1) {
        s += __shfl_xor_sync(0xffffffffu, s, off);
        q += __shfl_xor_sync(0xffffffffu, q, off);
    }
    if (lane == 0) { sS[wid] = s; sQ[wid] = q; }
    __syncthreads();
    if (tid == 0) {
        float ts = 0.f, tq = 0.f;
#pragma unroll
        for (int i = 0; i < 8; i++) { ts += sS[i]; tq += sQ[i]; }
        sS[0] = ts; sQ[0] = tq;
    }
    __syncthreads();
    float mu = sS[0] * (1.f / 1024.f);
    float var = sQ[0] * (1.f / 1024.f) - mu * mu;
    float rstd = rsqrtf(var + 1e-5f);
    const float4 gm = reinterpret_cast<const float4*>(gamma)[tid];
    const float4 bt = reinterpret_cast<const float4*>(beta)[tid];
    float4 o;
    o.x = gm.x * (v.x - mu) * rstd + bt.x;
    o.y = gm.y * (v.y - mu) * rstd + bt.y;
    o.z = gm.z * (v.z - mu) * rstd + bt.z;
    o.w = gm.w * (v.w - mu) * rstd + bt.w;
    yr[tid] = o;
}

// ---------------- launch ----------------
extern "C" void kernel_launch(void* const* d_in, const int* in_sizes, int n_in,
                              void* d_out, int out_size) {
    const float* x    = (const float*)d_in[0];
    const float* ctxW = (const float*)d_in[1];
    const float* ctxb = (const float*)d_in[2];
    const float* qaW  = (const float*)d_in[3];
    const float* qab  = (const float*)d_in[4];
    const float* qbW  = (const float*)d_in[5];
    const float* qbb  = (const float*)d_in[6];
    const float* kaW  = (const float*)d_in[7];
    const float* kab  = (const float*)d_in[8];
    const float* kbW  = (const float*)d_in[9];
    const float* kbb  = (const float*)d_in[10];
    const float* vaW  = (const float*)d_in[11];
    const float* vab  = (const float*)d_in[12];
    const float* vbW  = (const float*)d_in[13];
    const float* vbb  = (const float*)d_in[14];
    const float* qeW  = (const float*)d_in[15];
    const float* qeb  = (const float*)d_in[16];
    const float* vqc  = (const float*)d_in[17];
    const float* ent  = (const float*)d_in[18];
    const float* outW = (const float*)d_in[19];
    const float* outb = (const float*)d_in[20];
    const float* gamma = (const float*)d_in[21];
    const float* beta  = (const float*)d_in[22];
    float* out = (float*)d_out;

    cudaFuncSetAttribute(gemm_tc_kernel, cudaFuncAttributeMaxDynamicSharedMemorySize, 3 * (int)STAGE_BYTES);

    pack_comp_kernel<<<1025, 256>>>(ctxW, qaW, kaW, qbW, kbW, vbW,
                                    ctxb, qab, kab, qbb, kbb, vbb, vab, qeW);
    pack_split_kernel<<<1024, 256>>>(vaW, outW);
    convx_kernel<<<1024, 256>>>(x);

    __nv_bfloat16 *p_xh, *p_xl, *p_Wh, *p_Wl, *p_ah, *p_al, *p_oWh, *p_oWl;
    float *p_P, *p_bcat;
    cudaGetSymbolAddress((void**)&p_xh, g_xh);
    cudaGetSymbolAddress((void**)&p_xl, g_xl);
    cudaGetSymbolAddress((void**)&p_Wh, g_Wh);
    cudaGetSymbolAddress((void**)&p_Wl, g_Wl);
    cudaGetSymbolAddress((void**)&p_ah, g_ah);
    cudaGetSymbolAddress((void**)&p_al, g_al);
    cudaGetSymbolAddress((void**)&p_oWh, g_oWh);
    cudaGetSymbolAddress((void**)&p_oWl, g_oWl);
    cudaGetSymbolAddress((void**)&p_P, g_P);
    cudaGetSymbolAddress((void**)&p_bcat, g_bcat);

    dim3 g1((NCAT + 127) / 128, NTOK / 64);
    gemm_tc_kernel<<<g1, 256, 3 * STAGE_BYTES>>>(NCAT, Ee, p_xh, p_xl, p_Wh, p_Wl, p_bcat, nullptr, p_P);

    tpa_feat_kernel<<<NTOK, 256>>>(qeb, vqc, ent);

    passA_kernel<<<Bb * KVv * NCH, 64>>>();
    passC_kernel<<<Bb * KVv * NCH, 64>>>();

    dim3 g2(Ee / 128, NTOK / 64);
    gemm_tc_kernel<<<g2, 256, 3 * STAGE_BYTES>>>(Ee, Ee, p_ah, p_al, p_oWh, p_oWl, outb, x, out);

    ln_kernel<<<NTOK, 256>>>(out, gamma, beta);
}

// round 13
// speedup vs baseline: 7.4859x; 1.5946x over previous
#include <cuda_runtime.h>
#include <cuda_fp16.h>
#include <math.h>

#define Bb 4
#define Ss 2048
#define Ee 1024
#define Hh 16
#define KVv 4
#define HDd 64
#define Rr 8
#define CDd 64
#define NQq 8
#define NCH 32
#define CHUNK 64
#define NTOK (Bb*Ss)      // 8192
#define NCAT 832          // aq 64 | kaq 64 | qb 128 | kb 32 | vb 32 | va 512

// ---------------- scratch (device globals; no cudaMalloc allowed) ----------------
// GEMM B operands stored TRANSPOSED [N][K] for cp.async. Single fp16 precision.
__device__ __align__(16) __half g_W[(size_t)NCAT * 1024];
__device__ __align__(16) __half g_oW[(size_t)1024 * 1024];
__device__ __align__(16) __half g_x[(size_t)NTOK * Ee];
__device__ __align__(16) __half g_a[(size_t)NTOK * Ee];
__device__ float g_cw[(size_t)1024 * 320];     // fp32 composite weights [k][n<320]
__device__ float g_bcat[NCAT];
__device__ float g_P[(size_t)NTOK * NCAT];
__device__ float g_v[(size_t)Bb * KVv * Ss * HDd];
__device__ float g_qf[(size_t)Bb * Hh * Ss * 16];
__device__ float g_kf[(size_t)Bb * KVv * Ss * 16];
__device__ float g_kvc[(size_t)Bb * KVv * NCH * 16 * 64];
__device__ float g_kfc[Bb * KVv * NCH * 16];

// ---------------- helpers ----------------
__device__ __forceinline__ void ld16(float* o, const float4* p) {
    float4 a = __ldg(p + 0), b = __ldg(p + 1), c = __ldg(p + 2), d = __ldg(p + 3);
    o[0] = a.x;  o[1] = a.y;  o[2] = a.z;  o[3] = a.w;
    o[4] = b.x;  o[5] = b.y;  o[6] = b.z;  o[7] = b.w;
    o[8] = c.x;  o[9] = c.y;  o[10] = c.z; o[11] = c.w;
    o[12] = d.x; o[13] = d.y; o[14] = d.z; o[15] = d.w;
}

#define MMA_F16(d, a, b0, b1)                                               \
    asm volatile("mma.sync.aligned.m16n8k16.row.col.f32.f16.f16.f32 "       \
                 "{%0,%1,%2,%3}, {%4,%5,%6,%7}, {%8,%9}, {%0,%1,%2,%3};"    \
                 : "+f"(d[0]), "+f"(d[1]), "+f"(d[2]), "+f"(d[3])           \
                 : "r"(a[0]), "r"(a[1]), "r"(a[2]), "r"(a[3]),              \
                   "r"(b0), "r"(b1))

#define LDM4A(rr, addr)                                                     \
    asm volatile("ldmatrix.sync.aligned.m8n8.x4.shared.b16 {%0,%1,%2,%3}, [%4];" \
                 : "=r"((rr)[0]), "=r"((rr)[1]), "=r"((rr)[2]), "=r"((rr)[3]) \
                 : "r"(addr))

// ---------------- K0a: composite weights, fp32, [k][n] (coalesced writes) ----------------
__global__ void pack_comp_kernel(
    const float* __restrict__ ctxW, const float* __restrict__ qaW, const float* __restrict__ kaW,
    const float* __restrict__ qbW,  const float* __restrict__ kbW, const float* __restrict__ vbW,
    const float* __restrict__ ctxb, const float* __restrict__ qab, const float* __restrict__ kab,
    const float* __restrict__ qbb,  const float* __restrict__ kbb, const float* __restrict__ vbb,
    const float* __restrict__ vab,  const float* __restrict__ qeW)
{
    const int k = blockIdx.x;
    const int tid = threadIdx.x;
    if (k < 1024) {
        __shared__ float sA[512], sKA[512], sCtx[64];
        for (int i = tid; i < 512; i += 256) { sA[i] = qaW[(size_t)k * 512 + i]; sKA[i] = kaW[(size_t)k * 512 + i]; }
        if (tid < 64) sCtx[tid] = ctxW[k * 64 + tid];
        __syncthreads();
        for (int n = tid; n < 320; n += 256) {
            float v = 0.f;
            if (n < 64) {
                int r = n >> 3, j = n & 7;
#pragma unroll 8
                for (int d = 0; d < 64; d++) v += sA[r * 64 + d] * __ldg(&qeW[d * 8 + j]);
            } else if (n < 128) {
                int m = n - 64, r = m >> 3, j = m & 7;
#pragma unroll 8
                for (int d = 0; d < 64; d++) v += sKA[r * 64 + d] * __ldg(&qeW[d * 8 + j]);
            } else if (n < 256) {
                int h = n - 128;
#pragma unroll 8
                for (int c = 0; c < 64; c++) v += sCtx[c] * __ldg(&qbW[c * 128 + h]);
            } else if (n < 288) {
                int h = n - 256;
#pragma unroll 8
                for (int c = 0; c < 64; c++) v += sCtx[c] * __ldg(&kbW[c * 32 + h]);
            } else {
                int h = n - 288;
#pragma unroll 8
                for (int c = 0; c < 64; c++) v += sCtx[c] * __ldg(&vbW[c * 32 + h]);
            }
            g_cw[(size_t)k * 320 + n] = v;
        }
    } else {
        for (int n = tid; n < NCAT; n += 256) {
            float v = 0.f;
            if (n < 64) {
                int r = n >> 3, j = n & 7;
                for (int d = 0; d < 64; d++) v += __ldg(&qab[r * 64 + d]) * __ldg(&qeW[d * 8 + j]);
            } else if (n < 128) {
                int m = n - 64, r = m >> 3, j = m & 7;
                for (int d = 0; d < 64; d++) v += __ldg(&kab[r * 64 + d]) * __ldg(&qeW[d * 8 + j]);
            } else if (n < 256) {
                int h = n - 128; v = qbb[h];
                for (int c = 0; c < 64; c++) v += ctxb[c] * __ldg(&qbW[c * 128 + h]);
            } else if (n < 288) {
                int h = n - 256; v = kbb[h];
                for (int c = 0; c < 64; c++) v += ctxb[c] * __ldg(&kbW[c * 32 + h]);
            } else if (n < 320) {
                int h = n - 288; v = vbb[h];
                for (int c = 0; c < 64; c++) v += ctxb[c] * __ldg(&vbW[c * 32 + h]);
            } else {
                v = vab[n - 320];
            }
            g_bcat[n] = v;
        }
    }
}

// ---------------- K0b: weights -> fp16, [n][k] layout ----------------
__global__ void pack_split_kernel(const float* __restrict__ vaW, const float* __restrict__ outW) {
    const size_t totalW = (size_t)NCAT * 1024;
    for (size_t i = blockIdx.x * blockDim.x + threadIdx.x; i < totalW; i += (size_t)gridDim.x * blockDim.x) {
        int k = (int)(i & 1023), n = (int)(i >> 10);
        float v = (n < 320) ? g_cw[(size_t)k * 320 + n]
                            : __ldg(&vaW[(size_t)k * 512 + (n - 320)]);
        g_W[i] = __float2half_rn(v);
    }
    const size_t total2 = (size_t)1024 * 1024;
    for (size_t i = blockIdx.x * blockDim.x + threadIdx.x; i < total2; i += (size_t)gridDim.x * blockDim.x) {
        int k = (int)(i & 1023);
        int n = (int)(i >> 10);
        g_oW[i] = __float2half_rn(__ldg(&outW[(size_t)k * 1024 + n]));
    }
}

// ---------------- K0c: x -> fp16 ----------------
__global__ void convx_kernel(const float* __restrict__ x) {
    const int total4 = NTOK * Ee / 4;
    for (int i = blockIdx.x * blockDim.x + threadIdx.x; i < total4; i += gridDim.x * blockDim.x) {
        float4 v = reinterpret_cast<const float4*>(x)[i];
        __half2 a; a.x = __float2half_rn(v.x); a.y = __float2half_rn(v.y);
        __half2 b; b.x = __float2half_rn(v.z); b.y = __float2half_rn(v.w);
        reinterpret_cast<__half2*>(g_x)[i * 2]     = a;
        reinterpret_cast<__half2*>(g_x)[i * 2 + 1] = b;
    }
}

// ---------------- tensor-core GEMM, single fp16 term, 3-stage cp.async ----------------
// C[M,N] = A[M,K] @ B^T, A/B fp16, B stored [N][K], fp32 accumulate.
// BM=64, BN=128, BK=64, 256 thr, 3 CTAs/SM.
// Stage: A 64x64 fp16 (8KB) @0 | B 128x64 (16KB) @8K; stage = 24KB x 3 = 72KB.
// Rows are 128B (8 x 16B chunks); swizzle: phys_chunk = ch ^ (row & 7).
#define STAGE_BYTES 24576u

__global__ __launch_bounds__(256, 3)
void gemm_tc_kernel(int N, int K,
                    const __half* __restrict__ Ap, const __half* __restrict__ Bp,
                    const float* __restrict__ bias, const float* __restrict__ res,
                    float* __restrict__ C)
{
    extern __shared__ __align__(16) unsigned char dsm[];
    unsigned sbase = (unsigned)__cvta_generic_to_shared(dsm);
    const int bm = blockIdx.y * 64, bn = blockIdx.x * 128;
    const int tid = threadIdx.x, warp = tid >> 5, lane = tid & 31;
    const int wm = (warp >> 2) * 32, wn = (warp & 3) * 32;
    const int r = lane >> 2, cq = (lane & 3) * 2;

    // ---- persistent fill-task state (pointers advance +64 elems per stage) ----
    const __half* gp[6];
    unsigned doff[6], fsz[6];
#pragma unroll
    for (int w = 0; w < 6; w++) {
        int tsk = tid + w * 256;             // 0..1535 16B-chunks of one stage
        int row, ch;
        unsigned abase;
        const __half* g;
        unsigned s = 16;
        if (tsk < 512) {                     // A: 64 rows x 8 chunks
            row = tsk >> 3; ch = tsk & 7;
            abase = 0u;
            g = Ap + (size_t)(bm + row) * K + ch * 8;
        } else {                             // B: 128 rows x 8 chunks
            int t2 = tsk - 512;
            row = t2 >> 3; ch = t2 & 7;
            abase = 8192u;
            int n = bn + row;
            int nc = n < N ? n : 0;
            s = n < N ? 16u : 0u;
            g = Bp + (size_t)nc * K + ch * 8;
        }
        gp[w] = g; fsz[w] = s;
        doff[w] = abase + (unsigned)(row * 128 + ((ch ^ (row & 7)) << 4));
    }

#define FILL_STAGE(ST) do {                                                  \
    _Pragma("unroll")                                                        \
    for (int w = 0; w < 6; w++) {                                            \
        asm volatile("cp.async.cg.shared.global [%0], [%1], 16, %2;"         \
                     :: "r"((ST) + doff[w]), "l"(gp[w]), "r"(fsz[w]));       \
        gp[w] += 64;                                                         \
    }                                                                        \
    asm volatile("cp.async.commit_group;");                                  \
} while (0)

    // ---- fragment base geometry ----
    const int rA = wm + (lane & 15);
    const int rB = wn + (lane & 15);
    const unsigned oAr = (unsigned)(rA * 128);
    const unsigned oBr = 8192u + (unsigned)(rB * 128);
    const unsigned swA = (unsigned)(rA & 7);
    const unsigned swB = (unsigned)(rB & 7);
    const unsigned c0 = (unsigned)(lane >> 4);

    float acc[2][4][4];
#pragma unroll
    for (int mt = 0; mt < 2; mt++)
#pragma unroll
        for (int j = 0; j < 4; j++)
#pragma unroll
            for (int q = 0; q < 4; q++) acc[mt][j][q] = 0.f;

    const int nk = K / 64;
    FILL_STAGE(sbase);
    FILL_STAGE(sbase + STAGE_BYTES);

    for (int kt = 0; kt < nk; kt++) {
        asm volatile("cp.async.wait_group 1;");
        __syncthreads();
        if (kt + 2 < nk) {
            FILL_STAGE(sbase + (unsigned)((kt + 2) % 3) * STAGE_BYTES);
        } else {
            asm volatile("cp.async.commit_group;");
        }

        const unsigned st = sbase + (unsigned)(kt % 3) * STAGE_BYTES;
#pragma unroll
        for (int ks = 0; ks < 4; ks++) {
            const unsigned ch = (unsigned)(2 * ks) + c0;
            const unsigned aaddr = st + oAr + ((ch ^ swA) << 4);
            const unsigned baddr = st + oBr + ((ch ^ swB) << 4);
            unsigned ah[2][4];
            LDM4A(ah[0], aaddr);
            LDM4A(ah[1], aaddr + 2048u);     // rows +16: same swizzle (16 % 8 == 0)
#pragma unroll
            for (int jj = 0; jj < 2; jj++) {
                unsigned bh[4];
                LDM4A(bh, baddr + (unsigned)jj * 2048u);
#pragma unroll
                for (int sub = 0; sub < 2; sub++)
#pragma unroll
                    for (int mt = 0; mt < 2; mt++)
                        MMA_F16(acc[mt][jj * 2 + sub], ah[mt], bh[sub], bh[2 + sub]);
            }
        }
    }

    // ---- epilogue: + bias (+ residual) ----
#pragma unroll
    for (int mt = 0; mt < 2; mt++) {
        int row0 = bm + wm + mt * 16 + r;
#pragma unroll
        for (int j = 0; j < 4; j++) {
            int col = bn + wn + j * 8 + cq;
            if (col < N) {
                float b0v = bias[col], b1v = bias[col + 1];
                size_t o0 = (size_t)row0 * N + col;
                size_t o1 = (size_t)(row0 + 8) * N + col;
                float v0 = acc[mt][j][0] + b0v, v1 = acc[mt][j][1] + b1v;
                float v2 = acc[mt][j][2] + b0v, v3 = acc[mt][j][3] + b1v;
                if (res) {
                    v0 += res[o0]; v1 += res[o0 + 1];
                    v2 += res[o1]; v3 += res[o1 + 1];
                }
                C[o0] = v0; C[o0 + 1] = v1;
                C[o1] = v2; C[o1 + 1] = v3;
            }
        }
    }
#undef FILL_STAGE
}

// ---------------- K2: v-assembly + quantum features ----------------
// g_P row layout: [aq 0:64 | kaq 64:128 | qb 128:256 | kb 256:288 | vb 288:320 | va 320:832]
__global__ __launch_bounds__(256, 6)
void tpa_feat_kernel(const float* __restrict__ qeb, const float* __restrict__ vqc,
                     const float* __restrict__ ent) {
    __shared__ float sP[NCAT];
    __shared__ float sVQ[48];
    __shared__ float sQEB[8];
    const int token = blockIdx.x;
    const int b = token / Ss, s = token % Ss;
    const int tid = threadIdx.x;

    const float4* p4 = reinterpret_cast<const float4*>(&g_P[(size_t)token * NCAT]);
    if (tid < NCAT / 4) reinterpret_cast<float4*>(sP)[tid] = p4[tid];
    if (tid >= 192 && tid < 240) sVQ[tid - 192] = __ldg(&vqc[tid - 192]);
    if (tid >= 240 && tid < 248) sQEB[tid - 240] = __ldg(&qeb[tid - 240]);
    __syncthreads();

    // v[kv,d] = sum_r va[r,d] * vb[r,kv]
    {
        int kv = tid >> 6, d = tid & 63;
        float av = 0.f;
#pragma unroll
        for (int r = 0; r < 8; r++) av += sP[320 + r * 64 + d] * sP[288 + r * 4 + kv];
        g_v[(((size_t)(b * KVv + kv)) * Ss + s) * 64 + d] = av;
    }

    // quantum features: one thread per (head, qubit), 20 heads x 8 = 160 threads
    const int oct = tid >> 3, j = tid & 7;
    if (oct < 20) {
        const float ev = __ldg(ent);
        float p = sQEB[j];
        if (oct < 16) {
#pragma unroll
            for (int r = 0; r < 8; r++) p += sP[128 + r * 16 + oct] * sP[r * 8 + j];
        } else {
#pragma unroll
            for (int r = 0; r < 8; r++) p += sP[256 + r * 4 + (oct - 16)] * sP[64 + r * 8 + j];
        }
        float f = tanhf(p) * 3.14159265358979323846f;
#pragma unroll
        for (int l = 0; l < 2; l++) {
            float a0 = sVQ[(l * 8 + j) * 3 + 0];
            float a1 = sVQ[(l * 8 + j) * 3 + 1];
            float a2 = sVQ[(l * 8 + j) * 3 + 2];
            float g = cosf(f + a0) * sinf(f + a1) + cosf(f + a2);
            int srcLane = ((tid & 31) & ~7) | ((j + 7) & 7);
            float gp = __shfl_sync(0xffffffffu, g, srcLane);
            f = g * (1.f + ev * gp);
        }
        float cv = cosf(f), sv = sinf(f);
        float nr = cv * cv + sv * sv;
        nr += __shfl_xor_sync(0xffffffffu, nr, 1);
        nr += __shfl_xor_sync(0xffffffffu, nr, 2);
        nr += __shfl_xor_sync(0xffffffffu, nr, 4);
        float inv = 1.f / (sqrtf(nr) + 1e-6f);
        float* dst = oct < 16
            ? &g_qf[(((size_t)(b * Hh + oct)) * Ss + s) * 16]
            : &g_kf[(((size_t)(b * KVv + (oct - 16))) * Ss + s) * 16];
        dst[j]     = cv * inv;
        dst[j + 8] = sv * inv;
    }
}

// ---------------- Pass A: per-chunk sums of kf (x) v and kf ----------------
__global__ __launch_bounds__(64, 8)
void passA_kernel() {
    const int blk = blockIdx.x;            // (b*KV+kv)*NCH + c
    const int c = blk % NCH;
    const int bk = blk / NCH;
    const int tid = threadIdx.x;           // d
    const float4* kfb = reinterpret_cast<const float4*>(&g_kf[(((size_t)bk) * Ss + c * CHUNK) * 16]);
    const float* vb = &g_v[(((size_t)bk) * Ss + c * CHUNK) * 64];
    float acc[16];
#pragma unroll
    for (int f = 0; f < 16; f++) acc[f] = 0.f;
    float kfs = 0.f;
    for (int t = 0; t < CHUNK; t++) {
        float vd = vb[t * 64 + tid];
        float kv[16]; ld16(kv, kfb + t * 4);
#pragma unroll
        for (int f = 0; f < 16; f++) acc[f] += kv[f] * vd;
        if (tid < 16) kfs += __ldg(&g_kf[(((size_t)bk) * Ss + c * CHUNK + t) * 16 + tid]);
    }
#pragma unroll
    for (int f = 0; f < 16; f++) g_kvc[((size_t)blk * 16 + f) * 64 + tid] = acc[f];
    if (tid < 16) g_kfc[blk * 16 + tid] = kfs;
}

// ---------------- Pass C: chunk prefix + within-chunk scan + query eval ----------------
__global__ __launch_bounds__(64, 8)
void passC_kernel() {
    const int blk = blockIdx.x;
    const int c = blk % NCH;
    const int bk = blk / NCH;
    const int b = bk / KVv, kvh = bk % KVv;
    const int tid = threadIdx.x;           // d
    float st[16], kc[16];
#pragma unroll
    for (int f = 0; f < 16; f++) { st[f] = 0.f; kc[f] = 0.f; }
    for (int cp = 0; cp < c; cp++) {
        int blk2 = bk * NCH + cp;
#pragma unroll
        for (int f = 0; f < 16; f++) {
            st[f] += g_kvc[((size_t)blk2 * 16 + f) * 64 + tid];
            kc[f] += __ldg(&g_kfc[blk2 * 16 + f]);
        }
    }
    const float4* kfb = reinterpret_cast<const float4*>(&g_kf[(((size_t)bk) * Ss + c * CHUNK) * 16]);
    const float* vb = &g_v[(((size_t)bk) * Ss + c * CHUNK) * 64];
    const int h0 = kvh * 4;
    const float4* qfb[4];
#pragma unroll
    for (int hh = 0; hh < 4; hh++)
        qfb[hh] = reinterpret_cast<const float4*>(&g_qf[(((size_t)(b * Hh + h0 + hh)) * Ss + c * CHUNK) * 16]);
    const size_t abase = ((size_t)b * Ss + c * CHUNK) * Ee + h0 * 64 + tid;

    for (int t = 0; t < CHUNK; t++) {
        float vd = vb[t * 64 + tid];
        float kv[16]; ld16(kv, kfb + t * 4);
#pragma unroll
        for (int f = 0; f < 16; f++) { st[f] += kv[f] * vd; kc[f] += kv[f]; }
#pragma unroll
        for (int hh = 0; hh < 4; hh++) {
            float qv[16]; ld16(qv, qfb[hh] + t * 4);
            float num = 0.f, den = 0.f;
#pragma unroll
            for (int f = 0; f < 16; f++) { num += qv[f] * st[f]; den += qv[f] * kc[f]; }
            float val = num / (den + 1e-6f);
            g_a[abase + (size_t)t * Ee + hh * 64] = __float2half_rn(val);
        }
    }
}

// ---------------- LayerNorm (in-place on d_out) ----------------
__global__ __launch_bounds__(256, 4)
void ln_kernel(float* __restrict__ y, const float* __restrict__ gamma, const float* __restrict__ beta) {
    const int row = blockIdx.x, tid = threadIdx.x;
    float4* yr = reinterpret_cast<float4*>(y + (size_t)row * Ee);
    float4 v = yr[tid];
    float s = v.x + v.y + v.z + v.w;
    float q = v.x * v.x + v.y * v.y + v.z * v.z + v.w * v.w;
    __shared__ float sS[8], sQ[8];
    const int lane = tid & 31, wid = tid >> 5;
#pragma unroll
    for (int off = 16; off; off >>= 1) {
        s += __shfl_xor_sync(0xffffffffu, s, off);
        q += __shfl_xor_sync(0xffffffffu, q, off);
    }
    if (lane == 0) { sS[wid] = s; sQ[wid] = q; }
    __syncthreads();
    if (tid == 0) {
        float ts = 0.f, tq = 0.f;
#pragma unroll
        for (int i = 0; i < 8; i++) { ts += sS[i]; tq += sQ[i]; }
        sS[0] = ts; sQ[0] = tq;
    }
    __syncthreads();
    float mu = sS[0] * (1.f / 1024.f);
    float var = sQ[0] * (1.f / 1024.f) - mu * mu;
    float rstd = rsqrtf(var + 1e-5f);
    const float4 gm = reinterpret_cast<const float4*>(gamma)[tid];
    const float4 bt = reinterpret_cast<const float4*>(beta)[tid];
    float4 o;
    o.x = gm.x * (v.x - mu) * rstd + bt.x;
    o.y = gm.y * (v.y - mu) * rstd + bt.y;
    o.z = gm.z * (v.z - mu) * rstd + bt.z;
    o.w = gm.w * (v.w - mu) * rstd + bt.w;
    yr[tid] = o;
}

// ---------------- launch ----------------
extern "C" void kernel_launch(void* const* d_in, const int* in_sizes, int n_in,
                              void* d_out, int out_size) {
    const float* x    = (const float*)d_in[0];
    const float* ctxW = (const float*)d_in[1];
    const float* ctxb = (const float*)d_in[2];
    const float* qaW  = (const float*)d_in[3];
    const float* qab  = (const float*)d_in[4];
    const float* qbW  = (const float*)d_in[5];
    const float* qbb  = (const float*)d_in[6];
    const float* kaW  = (const float*)d_in[7];
    const float* kab  = (const float*)d_in[8];
    const float* kbW  = (const float*)d_in[9];
    const float* kbb  = (const float*)d_in[10];
    const float* vaW  = (const float*)d_in[11];
    const float* vab  = (const float*)d_in[12];
    const float* vbW  = (const float*)d_in[13];
    const float* vbb  = (const float*)d_in[14];
    const float* qeW  = (const float*)d_in[15];
    const float* qeb  = (const float*)d_in[16];
    const float* vqc  = (const float*)d_in[17];
    const float* ent  = (const float*)d_in[18];
    const float* outW = (const float*)d_in[19];
    const float* outb = (const float*)d_in[20];
    const float* gamma = (const float*)d_in[21];
    const float* beta  = (const float*)d_in[22];
    float* out = (float*)d_out;

    cudaFuncSetAttribute(gemm_tc_kernel, cudaFuncAttributeMaxDynamicSharedMemorySize, 3 * (int)STAGE_BYTES);

    pack_comp_kernel<<<1025, 256>>>(ctxW, qaW, kaW, qbW, kbW, vbW,
                                    ctxb, qab, kab, qbb, kbb, vbb, vab, qeW);
    pack_split_kernel<<<1024, 256>>>(vaW, outW);
    convx_kernel<<<1024, 256>>>(x);

    __half *p_x, *p_W, *p_a, *p_oW;
    float *p_P, *p_bcat;
    cudaGetSymbolAddress((void**)&p_x, g_x);
    cudaGetSymbolAddress((void**)&p_W, g_W);
    cudaGetSymbolAddress((void**)&p_a, g_a);
    cudaGetSymbolAddress((void**)&p_oW, g_oW);
    cudaGetSymbolAddress((void**)&p_P, g_P);
    cudaGetSymbolAddress((void**)&p_bcat, g_bcat);

    dim3 g1((NCAT + 127) / 128, NTOK / 64);
    gemm_tc_kernel<<<g1, 256, 3 * STAGE_BYTES>>>(NCAT, Ee, p_x, p_W, p_bcat, nullptr, p_P);

    tpa_feat_kernel<<<NTOK, 256>>>(qeb, vqc, ent);

    passA_kernel<<<Bb * KVv * NCH, 64>>>();
    passC_kernel<<<Bb * KVv * NCH, 64>>>();

    dim3 g2(Ee / 128, NTOK / 64);
    gemm_tc_kernel<<<g2, 256, 3 * STAGE_BYTES>>>(Ee, Ee, p_a, p_oW, outb, x, out);

    ln_kernel<<<NTOK, 256>>>(out, gamma, beta);
}